// round 1
// baseline (speedup 1.0000x reference)
#include <cuda_runtime.h>
#include <math.h>

#define NN 1024
#define BB 64
#define CC 64
#define HH 64
#define DD 16
#define CIN 128
#define BC 8192            // BB * CIN
#define KIO_G 49152        // 3*128*128
#define KIO_U 24576        // 3*128*64

// ---------------- scratch (static device globals; no allocation) ----------------
__device__ float g_eg[NN * DD];
__device__ float g_eu[NN * DD];
__device__ float g_bg[NN * 128];
__device__ float g_bu[NN * 64];
__device__ float g_Sg[NN * NN];
__device__ float g_Su[NN * NN];
__device__ float g_Xin[NN * BC];
__device__ float g_xg1[NN * BC];
__device__ float g_xg2[NN * BC];
__device__ float g_wg[NN * KIO_G];   // per-node gate weights [n][ki][o]
__device__ float g_wu[NN * KIO_U];   // per-node update weights
__device__ float g_z[BB * NN * HH];
__device__ float g_r[BB * NN * HH];

// ---------------- 1) e = LN(node_emb + time_emb), bias = e @ b_pool ----------------
__global__ void k_prep(const float* __restrict__ ne, const float* __restrict__ te,
                       const float* __restrict__ gw, const float* __restrict__ gbln,
                       const float* __restrict__ uw, const float* __restrict__ ubln,
                       const float* __restrict__ gate_b, const float* __restrict__ update_b)
{
    int n = blockIdx.x;
    int lane = threadIdx.x;          // 32 threads
    int d = lane & 15;               // duplicated over the two halves of the warp
    float v = ne[n * DD + d] + te[d];

    float s = v;
    #pragma unroll
    for (int off = 16; off > 0; off >>= 1) s += __shfl_xor_sync(0xffffffffu, s, off);
    float mean = s * (1.0f / 32.0f);
    float dv = v - mean;
    float q = dv * dv;
    #pragma unroll
    for (int off = 16; off > 0; off >>= 1) q += __shfl_xor_sync(0xffffffffu, q, off);
    float var = q * (1.0f / 32.0f);
    float inv = rsqrtf(var + 1e-12f);

    float eg = dv * inv * gw[d] + gbln[d];
    float eu = dv * inv * uw[d] + ubln[d];
    if (lane < 16) { g_eg[n * DD + d] = eg; g_eu[n * DD + d] = eu; }

    // bias_g[n,o] = sum_d e_g[n,d] * gate_b[d,o]   (gate_b is [16][128])
    for (int o = lane; o < 128; o += 32) {
        float b = 0.f;
        #pragma unroll
        for (int dd = 0; dd < 16; dd++)
            b += __shfl_sync(0xffffffffu, eg, dd) * gate_b[dd * 128 + o];
        g_bg[n * 128 + o] = b;
    }
    for (int o = lane; o < 64; o += 32) {
        float b = 0.f;
        #pragma unroll
        for (int dd = 0; dd < 16; dd++)
            b += __shfl_sync(0xffffffffu, eu, dd) * update_b[dd * 64 + o];
        g_bu[n * 64 + o] = b;
    }
}

// ---------------- 2) S = softmax(e e^T) row-wise ----------------
__global__ void k_supports()
{
    int n = blockIdx.x;
    int which = blockIdx.y;
    const float* e = which ? g_eu : g_eg;
    float* S = which ? g_Su : g_Sg;

    __shared__ float en[16];
    __shared__ float red[256];
    int tid = threadIdx.x;
    if (tid < 16) en[tid] = e[n * DD + tid];
    __syncthreads();

    float lv[4];
    float mx = -1e30f;
    #pragma unroll
    for (int i = 0; i < 4; i++) {
        int m = tid + i * 256;
        const float* em = &e[m * DD];
        float dot = 0.f;
        #pragma unroll
        for (int dd = 0; dd < 16; dd++) dot += en[dd] * em[dd];
        lv[i] = dot;
        mx = fmaxf(mx, dot);
    }
    red[tid] = mx; __syncthreads();
    for (int s = 128; s > 0; s >>= 1) {
        if (tid < s) red[tid] = fmaxf(red[tid], red[tid + s]);
        __syncthreads();
    }
    mx = red[0];
    __syncthreads();

    float sum = 0.f;
    #pragma unroll
    for (int i = 0; i < 4; i++) { lv[i] = expf(lv[i] - mx); sum += lv[i]; }
    red[tid] = sum; __syncthreads();
    for (int s = 128; s > 0; s >>= 1) {
        if (tid < s) red[tid] += red[tid + s];
        __syncthreads();
    }
    float invs = 1.0f / red[0];
    #pragma unroll
    for (int i = 0; i < 4; i++) S[n * NN + tid + i * 256] = lv[i] * invs;
}

// ---------------- 3) per-node weights: w[n][kio] = sum_d e[n,d] * Wp[d][kio] ----------------
__global__ void k_wgen(const float* __restrict__ Wp, int which)
{
    const int KIO = which ? KIO_U : KIO_G;
    float* wout = which ? g_wu : g_wg;
    const float* e = which ? g_eu : g_eg;

    int tid = threadIdx.x;
    int kio = blockIdx.x * 256 + tid;
    int n0 = blockIdx.y * 16;

    __shared__ float es[256];
    es[tid] = e[n0 * DD + tid];   // 16 nodes x 16 dims
    __syncthreads();

    float wr[16];
    #pragma unroll
    for (int dd = 0; dd < 16; dd++) wr[dd] = Wp[dd * KIO + kio];

    #pragma unroll
    for (int j = 0; j < 16; j++) {
        float a = 0.f;
        #pragma unroll
        for (int dd = 0; dd < 16; dd++) a += es[j * 16 + dd] * wr[dd];
        wout[(n0 + j) * KIO + kio] = a;
    }
}

// ---------------- 4) build Xin[n][b*128+c] = concat(x, state or z*state) ----------------
__global__ void k_build_xin(const float* __restrict__ x, const float* __restrict__ state, int mode)
{
    int t = blockIdx.x * 256 + threadIdx.x;   // 2,097,152 float4 lanes
    int n = t >> 11;
    int j = t & 2047;
    int b = j >> 5;
    int c = (j & 31) << 2;

    float4 v;
    if (c < 64) {
        v = *(const float4*)&x[b * (NN * CC) + n * CC + c];
    } else {
        int cc = c - 64;
        float4 s4 = *(const float4*)&state[b * (NN * HH) + n * HH + cc];
        if (mode) {
            float4 z4 = *(const float4*)&g_z[b * (NN * HH) + n * HH + cc];
            v.x = z4.x * s4.x; v.y = z4.y * s4.y; v.z = z4.z * s4.z; v.w = z4.w * s4.w;
        } else {
            v = s4;
        }
    }
    *(float4*)&g_Xin[n * BC + b * CIN + c] = v;
}

// ---------------- 5) SGEMM: C(1024x8192) = alpha*A(1024x1024)@B(1024x8192) + beta*D ----------------
__global__ void __launch_bounds__(256, 2)
k_sgemm(const float* __restrict__ A, const float* __restrict__ B,
        const float* __restrict__ D, float* __restrict__ C,
        float alpha, float beta)
{
    __shared__ float As[16][132];   // [k][m], padded
    __shared__ float Bs[16][128];   // [k][n]

    const int tid = threadIdx.x;
    const int tx = tid & 15, ty = tid >> 4;
    const int brow = blockIdx.y << 7;
    const int bcol = blockIdx.x << 7;

    float acc[8][8];
    #pragma unroll
    for (int i = 0; i < 8; i++)
        #pragma unroll
        for (int j = 0; j < 8; j++) acc[i][j] = 0.f;

    for (int kk = 0; kk < 1024; kk += 16) {
        #pragma unroll
        for (int i = 0; i < 2; i++) {
            int lin = tid + (i << 8);               // 0..511
            int ar = lin >> 2;                       // 0..127
            int kq = (lin & 3) << 2;                 // 0,4,8,12
            float4 a = *(const float4*)&A[(brow + ar) * 1024 + kk + kq];
            As[kq + 0][ar] = a.x; As[kq + 1][ar] = a.y;
            As[kq + 2][ar] = a.z; As[kq + 3][ar] = a.w;
        }
        #pragma unroll
        for (int i = 0; i < 2; i++) {
            int lin = tid + (i << 8);
            int kr = lin >> 5;                       // 0..15
            int cq = (lin & 31) << 2;                // 0..124
            *(float4*)&Bs[kr][cq] = *(const float4*)&B[(kk + kr) * BC + bcol + cq];
        }
        __syncthreads();

        #pragma unroll
        for (int k = 0; k < 16; k++) {
            float ar[8], br[8];
            *(float4*)&ar[0] = *(float4*)&As[k][ty * 8];
            *(float4*)&ar[4] = *(float4*)&As[k][ty * 8 + 4];
            *(float4*)&br[0] = *(float4*)&Bs[k][tx * 8];
            *(float4*)&br[4] = *(float4*)&Bs[k][tx * 8 + 4];
            #pragma unroll
            for (int i = 0; i < 8; i++)
                #pragma unroll
                for (int j = 0; j < 8; j++)
                    acc[i][j] += ar[i] * br[j];
        }
        __syncthreads();
    }

    #pragma unroll
    for (int i = 0; i < 8; i++) {
        int row = brow + ty * 8 + i;
        #pragma unroll
        for (int j = 0; j < 8; j += 4) {
            int col = bcol + tx * 8 + j;
            float4 o;
            o.x = alpha * acc[i][j + 0];
            o.y = alpha * acc[i][j + 1];
            o.z = alpha * acc[i][j + 2];
            o.w = alpha * acc[i][j + 3];
            if (beta != 0.f) {
                float4 d4 = *(const float4*)&D[row * BC + col];
                o.x += beta * d4.x; o.y += beta * d4.y;
                o.z += beta * d4.z; o.w += beta * d4.w;
            }
            *(float4*)&C[row * BC + col] = o;
        }
    }
}

// ---------------- 6) per-node gate GEMM (64x384)@(384x128) + bias -> sigmoid -> z,r ----------------
__global__ void __launch_bounds__(256)
k_ngemm_gate()
{
    int n = blockIdx.x;
    __shared__ float As[64][36];
    __shared__ float Ws[32][128];
    int tid = threadIdx.x;
    int tx = tid & 15, ty = tid >> 4;

    float acc[4][8];
    #pragma unroll
    for (int i = 0; i < 4; i++)
        #pragma unroll
        for (int j = 0; j < 8; j++) acc[i][j] = 0.f;

    for (int kk = 0; kk < 384; kk += 32) {
        const float* buf = (kk < 128) ? g_Xin : ((kk < 256) ? g_xg1 : g_xg2);
        int i0 = kk & 127;
        #pragma unroll
        for (int i = 0; i < 2; i++) {
            int lin = tid + (i << 8);        // 0..511
            int b = lin >> 3;                 // 0..63
            int tq = (lin & 7) << 2;          // 0..28
            float4 a = *(const float4*)&buf[n * BC + b * CIN + i0 + tq];
            *(float4*)&As[b][tq] = a;
        }
        #pragma unroll
        for (int i = 0; i < 4; i++) {
            int lin = tid + (i << 8);        // 0..1023
            int t = lin >> 5;                 // 0..31
            int oq = (lin & 31) << 2;         // 0..124
            *(float4*)&Ws[t][oq] = *(const float4*)&g_wg[n * KIO_G + (kk + t) * 128 + oq];
        }
        __syncthreads();

        #pragma unroll
        for (int k = 0; k < 32; k++) {
            float a0 = As[ty * 4 + 0][k];
            float a1 = As[ty * 4 + 1][k];
            float a2 = As[ty * 4 + 2][k];
            float a3 = As[ty * 4 + 3][k];
            float br[8];
            *(float4*)&br[0] = *(float4*)&Ws[k][tx * 8];
            *(float4*)&br[4] = *(float4*)&Ws[k][tx * 8 + 4];
            #pragma unroll
            for (int j = 0; j < 8; j++) {
                acc[0][j] += a0 * br[j];
                acc[1][j] += a1 * br[j];
                acc[2][j] += a2 * br[j];
                acc[3][j] += a3 * br[j];
            }
        }
        __syncthreads();
    }

    #pragma unroll
    for (int i = 0; i < 4; i++) {
        int b = ty * 4 + i;
        #pragma unroll
        for (int j = 0; j < 8; j++) {
            int o = tx * 8 + j;
            float v = acc[i][j] + g_bg[n * 128 + o];
            float s = 1.0f / (1.0f + expf(-v));
            int idx = b * (NN * HH) + n * HH + (o & 63);
            if (o < 64) g_z[idx] = s; else g_r[idx] = s;
        }
    }
}

// ---------------- 7) per-node update GEMM (64x384)@(384x64) + bias -> tanh -> final GRU out ----------------
__global__ void __launch_bounds__(256)
k_ngemm_update(const float* __restrict__ state, float* __restrict__ dout)
{
    int n = blockIdx.x;
    __shared__ float As[64][36];
    __shared__ float Ws[32][68];
    int tid = threadIdx.x;
    int tx = tid & 15, ty = tid >> 4;

    float acc[4][4];
    #pragma unroll
    for (int i = 0; i < 4; i++)
        #pragma unroll
        for (int j = 0; j < 4; j++) acc[i][j] = 0.f;

    for (int kk = 0; kk < 384; kk += 32) {
        const float* buf = (kk < 128) ? g_Xin : ((kk < 256) ? g_xg1 : g_xg2);
        int i0 = kk & 127;
        #pragma unroll
        for (int i = 0; i < 2; i++) {
            int lin = tid + (i << 8);
            int b = lin >> 3;
            int tq = (lin & 7) << 2;
            float4 a = *(const float4*)&buf[n * BC + b * CIN + i0 + tq];
            *(float4*)&As[b][tq] = a;
        }
        #pragma unroll
        for (int i = 0; i < 2; i++) {
            int lin = tid + (i << 8);        // 0..511
            int t = lin >> 4;                 // 0..31
            int oq = (lin & 15) << 2;         // 0..60
            *(float4*)&Ws[t][oq] = *(const float4*)&g_wu[n * KIO_U + (kk + t) * 64 + oq];
        }
        __syncthreads();

        #pragma unroll
        for (int k = 0; k < 32; k++) {
            float a0 = As[ty * 4 + 0][k];
            float a1 = As[ty * 4 + 1][k];
            float a2 = As[ty * 4 + 2][k];
            float a3 = As[ty * 4 + 3][k];
            float br[4];
            *(float4*)&br[0] = *(float4*)&Ws[k][tx * 4];
            #pragma unroll
            for (int j = 0; j < 4; j++) {
                acc[0][j] += a0 * br[j];
                acc[1][j] += a1 * br[j];
                acc[2][j] += a2 * br[j];
                acc[3][j] += a3 * br[j];
            }
        }
        __syncthreads();
    }

    #pragma unroll
    for (int i = 0; i < 4; i++) {
        int b = ty * 4 + i;
        #pragma unroll
        for (int j = 0; j < 4; j++) {
            int o = tx * 4 + j;
            float v = acc[i][j] + g_bu[n * 64 + o];
            float hc = tanhf(v);
            int idx = b * (NN * HH) + n * HH + o;
            float r = g_r[idx];
            float st = state[idx];
            dout[idx] = r * st + (1.0f - r) * hc;
        }
    }
}

// ---------------- launch ----------------
extern "C" void kernel_launch(void* const* d_in, const int* in_sizes, int n_in,
                              void* d_out, int out_size)
{
    const float* x         = (const float*)d_in[0];
    const float* state     = (const float*)d_in[2];
    const float* node_emb  = (const float*)d_in[3];
    const float* time_emb  = (const float*)d_in[5];
    const float* gate_W    = (const float*)d_in[6];
    const float* gate_b    = (const float*)d_in[7];
    const float* gate_lnw  = (const float*)d_in[8];
    const float* gate_lnb  = (const float*)d_in[9];
    const float* update_W  = (const float*)d_in[10];
    const float* update_b  = (const float*)d_in[11];
    const float* update_lnw= (const float*)d_in[12];
    const float* update_lnb= (const float*)d_in[13];
    float* out = (float*)d_out;

    float *Sg, *Su, *Xin, *xg1, *xg2;
    cudaGetSymbolAddress((void**)&Sg,  g_Sg);
    cudaGetSymbolAddress((void**)&Su,  g_Su);
    cudaGetSymbolAddress((void**)&Xin, g_Xin);
    cudaGetSymbolAddress((void**)&xg1, g_xg1);
    cudaGetSymbolAddress((void**)&xg2, g_xg2);

    k_prep<<<NN, 32>>>(node_emb, time_emb, gate_lnw, gate_lnb, update_lnw, update_lnb,
                       gate_b, update_b);
    k_supports<<<dim3(NN, 2), 256>>>();
    k_wgen<<<dim3(KIO_G / 256, NN / 16), 256>>>(gate_W, 0);
    k_wgen<<<dim3(KIO_U / 256, NN / 16), 256>>>(update_W, 1);

    // gate magcn
    k_build_xin<<<(NN * BC / 4) / 256, 256>>>(x, state, 0);
    k_sgemm<<<dim3(BC / 128, NN / 128), 256>>>(Sg, Xin, Xin, xg1, 1.0f, 0.0f);
    k_sgemm<<<dim3(BC / 128, NN / 128), 256>>>(Sg, xg1, Xin, xg2, 2.0f, -1.0f);
    k_ngemm_gate<<<NN, 256>>>();

    // update magcn
    k_build_xin<<<(NN * BC / 4) / 256, 256>>>(x, state, 1);
    k_sgemm<<<dim3(BC / 128, NN / 128), 256>>>(Su, Xin, Xin, xg1, 1.0f, 0.0f);
    k_sgemm<<<dim3(BC / 128, NN / 128), 256>>>(Su, xg1, Xin, xg2, 2.0f, -1.0f);
    k_ngemm_update<<<NN, 256>>>(state, out);
}

// round 3
// speedup vs baseline: 1.8064x; 1.8064x over previous
#include <cuda_runtime.h>
#include <cuda_fp16.h>
#include <math.h>
#include <stdint.h>

#define NN 1024
#define BB 64
#define CC 64
#define HH 64
#define DD 16
#define CIN 128
#define BC 8192            // BB * CIN
#define KIO_G 49152        // 3*128*128
#define KIO_U 24576        // 3*128*64

// ---------------- scratch (static device globals; no allocation) ----------------
__device__ float g_eg[NN * DD];
__device__ float g_eu[NN * DD];
__device__ float g_bg[NN * 128];
__device__ float g_bu[NN * 64];
__device__ float g_Xin[NN * BC];
__device__ float g_xg1[NN * BC];
__device__ float g_xg2[NN * BC];
__device__ float g_wg[NN * KIO_G];   // per-node gate weights [n][ki][o]
__device__ float g_wu[NN * KIO_U];   // per-node update weights
__device__ float g_z[BB * NN * HH];
__device__ float g_r[BB * NN * HH];

// fp16 split buffers (stored as u16), all K-major with K stride = 1024
__device__ unsigned short g_Sgh[NN * NN];
__device__ unsigned short g_Sgl[NN * NN];
__device__ unsigned short g_Suh[NN * NN];
__device__ unsigned short g_Sul[NN * NN];
__device__ unsigned short g_XTh[BC * NN];   // transposed Xin split  [n][k]
__device__ unsigned short g_XTl[BC * NN];
__device__ unsigned short g_YTh[BC * NN];   // transposed xg1 split  [n][k]
__device__ unsigned short g_YTl[BC * NN];

// ---------------- helpers ----------------
__device__ __forceinline__ uint32_t smem_to_u32(const void* p) {
    uint32_t a;
    asm("{ .reg .u64 t; cvta.to.shared.u64 t, %1; cvt.u32.u64 %0, t; }" : "=r"(a) : "l"(p));
    return a;
}

#define CP_ASYNC16(dst, src) \
    asm volatile("cp.async.cg.shared.global [%0], [%1], 16;" :: "r"(dst), "l"(src))
#define CP_COMMIT()  asm volatile("cp.async.commit_group;" ::: "memory")
#define CP_WAIT0()   asm volatile("cp.async.wait_group 0;" ::: "memory")

__device__ __forceinline__ void ldsm_x4(uint32_t& r0, uint32_t& r1, uint32_t& r2, uint32_t& r3,
                                        uint32_t addr) {
    asm volatile("ldmatrix.sync.aligned.m8n8.x4.shared.b16 {%0,%1,%2,%3}, [%4];"
                 : "=r"(r0), "=r"(r1), "=r"(r2), "=r"(r3) : "r"(addr));
}

__device__ __forceinline__ void mma16816(float* c, const uint32_t* a, const uint32_t* b) {
    asm volatile("mma.sync.aligned.m16n8k16.row.col.f32.f16.f16.f32 "
                 "{%0,%1,%2,%3}, {%4,%5,%6,%7}, {%8,%9}, {%0,%1,%2,%3};"
                 : "+f"(c[0]), "+f"(c[1]), "+f"(c[2]), "+f"(c[3])
                 : "r"(a[0]), "r"(a[1]), "r"(a[2]), "r"(a[3]), "r"(b[0]), "r"(b[1]));
}

__device__ __forceinline__ void f16split(float x, unsigned short& h, unsigned short& l) {
    __half hb = __float2half_rn(x);
    __half lb = __float2half_rn(x - __half2float(hb));
    h = *reinterpret_cast<unsigned short*>(&hb);
    l = *reinterpret_cast<unsigned short*>(&lb);
}

// ---------------- 1) e = LN(node_emb + time_emb), bias = e @ b_pool ----------------
__global__ void k_prep(const float* __restrict__ ne, const float* __restrict__ te,
                       const float* __restrict__ gw, const float* __restrict__ gbln,
                       const float* __restrict__ uw, const float* __restrict__ ubln,
                       const float* __restrict__ gate_b, const float* __restrict__ update_b)
{
    int n = blockIdx.x;
    int lane = threadIdx.x;          // 32 threads
    int d = lane & 15;
    float v = ne[n * DD + d] + te[d];

    float s = v;
    #pragma unroll
    for (int off = 16; off > 0; off >>= 1) s += __shfl_xor_sync(0xffffffffu, s, off);
    float mean = s * (1.0f / 32.0f);
    float dv = v - mean;
    float q = dv * dv;
    #pragma unroll
    for (int off = 16; off > 0; off >>= 1) q += __shfl_xor_sync(0xffffffffu, q, off);
    float var = q * (1.0f / 32.0f);
    float inv = rsqrtf(var + 1e-12f);

    float eg = dv * inv * gw[d] + gbln[d];
    float eu = dv * inv * uw[d] + ubln[d];
    if (lane < 16) { g_eg[n * DD + d] = eg; g_eu[n * DD + d] = eu; }

    for (int o = lane; o < 128; o += 32) {
        float b = 0.f;
        #pragma unroll
        for (int dd = 0; dd < 16; dd++)
            b += __shfl_sync(0xffffffffu, eg, dd) * gate_b[dd * 128 + o];
        g_bg[n * 128 + o] = b;
    }
    for (int o = lane; o < 64; o += 32) {
        float b = 0.f;
        #pragma unroll
        for (int dd = 0; dd < 16; dd++)
            b += __shfl_sync(0xffffffffu, eu, dd) * update_b[dd * 64 + o];
        g_bu[n * 64 + o] = b;
    }
}

// ---------------- 2) S = softmax(e e^T) row-wise, fp16 hi/lo split ----------------
__global__ void k_supports()
{
    int n = blockIdx.x;
    int which = blockIdx.y;
    const float* e = which ? g_eu : g_eg;
    unsigned short* Sh = which ? g_Suh : g_Sgh;
    unsigned short* Sl = which ? g_Sul : g_Sgl;

    __shared__ float en[16];
    __shared__ float red[256];
    int tid = threadIdx.x;
    if (tid < 16) en[tid] = e[n * DD + tid];
    __syncthreads();

    float lv[4];
    float mx = -1e30f;
    #pragma unroll
    for (int i = 0; i < 4; i++) {
        int m = tid + i * 256;
        const float* em = &e[m * DD];
        float dot = 0.f;
        #pragma unroll
        for (int dd = 0; dd < 16; dd++) dot += en[dd] * em[dd];
        lv[i] = dot;
        mx = fmaxf(mx, dot);
    }
    red[tid] = mx; __syncthreads();
    for (int s = 128; s > 0; s >>= 1) {
        if (tid < s) red[tid] = fmaxf(red[tid], red[tid + s]);
        __syncthreads();
    }
    mx = red[0];
    __syncthreads();

    float sum = 0.f;
    #pragma unroll
    for (int i = 0; i < 4; i++) { lv[i] = expf(lv[i] - mx); sum += lv[i]; }
    red[tid] = sum; __syncthreads();
    for (int s = 128; s > 0; s >>= 1) {
        if (tid < s) red[tid] += red[tid + s];
        __syncthreads();
    }
    float invs = 1.0f / red[0];
    #pragma unroll
    for (int i = 0; i < 4; i++) {
        float v = lv[i] * invs;
        int idx = n * NN + tid + i * 256;
        unsigned short h, l;
        f16split(v, h, l);
        Sh[idx] = h; Sl[idx] = l;
    }
}

// ---------------- 3) per-node weights ----------------
__global__ void k_wgen(const float* __restrict__ Wp, int which)
{
    const int KIO = which ? KIO_U : KIO_G;
    float* wout = which ? g_wu : g_wg;
    const float* e = which ? g_eu : g_eg;

    int tid = threadIdx.x;
    int kio = blockIdx.x * 256 + tid;
    int n0 = blockIdx.y * 16;

    __shared__ float es[256];
    es[tid] = e[n0 * DD + tid];
    __syncthreads();

    float wr[16];
    #pragma unroll
    for (int dd = 0; dd < 16; dd++) wr[dd] = Wp[dd * KIO + kio];

    #pragma unroll
    for (int j = 0; j < 16; j++) {
        float a = 0.f;
        #pragma unroll
        for (int dd = 0; dd < 16; dd++) a += es[j * 16 + dd] * wr[dd];
        wout[(n0 + j) * KIO + kio] = a;
    }
}

// ---------------- 4) build Xin ----------------
__global__ void k_build_xin(const float* __restrict__ x, const float* __restrict__ state, int mode)
{
    int t = blockIdx.x * 256 + threadIdx.x;
    int n = t >> 11;
    int j = t & 2047;
    int b = j >> 5;
    int c = (j & 31) << 2;

    float4 v;
    if (c < 64) {
        v = *(const float4*)&x[b * (NN * CC) + n * CC + c];
    } else {
        int cc = c - 64;
        float4 s4 = *(const float4*)&state[b * (NN * HH) + n * HH + cc];
        if (mode) {
            float4 z4 = *(const float4*)&g_z[b * (NN * HH) + n * HH + cc];
            v.x = z4.x * s4.x; v.y = z4.y * s4.y; v.z = z4.z * s4.z; v.w = z4.w * s4.w;
        } else {
            v = s4;
        }
    }
    *(float4*)&g_Xin[n * BC + b * CIN + c] = v;
}

// ---------------- 4b) split + transpose: in[1024][8192] fp32 -> out[8192][1024] fp16 hi/lo ----------------
__global__ void k_splitT(const float* __restrict__ in,
                         unsigned short* __restrict__ oh, unsigned short* __restrict__ ol)
{
    __shared__ float t[32][33];
    int bx = blockIdx.x << 5;   // n (input col)
    int by = blockIdx.y << 5;   // k (input row)
    int x = threadIdx.x, y = threadIdx.y;  // 32 x 8
    #pragma unroll
    for (int i = 0; i < 4; i++)
        t[y + i * 8][x] = in[(by + y + i * 8) * BC + bx + x];
    __syncthreads();
    #pragma unroll
    for (int i = 0; i < 4; i++) {
        float v = t[x][y + i * 8];
        unsigned short h, l;
        f16split(v, h, l);
        int o = (bx + y + i * 8) * NN + by + x;
        oh[o] = h; ol[o] = l;
    }
}

// ---------------- 5) tensor-core GEMM: C(1024x8192) = A(1024x1024)@B(1024x8192) ----------------
// A split fp16 K-major [m][k] (Ah/Al); B split as B^T K-major [n][k] (Bh/Bl).
// 3-term: acc = Ah*Bh + Ah*Bl + Al*Bh.
// mode 0: Cout = acc (fp32); also CTh/CTl = f16split(acc) transposed [n][k-as-m].
// mode 1: Cout = 2*acc - Dmat.
#define STAGE_BYTES 65536
#define TCG_SMEM 131072

__global__ void __launch_bounds__(256, 1)
k_mmagemm(const unsigned short* __restrict__ Ah, const unsigned short* __restrict__ Al,
          const unsigned short* __restrict__ Bh, const unsigned short* __restrict__ Bl,
          const float* __restrict__ Dmat, float* __restrict__ Cout,
          unsigned short* __restrict__ CTh, unsigned short* __restrict__ CTl,
          int mode)
{
    extern __shared__ char smem[];
    const uint32_t smem_u = smem_to_u32(smem);
    const int tid = threadIdx.x;
    const int wid = tid >> 5;
    const int lane = tid & 31;
    const int brow = blockIdx.y << 7;    // M tile
    const int bcol = blockIdx.x << 7;    // N tile
    const int wm = wid & 1;              // 2 m-blocks of 64
    const int wn = wid >> 1;             // 4 n-blocks of 32

    // row bases (elements; row stride 1024)
    const unsigned short* srcs[4];
    srcs[0] = Ah + (size_t)brow * NN;
    srcs[1] = Al + (size_t)brow * NN;
    srcs[2] = Bh + (size_t)bcol * NN;
    srcs[3] = Bl + (size_t)bcol * NN;

    float acc[4][4][4];
    #pragma unroll
    for (int i = 0; i < 4; i++)
        #pragma unroll
        for (int j = 0; j < 4; j++)
            #pragma unroll
            for (int q = 0; q < 4; q++) acc[i][j][q] = 0.f;

    // ldmatrix per-lane address components
    const int arow = wm * 64 + (lane & 15);             // A row within tile
    const int axor = (arow & 7) << 4;
    const int agco = (lane >> 4) << 4;                  // +16B for k8-15 group
    const int bn   = wn * 32 + ((lane >> 4) << 3) + (lane & 7);   // base for nblk 0
    const int bxor = (bn & 7) << 4;
    const int bko  = ((lane >> 3) & 1) << 4;

    // loader: 4 arrays x (128 rows x 128B) per stage
    auto load_stage = [&](int buf, int kk) {
        uint32_t dst0 = smem_u + buf * STAGE_BYTES;
        #pragma unroll
        for (int i = 0; i < 16; i++) {
            int lin = tid + (i << 8);            // 0..4095
            int arr = lin >> 10;
            int r = (lin >> 3) & 127;
            int cb = (lin & 7) << 4;
            const char* src = (const char*)(srcs[arr] + (size_t)r * NN + kk) + cb;
            uint32_t d = dst0 + arr * 16384 + r * 128 + (cb ^ ((r & 7) << 4));
            CP_ASYNC16(d, src);
        }
        CP_COMMIT();
    };

    load_stage(0, 0);

    #pragma unroll 1
    for (int s = 0; s < 16; s++) {
        const int buf = s & 1;
        CP_WAIT0();
        __syncthreads();
        if (s + 1 < 16) load_stage(1 - buf, (s + 1) << 6);

        const uint32_t sb = smem_u + buf * STAGE_BYTES;
        #pragma unroll
        for (int ks = 0; ks < 4; ks++) {
            const int c = ks << 5;   // k byte offset within 128B row
            uint32_t ah[4][4], al[4][4], bh[4][2], bl[4][2];
            #pragma unroll
            for (int mt = 0; mt < 4; mt++) {
                uint32_t ao = (uint32_t)((arow + mt * 16) * 128) + (uint32_t)((c + agco) ^ axor);
                ldsm_x4(ah[mt][0], ah[mt][1], ah[mt][2], ah[mt][3], sb + ao);
                ldsm_x4(al[mt][0], al[mt][1], al[mt][2], al[mt][3], sb + 16384 + ao);
            }
            #pragma unroll
            for (int nb = 0; nb < 2; nb++) {
                uint32_t bo = (uint32_t)((bn + nb * 16) * 128) + (uint32_t)((c + bko) ^ bxor);
                ldsm_x4(bh[2 * nb][0], bh[2 * nb][1], bh[2 * nb + 1][0], bh[2 * nb + 1][1],
                        sb + 32768 + bo);
                ldsm_x4(bl[2 * nb][0], bl[2 * nb][1], bl[2 * nb + 1][0], bl[2 * nb + 1][1],
                        sb + 49152 + bo);
            }
            #pragma unroll
            for (int mt = 0; mt < 4; mt++)
                #pragma unroll
                for (int nt = 0; nt < 4; nt++) {
                    mma16816(acc[mt][nt], ah[mt], bh[nt]);
                    mma16816(acc[mt][nt], ah[mt], bl[nt]);
                    mma16816(acc[mt][nt], al[mt], bh[nt]);
                }
        }
        __syncthreads();
    }

    // ---- epilogue: stage C tile through smem (128 x 129 fp32) ----
    float* sf = (float*)smem;
    __syncthreads();
    {
        int g = lane >> 2, t4 = lane & 3;
        #pragma unroll
        for (int mt = 0; mt < 4; mt++) {
            int m0 = wm * 64 + mt * 16 + g;
            #pragma unroll
            for (int nt = 0; nt < 4; nt++) {
                int n0 = wn * 32 + nt * 8 + 2 * t4;
                sf[m0 * 129 + n0]           = acc[mt][nt][0];
                sf[m0 * 129 + n0 + 1]       = acc[mt][nt][1];
                sf[(m0 + 8) * 129 + n0]     = acc[mt][nt][2];
                sf[(m0 + 8) * 129 + n0 + 1] = acc[mt][nt][3];
            }
        }
    }
    __syncthreads();

    if (mode == 0) {
        #pragma unroll 4
        for (int it = 0; it < 64; it++) {
            int idx = tid + (it << 8);
            int m = idx >> 7, j = idx & 127;
            Cout[(size_t)(brow + m) * BC + bcol + j] = sf[m * 129 + j];
        }
        #pragma unroll 4
        for (int it = 0; it < 64; it++) {
            int idx = tid + (it << 8);
            int j = idx >> 7, m = idx & 127;
            float v = sf[m * 129 + j];
            unsigned short h, l;
            f16split(v, h, l);
            size_t o = (size_t)(bcol + j) * NN + brow + m;
            CTh[o] = h; CTl[o] = l;
        }
    } else {
        #pragma unroll 4
        for (int it = 0; it < 64; it++) {
            int idx = tid + (it << 8);
            int m = idx >> 7, j = idx & 127;
            size_t o = (size_t)(brow + m) * BC + bcol + j;
            Cout[o] = 2.0f * sf[m * 129 + j] - Dmat[o];
        }
    }
}

// ---------------- 6) per-node gate GEMM (64x384)@(384x128) + bias -> sigmoid -> z,r ----------------
__global__ void __launch_bounds__(256)
k_ngemm_gate()
{
    int n = blockIdx.x;
    __shared__ float As[64][36];
    __shared__ float Ws[32][128];
    int tid = threadIdx.x;
    int tx = tid & 15, ty = tid >> 4;

    float acc[4][8];
    #pragma unroll
    for (int i = 0; i < 4; i++)
        #pragma unroll
        for (int j = 0; j < 8; j++) acc[i][j] = 0.f;

    for (int kk = 0; kk < 384; kk += 32) {
        const float* buf = (kk < 128) ? g_Xin : ((kk < 256) ? g_xg1 : g_xg2);
        int i0 = kk & 127;
        #pragma unroll
        for (int i = 0; i < 2; i++) {
            int lin = tid + (i << 8);
            int b = lin >> 3;
            int tq = (lin & 7) << 2;
            float4 a = *(const float4*)&buf[n * BC + b * CIN + i0 + tq];
            *(float4*)&As[b][tq] = a;
        }
        #pragma unroll
        for (int i = 0; i < 4; i++) {
            int lin = tid + (i << 8);
            int t = lin >> 5;
            int oq = (lin & 31) << 2;
            *(float4*)&Ws[t][oq] = *(const float4*)&g_wg[n * KIO_G + (kk + t) * 128 + oq];
        }
        __syncthreads();

        #pragma unroll
        for (int k = 0; k < 32; k++) {
            float a0 = As[ty * 4 + 0][k];
            float a1 = As[ty * 4 + 1][k];
            float a2 = As[ty * 4 + 2][k];
            float a3 = As[ty * 4 + 3][k];
            float br[8];
            *(float4*)&br[0] = *(float4*)&Ws[k][tx * 8];
            *(float4*)&br[4] = *(float4*)&Ws[k][tx * 8 + 4];
            #pragma unroll
            for (int j = 0; j < 8; j++) {
                acc[0][j] += a0 * br[j];
                acc[1][j] += a1 * br[j];
                acc[2][j] += a2 * br[j];
                acc[3][j] += a3 * br[j];
            }
        }
        __syncthreads();
    }

    #pragma unroll
    for (int i = 0; i < 4; i++) {
        int b = ty * 4 + i;
        #pragma unroll
        for (int j = 0; j < 8; j++) {
            int o = tx * 8 + j;
            float v = acc[i][j] + g_bg[n * 128 + o];
            float s = 1.0f / (1.0f + expf(-v));
            int idx = b * (NN * HH) + n * HH + (o & 63);
            if (o < 64) g_z[idx] = s; else g_r[idx] = s;
        }
    }
}

// ---------------- 7) per-node update GEMM (64x384)@(384x64) + bias -> tanh -> GRU out ----------------
__global__ void __launch_bounds__(256)
k_ngemm_update(const float* __restrict__ state, float* __restrict__ dout)
{
    int n = blockIdx.x;
    __shared__ float As[64][36];
    __shared__ float Ws[32][68];
    int tid = threadIdx.x;
    int tx = tid & 15, ty = tid >> 4;

    float acc[4][4];
    #pragma unroll
    for (int i = 0; i < 4; i++)
        #pragma unroll
        for (int j = 0; j < 4; j++) acc[i][j] = 0.f;

    for (int kk = 0; kk < 384; kk += 32) {
        const float* buf = (kk < 128) ? g_Xin : ((kk < 256) ? g_xg1 : g_xg2);
        int i0 = kk & 127;
        #pragma unroll
        for (int i = 0; i < 2; i++) {
            int lin = tid + (i << 8);
            int b = lin >> 3;
            int tq = (lin & 7) << 2;
            float4 a = *(const float4*)&buf[n * BC + b * CIN + i0 + tq];
            *(float4*)&As[b][tq] = a;
        }
        #pragma unroll
        for (int i = 0; i < 2; i++) {
            int lin = tid + (i << 8);
            int t = lin >> 4;
            int oq = (lin & 15) << 2;
            *(float4*)&Ws[t][oq] = *(const float4*)&g_wu[n * KIO_U + (kk + t) * 64 + oq];
        }
        __syncthreads();

        #pragma unroll
        for (int k = 0; k < 32; k++) {
            float a0 = As[ty * 4 + 0][k];
            float a1 = As[ty * 4 + 1][k];
            float a2 = As[ty * 4 + 2][k];
            float a3 = As[ty * 4 + 3][k];
            float br[4];
            *(float4*)&br[0] = *(float4*)&Ws[k][tx * 4];
            #pragma unroll
            for (int j = 0; j < 4; j++) {
                acc[0][j] += a0 * br[j];
                acc[1][j] += a1 * br[j];
                acc[2][j] += a2 * br[j];
                acc[3][j] += a3 * br[j];
            }
        }
        __syncthreads();
    }

    #pragma unroll
    for (int i = 0; i < 4; i++) {
        int b = ty * 4 + i;
        #pragma unroll
        for (int j = 0; j < 4; j++) {
            int o = tx * 4 + j;
            float v = acc[i][j] + g_bu[n * 64 + o];
            float hc = tanhf(v);
            int idx = b * (NN * HH) + n * HH + o;
            float r = g_r[idx];
            float st = state[idx];
            dout[idx] = r * st + (1.0f - r) * hc;
        }
    }
}

// ---------------- launch ----------------
extern "C" void kernel_launch(void* const* d_in, const int* in_sizes, int n_in,
                              void* d_out, int out_size)
{
    const float* x         = (const float*)d_in[0];
    const float* state     = (const float*)d_in[2];
    const float* node_emb  = (const float*)d_in[3];
    const float* time_emb  = (const float*)d_in[5];
    const float* gate_W    = (const float*)d_in[6];
    const float* gate_b    = (const float*)d_in[7];
    const float* gate_lnw  = (const float*)d_in[8];
    const float* gate_lnb  = (const float*)d_in[9];
    const float* update_W  = (const float*)d_in[10];
    const float* update_b  = (const float*)d_in[11];
    const float* update_lnw= (const float*)d_in[12];
    const float* update_lnb= (const float*)d_in[13];
    float* out = (float*)d_out;

    float *Xin, *xg1, *xg2;
    unsigned short *Sgh, *Sgl, *Suh, *Sul, *XTh, *XTl, *YTh, *YTl;
    cudaGetSymbolAddress((void**)&Xin, g_Xin);
    cudaGetSymbolAddress((void**)&xg1, g_xg1);
    cudaGetSymbolAddress((void**)&xg2, g_xg2);
    cudaGetSymbolAddress((void**)&Sgh, g_Sgh);
    cudaGetSymbolAddress((void**)&Sgl, g_Sgl);
    cudaGetSymbolAddress((void**)&Suh, g_Suh);
    cudaGetSymbolAddress((void**)&Sul, g_Sul);
    cudaGetSymbolAddress((void**)&XTh, g_XTh);
    cudaGetSymbolAddress((void**)&XTl, g_XTl);
    cudaGetSymbolAddress((void**)&YTh, g_YTh);
    cudaGetSymbolAddress((void**)&YTl, g_YTl);

    cudaFuncSetAttribute(k_mmagemm, cudaFuncAttributeMaxDynamicSharedMemorySize, TCG_SMEM);

    k_prep<<<NN, 32>>>(node_emb, time_emb, gate_lnw, gate_lnb, update_lnw, update_lnb,
                       gate_b, update_b);
    k_supports<<<dim3(NN, 2), 256>>>();
    k_wgen<<<dim3(KIO_G / 256, NN / 16), 256>>>(gate_W, 0);
    k_wgen<<<dim3(KIO_U / 256, NN / 16), 256>>>(update_W, 1);

    dim3 gg(BC / 128, NN / 128);

    // ---- gate magcn ----
    k_build_xin<<<(NN * BC / 4) / 256, 256>>>(x, state, 0);
    k_splitT<<<dim3(BC / 32, NN / 32), dim3(32, 8)>>>(Xin, XTh, XTl);
    k_mmagemm<<<gg, 256, TCG_SMEM>>>(Sgh, Sgl, XTh, XTl, nullptr, xg1, YTh, YTl, 0);
    k_mmagemm<<<gg, 256, TCG_SMEM>>>(Sgh, Sgl, YTh, YTl, Xin, xg2, nullptr, nullptr, 1);
    k_ngemm_gate<<<NN, 256>>>();

    // ---- update magcn ----
    k_build_xin<<<(NN * BC / 4) / 256, 256>>>(x, state, 1);
    k_splitT<<<dim3(BC / 32, NN / 32), dim3(32, 8)>>>(Xin, XTh, XTl);
    k_mmagemm<<<gg, 256, TCG_SMEM>>>(Suh, Sul, XTh, XTl, nullptr, xg1, YTh, YTl, 0);
    k_mmagemm<<<gg, 256, TCG_SMEM>>>(Suh, Sul, YTh, YTl, Xin, xg2, nullptr, nullptr, 1);
    k_ngemm_update<<<NN, 256>>>(state, out);
}

// round 4
// speedup vs baseline: 2.2108x; 1.2239x over previous
#include <cuda_runtime.h>
#include <cuda_fp16.h>
#include <math.h>
#include <stdint.h>

#define NN 1024
#define BB 64
#define CC 64
#define HH 64
#define DD 16
#define CIN 128
#define BC 8192            // BB * CIN
#define KIO_G 49152        // 384*128
#define KIO_U 24576        // 384*64

// ---------------- scratch (static device globals; no allocation) ----------------
__device__ float g_eg[NN * DD];
__device__ float g_eu[NN * DD];
__device__ float g_bg[NN * 128];
__device__ float g_bu[NN * 64];
__device__ float g_Xin[NN * BC];
__device__ float g_z[BB * NN * HH];
__device__ float g_r[BB * NN * HH];

// fp16 split buffers (u16)
__device__ unsigned short g_Sgh[NN * NN];
__device__ unsigned short g_Sgl[NN * NN];
__device__ unsigned short g_Suh[NN * NN];
__device__ unsigned short g_Sul[NN * NN];
__device__ unsigned short g_XTh[BC * NN];   // transposed Xin split  [col][k]
__device__ unsigned short g_XTl[BC * NN];
__device__ unsigned short g_YTh[BC * NN];   // transposed xg1 split  [col][k]
__device__ unsigned short g_YTl[BC * NN];
// x stages untransposed [n][b*128+c] for node GEMMs
__device__ unsigned short g_X0h[NN * BC];
__device__ unsigned short g_X0l[NN * BC];
__device__ unsigned short g_X1h[NN * BC];
__device__ unsigned short g_X1l[NN * BC];
__device__ unsigned short g_X2h[NN * BC];
__device__ unsigned short g_X2l[NN * BC];
// per-node weights split [n][kidx][o]
__device__ unsigned short g_wgh[NN * KIO_G];
__device__ unsigned short g_wgl[NN * KIO_G];
__device__ unsigned short g_wuh[NN * KIO_U];
__device__ unsigned short g_wul[NN * KIO_U];

// ---------------- helpers ----------------
__device__ __forceinline__ uint32_t smem_to_u32(const void* p) {
    uint32_t a;
    asm("{ .reg .u64 t; cvta.to.shared.u64 t, %1; cvt.u32.u64 %0, t; }" : "=r"(a) : "l"(p));
    return a;
}

#define CP_ASYNC16(dst, src) \
    asm volatile("cp.async.cg.shared.global [%0], [%1], 16;" :: "r"(dst), "l"(src))
#define CP_COMMIT()  asm volatile("cp.async.commit_group;" ::: "memory")
#define CP_WAIT0()   asm volatile("cp.async.wait_group 0;" ::: "memory")

__device__ __forceinline__ void ldsm_x4(uint32_t& r0, uint32_t& r1, uint32_t& r2, uint32_t& r3,
                                        uint32_t addr) {
    asm volatile("ldmatrix.sync.aligned.m8n8.x4.shared.b16 {%0,%1,%2,%3}, [%4];"
                 : "=r"(r0), "=r"(r1), "=r"(r2), "=r"(r3) : "r"(addr));
}
__device__ __forceinline__ void ldsm_x4_t(uint32_t& r0, uint32_t& r1, uint32_t& r2, uint32_t& r3,
                                          uint32_t addr) {
    asm volatile("ldmatrix.sync.aligned.m8n8.x4.trans.shared.b16 {%0,%1,%2,%3}, [%4];"
                 : "=r"(r0), "=r"(r1), "=r"(r2), "=r"(r3) : "r"(addr));
}

__device__ __forceinline__ void mma16816(float* c, const uint32_t* a, const uint32_t* b) {
    asm volatile("mma.sync.aligned.m16n8k16.row.col.f32.f16.f16.f32 "
                 "{%0,%1,%2,%3}, {%4,%5,%6,%7}, {%8,%9}, {%0,%1,%2,%3};"
                 : "+f"(c[0]), "+f"(c[1]), "+f"(c[2]), "+f"(c[3])
                 : "r"(a[0]), "r"(a[1]), "r"(a[2]), "r"(a[3]), "r"(b[0]), "r"(b[1]));
}

__device__ __forceinline__ void f16split(float x, unsigned short& h, unsigned short& l) {
    __half hb = __float2half_rn(x);
    __half lb = __float2half_rn(x - __half2float(hb));
    h = *reinterpret_cast<unsigned short*>(&hb);
    l = *reinterpret_cast<unsigned short*>(&lb);
}

// ---------------- 1) e = LN(node_emb + time_emb), bias = e @ b_pool ----------------
__global__ void k_prep(const float* __restrict__ ne, const float* __restrict__ te,
                       const float* __restrict__ gw, const float* __restrict__ gbln,
                       const float* __restrict__ uw, const float* __restrict__ ubln,
                       const float* __restrict__ gate_b, const float* __restrict__ update_b)
{
    int n = blockIdx.x;
    int lane = threadIdx.x;          // 32 threads
    int d = lane & 15;
    float v = ne[n * DD + d] + te[d];

    float s = v;
    #pragma unroll
    for (int off = 16; off > 0; off >>= 1) s += __shfl_xor_sync(0xffffffffu, s, off);
    float mean = s * (1.0f / 32.0f);
    float dv = v - mean;
    float q = dv * dv;
    #pragma unroll
    for (int off = 16; off > 0; off >>= 1) q += __shfl_xor_sync(0xffffffffu, q, off);
    float var = q * (1.0f / 32.0f);
    float inv = rsqrtf(var + 1e-12f);

    float eg = dv * inv * gw[d] + gbln[d];
    float eu = dv * inv * uw[d] + ubln[d];
    if (lane < 16) { g_eg[n * DD + d] = eg; g_eu[n * DD + d] = eu; }

    for (int o = lane; o < 128; o += 32) {
        float b = 0.f;
        #pragma unroll
        for (int dd = 0; dd < 16; dd++)
            b += __shfl_sync(0xffffffffu, eg, dd) * gate_b[dd * 128 + o];
        g_bg[n * 128 + o] = b;
    }
    for (int o = lane; o < 64; o += 32) {
        float b = 0.f;
        #pragma unroll
        for (int dd = 0; dd < 16; dd++)
            b += __shfl_sync(0xffffffffu, eu, dd) * update_b[dd * 64 + o];
        g_bu[n * 64 + o] = b;
    }
}

// ---------------- 2) S = softmax(e e^T), fp16 hi/lo split ----------------
__global__ void k_supports()
{
    int n = blockIdx.x;
    int which = blockIdx.y;
    const float* e = which ? g_eu : g_eg;
    unsigned short* Sh = which ? g_Suh : g_Sgh;
    unsigned short* Sl = which ? g_Sul : g_Sgl;

    __shared__ float en[16];
    __shared__ float red[256];
    int tid = threadIdx.x;
    if (tid < 16) en[tid] = e[n * DD + tid];
    __syncthreads();

    float lv[4];
    float mx = -1e30f;
    #pragma unroll
    for (int i = 0; i < 4; i++) {
        int m = tid + i * 256;
        const float* em = &e[m * DD];
        float dot = 0.f;
        #pragma unroll
        for (int dd = 0; dd < 16; dd++) dot += en[dd] * em[dd];
        lv[i] = dot;
        mx = fmaxf(mx, dot);
    }
    red[tid] = mx; __syncthreads();
    for (int s = 128; s > 0; s >>= 1) {
        if (tid < s) red[tid] = fmaxf(red[tid], red[tid + s]);
        __syncthreads();
    }
    mx = red[0];
    __syncthreads();

    float sum = 0.f;
    #pragma unroll
    for (int i = 0; i < 4; i++) { lv[i] = expf(lv[i] - mx); sum += lv[i]; }
    red[tid] = sum; __syncthreads();
    for (int s = 128; s > 0; s >>= 1) {
        if (tid < s) red[tid] += red[tid + s];
        __syncthreads();
    }
    float invs = 1.0f / red[0];
    #pragma unroll
    for (int i = 0; i < 4; i++) {
        float v = lv[i] * invs;
        int idx = n * NN + tid + i * 256;
        unsigned short h, l;
        f16split(v, h, l);
        Sh[idx] = h; Sl[idx] = l;
    }
}

// ---------------- 3) per-node weights, fp16 split, [n][kidx][o] ----------------
__global__ void k_wgen(const float* __restrict__ Wp, int which)
{
    const int KIO = which ? KIO_U : KIO_G;
    unsigned short* wh = which ? g_wuh : g_wgh;
    unsigned short* wl = which ? g_wul : g_wgl;
    const float* e = which ? g_eu : g_eg;

    int tid = threadIdx.x;
    int kio = blockIdx.x * 256 + tid;
    int n0 = blockIdx.y * 32;

    __shared__ float es[512];
    es[tid] = e[n0 * DD + tid];
    es[tid + 256] = e[n0 * DD + 256 + tid];
    __syncthreads();

    float wr[16];
    #pragma unroll
    for (int dd = 0; dd < 16; dd++) wr[dd] = Wp[dd * KIO + kio];

    #pragma unroll
    for (int j = 0; j < 32; j++) {
        float a = 0.f;
        #pragma unroll
        for (int dd = 0; dd < 16; dd++) a += es[j * 16 + dd] * wr[dd];
        unsigned short h, l;
        f16split(a, h, l);
        size_t o = (size_t)(n0 + j) * KIO + kio;
        wh[o] = h; wl[o] = l;
    }
}

// ---------------- 4) build Xin (fp32 + fp16 split stage-0) ----------------
__global__ void k_build_xin(const float* __restrict__ x, const float* __restrict__ state, int mode)
{
    int t = blockIdx.x * 256 + threadIdx.x;
    int n = t >> 11;
    int j = t & 2047;
    int b = j >> 5;
    int c = (j & 31) << 2;

    float4 v;
    if (c < 64) {
        v = *(const float4*)&x[b * (NN * CC) + n * CC + c];
    } else {
        int cc = c - 64;
        float4 s4 = *(const float4*)&state[b * (NN * HH) + n * HH + cc];
        if (mode) {
            float4 z4 = *(const float4*)&g_z[b * (NN * HH) + n * HH + cc];
            v.x = z4.x * s4.x; v.y = z4.y * s4.y; v.z = z4.z * s4.z; v.w = z4.w * s4.w;
        } else {
            v = s4;
        }
    }
    int o = n * BC + b * CIN + c;
    *(float4*)&g_Xin[o] = v;

    ushort4 h4, l4;
    f16split(v.x, h4.x, l4.x); f16split(v.y, h4.y, l4.y);
    f16split(v.z, h4.z, l4.z); f16split(v.w, h4.w, l4.w);
    *(ushort4*)&g_X0h[o] = h4;
    *(ushort4*)&g_X0l[o] = l4;
}

// ---------------- 4b) split + transpose: Xin[1024][8192] -> XT[8192][1024] fp16 hi/lo ----------------
__global__ void k_splitT(const float* __restrict__ in,
                         unsigned short* __restrict__ oh, unsigned short* __restrict__ ol)
{
    __shared__ float t[32][33];
    int bx = blockIdx.x << 5;
    int by = blockIdx.y << 5;
    int x = threadIdx.x, y = threadIdx.y;  // 32 x 8
    #pragma unroll
    for (int i = 0; i < 4; i++)
        t[y + i * 8][x] = in[(by + y + i * 8) * BC + bx + x];
    __syncthreads();
    #pragma unroll
    for (int i = 0; i < 4; i++) {
        float v = t[x][y + i * 8];
        unsigned short h, l;
        f16split(v, h, l);
        int o = (bx + y + i * 8) * NN + by + x;
        oh[o] = h; ol[o] = l;
    }
}

// ---------------- 5) big tensor GEMM: acc(1024x8192) = A(1024x1024)@B(1024x8192), 3-term ----------------
// mode 0: emit X1h/X1l = split(acc) row-major, CTh/CTl = split(acc) transposed [col][row]
// mode 1: emit X2h/X2l = split(2*acc - Dmat) row-major
#define STAGE_BYTES 65536
#define TCG_SMEM 131072

__global__ void __launch_bounds__(256, 1)
k_mmagemm(const unsigned short* __restrict__ Ah, const unsigned short* __restrict__ Al,
          const unsigned short* __restrict__ Bh, const unsigned short* __restrict__ Bl,
          const float* __restrict__ Dmat,
          unsigned short* __restrict__ Xh, unsigned short* __restrict__ Xl,
          unsigned short* __restrict__ CTh, unsigned short* __restrict__ CTl,
          int mode)
{
    extern __shared__ char smem[];
    const uint32_t smem_u = smem_to_u32(smem);
    const int tid = threadIdx.x;
    const int wid = tid >> 5;
    const int lane = tid & 31;
    const int brow = blockIdx.y << 7;
    const int bcol = blockIdx.x << 7;
    const int wm = wid & 1;
    const int wn = wid >> 1;

    const unsigned short* srcs[4];
    srcs[0] = Ah + (size_t)brow * NN;
    srcs[1] = Al + (size_t)brow * NN;
    srcs[2] = Bh + (size_t)bcol * NN;
    srcs[3] = Bl + (size_t)bcol * NN;

    float acc[4][4][4];
    #pragma unroll
    for (int i = 0; i < 4; i++)
        #pragma unroll
        for (int j = 0; j < 4; j++)
            #pragma unroll
            for (int q = 0; q < 4; q++) acc[i][j][q] = 0.f;

    const int arow = wm * 64 + (lane & 15);
    const int axor = (arow & 7) << 4;
    const int agco = (lane >> 4) << 4;
    const int bn   = wn * 32 + ((lane >> 4) << 3) + (lane & 7);
    const int bxor = (bn & 7) << 4;
    const int bko  = ((lane >> 3) & 1) << 4;

    auto load_stage = [&](int buf, int kk) {
        uint32_t dst0 = smem_u + buf * STAGE_BYTES;
        #pragma unroll
        for (int i = 0; i < 16; i++) {
            int lin = tid + (i << 8);
            int arr = lin >> 10;
            int r = (lin >> 3) & 127;
            int cb = (lin & 7) << 4;
            const char* src = (const char*)(srcs[arr] + (size_t)r * NN + kk) + cb;
            uint32_t d = dst0 + arr * 16384 + r * 128 + (cb ^ ((r & 7) << 4));
            CP_ASYNC16(d, src);
        }
        CP_COMMIT();
    };

    load_stage(0, 0);

    #pragma unroll 1
    for (int s = 0; s < 16; s++) {
        const int buf = s & 1;
        CP_WAIT0();
        __syncthreads();
        if (s + 1 < 16) load_stage(1 - buf, (s + 1) << 6);

        const uint32_t sb = smem_u + buf * STAGE_BYTES;
        #pragma unroll
        for (int ks = 0; ks < 4; ks++) {
            const int c = ks << 5;
            uint32_t ah[4][4], al[4][4], bh[4][2], bl[4][2];
            #pragma unroll
            for (int mt = 0; mt < 4; mt++) {
                uint32_t ao = (uint32_t)((arow + mt * 16) * 128) + (uint32_t)((c + agco) ^ axor);
                ldsm_x4(ah[mt][0], ah[mt][1], ah[mt][2], ah[mt][3], sb + ao);
                ldsm_x4(al[mt][0], al[mt][1], al[mt][2], al[mt][3], sb + 16384 + ao);
            }
            #pragma unroll
            for (int nb = 0; nb < 2; nb++) {
                uint32_t bo = (uint32_t)((bn + nb * 16) * 128) + (uint32_t)((c + bko) ^ bxor);
                ldsm_x4(bh[2 * nb][0], bh[2 * nb][1], bh[2 * nb + 1][0], bh[2 * nb + 1][1],
                        sb + 32768 + bo);
                ldsm_x4(bl[2 * nb][0], bl[2 * nb][1], bl[2 * nb + 1][0], bl[2 * nb + 1][1],
                        sb + 49152 + bo);
            }
            #pragma unroll
            for (int mt = 0; mt < 4; mt++)
                #pragma unroll
                for (int nt = 0; nt < 4; nt++) {
                    mma16816(acc[mt][nt], ah[mt], bh[nt]);
                    mma16816(acc[mt][nt], ah[mt], bl[nt]);
                    mma16816(acc[mt][nt], al[mt], bh[nt]);
                }
        }
        __syncthreads();
    }

    // ---- epilogue via smem (128 x 129 fp32) ----
    float* sf = (float*)smem;
    __syncthreads();
    {
        int g = lane >> 2, t4 = lane & 3;
        #pragma unroll
        for (int mt = 0; mt < 4; mt++) {
            int m0 = wm * 64 + mt * 16 + g;
            #pragma unroll
            for (int nt = 0; nt < 4; nt++) {
                int n0 = wn * 32 + nt * 8 + 2 * t4;
                sf[m0 * 129 + n0]           = acc[mt][nt][0];
                sf[m0 * 129 + n0 + 1]       = acc[mt][nt][1];
                sf[(m0 + 8) * 129 + n0]     = acc[mt][nt][2];
                sf[(m0 + 8) * 129 + n0 + 1] = acc[mt][nt][3];
            }
        }
    }
    __syncthreads();

    if (mode == 0) {
        #pragma unroll 4
        for (int it = 0; it < 64; it++) {
            int idx = tid + (it << 8);
            int m = idx >> 7, j = idx & 127;
            float v = sf[m * 129 + j];
            unsigned short h, l;
            f16split(v, h, l);
            size_t o = (size_t)(brow + m) * BC + bcol + j;
            Xh[o] = h; Xl[o] = l;
        }
        #pragma unroll 4
        for (int it = 0; it < 64; it++) {
            int idx = tid + (it << 8);
            int j = idx >> 7, m = idx & 127;
            float v = sf[m * 129 + j];
            unsigned short h, l;
            f16split(v, h, l);
            size_t o = (size_t)(bcol + j) * NN + brow + m;
            CTh[o] = h; CTl[o] = l;
        }
    } else {
        #pragma unroll 4
        for (int it = 0; it < 64; it++) {
            int idx = tid + (it << 8);
            int m = idx >> 7, j = idx & 127;
            size_t o = (size_t)(brow + m) * BC + bcol + j;
            float v = 2.0f * sf[m * 129 + j] - Dmat[o];
            unsigned short h, l;
            f16split(v, h, l);
            Xh[o] = h; Xl[o] = l;
        }
    }
}

// ---------------- 6) tensor node GEMM gate: per node (64x384)@(384x128) -> sigmoid -> z,r ----------------
__global__ void __launch_bounds__(256)
k_tc_gate()
{
    __shared__ char sm[49152];  // Ah 8K | Al 8K | Bh 16K | Bl 16K
    const uint32_t su = smem_to_u32(sm);
    const int n = blockIdx.x;
    const int tid = threadIdx.x;
    const int wid = tid >> 5, lane = tid & 31;
    const int wm = wid & 1, wn = wid >> 1;

    const unsigned short* xh[3] = { g_X0h + (size_t)n * BC, g_X1h + (size_t)n * BC, g_X2h + (size_t)n * BC };
    const unsigned short* xl[3] = { g_X0l + (size_t)n * BC, g_X1l + (size_t)n * BC, g_X2l + (size_t)n * BC };
    const unsigned short* wh = g_wgh + (size_t)n * KIO_G;
    const unsigned short* wl = g_wgl + (size_t)n * KIO_G;

    float acc[2][4][4];
    #pragma unroll
    for (int i = 0; i < 2; i++)
        #pragma unroll
        for (int j = 0; j < 4; j++)
            #pragma unroll
            for (int q = 0; q < 4; q++) acc[i][j][q] = 0.f;

    const int arow = wm * 32 + (lane & 15);
    const int axor = (arow & 7) << 4;
    const int agco = (lane >> 4) << 4;
    const int brow = (lane & 7) + (((lane >> 3) & 1) << 3);
    const int bxor = (lane & 7) << 4;
    const int bgrp = (lane >> 4) << 4;

    #pragma unroll 1
    for (int q = 0; q < 6; q++) {
        const int t = q >> 1;
        const int c0 = (q & 1) << 6;        // element offset within stage row
        // A: 64 rows x 128B (hi, lo)
        #pragma unroll
        for (int i = 0; i < 2; i++) {
            int lin = tid + (i << 8);
            int r = lin >> 3;
            int cb = (lin & 7) << 4;
            uint32_t dsw = r * 128 + (cb ^ ((r & 7) << 4));
            CP_ASYNC16(su + dsw,        (const char*)(xh[t] + r * 128 + c0) + cb);
            CP_ASYNC16(su + 8192 + dsw, (const char*)(xl[t] + r * 128 + c0) + cb);
        }
        // B: 64 rows x 256B (hi, lo)
        #pragma unroll
        for (int i = 0; i < 4; i++) {
            int lin = tid + (i << 8);
            int kr = lin >> 4;
            int cb = (lin & 15) << 4;
            uint32_t dsw = kr * 256 + (cb ^ ((kr & 7) << 4));
            const char* sh = (const char*)(wh + (size_t)(q * 64 + kr) * 128) + cb;
            const char* sl = (const char*)(wl + (size_t)(q * 64 + kr) * 128) + cb;
            CP_ASYNC16(su + 16384 + dsw, sh);
            CP_ASYNC16(su + 32768 + dsw, sl);
        }
        CP_COMMIT();
        CP_WAIT0();
        __syncthreads();

        #pragma unroll
        for (int ks = 0; ks < 4; ks++) {
            const int c = ks << 5;
            uint32_t ah[2][4], al[2][4], bh[4][2], bl[4][2];
            #pragma unroll
            for (int mt = 0; mt < 2; mt++) {
                uint32_t ao = (uint32_t)((arow + mt * 16) * 128) + (uint32_t)((c + agco) ^ axor);
                ldsm_x4(ah[mt][0], ah[mt][1], ah[mt][2], ah[mt][3], su + ao);
                ldsm_x4(al[mt][0], al[mt][1], al[mt][2], al[mt][3], su + 8192 + ao);
            }
            #pragma unroll
            for (int nb = 0; nb < 2; nb++) {
                uint32_t bo = (uint32_t)((ks * 16 + brow) * 256)
                            + (uint32_t)((wn * 64 + nb * 32 + bgrp) ^ bxor);
                ldsm_x4_t(bh[2 * nb][0], bh[2 * nb][1], bh[2 * nb + 1][0], bh[2 * nb + 1][1],
                          su + 16384 + bo);
                ldsm_x4_t(bl[2 * nb][0], bl[2 * nb][1], bl[2 * nb + 1][0], bl[2 * nb + 1][1],
                          su + 32768 + bo);
            }
            #pragma unroll
            for (int mt = 0; mt < 2; mt++)
                #pragma unroll
                for (int nt = 0; nt < 4; nt++) {
                    mma16816(acc[mt][nt], ah[mt], bh[nt]);
                    mma16816(acc[mt][nt], ah[mt], bl[nt]);
                    mma16816(acc[mt][nt], al[mt], bh[nt]);
                }
        }
        __syncthreads();
    }

    // epilogue: bias + sigmoid -> z (o<64), r (o>=64)
    const int g = lane >> 2, t4 = lane & 3;
    #pragma unroll
    for (int mt = 0; mt < 2; mt++) {
        int b0 = wm * 32 + mt * 16 + g;
        #pragma unroll
        for (int nt = 0; nt < 4; nt++) {
            int o = wn * 32 + nt * 8 + 2 * t4;
            float bi0 = g_bg[n * 128 + o];
            float bi1 = g_bg[n * 128 + o + 1];
            #pragma unroll
            for (int half = 0; half < 2; half++) {
                int b = b0 + half * 8;
                float v0 = acc[mt][nt][2 * half]     + bi0;
                float v1 = acc[mt][nt][2 * half + 1] + bi1;
                float s0 = 1.0f / (1.0f + expf(-v0));
                float s1 = 1.0f / (1.0f + expf(-v1));
                int base = b * (NN * HH) + n * HH;
                if (o < 64) { g_z[base + o] = s0; g_z[base + o + 1] = s1; }
                else        { g_r[base + o - 64] = s0; g_r[base + o - 63] = s1; }
            }
        }
    }
}

// ---------------- 7) tensor node GEMM update: per node (64x384)@(384x64) -> tanh -> GRU out ----------------
__global__ void __launch_bounds__(128)
k_tc_upd(const float* __restrict__ state, float* __restrict__ dout)
{
    __shared__ char sm[32768];  // Ah 8K | Al 8K | Bh 8K | Bl 8K
    const uint32_t su = smem_to_u32(sm);
    const int n = blockIdx.x;
    const int tid = threadIdx.x;
    const int wid = tid >> 5, lane = tid & 31;
    const int wm = wid & 1, wn = wid >> 1;

    const unsigned short* xh[3] = { g_X0h + (size_t)n * BC, g_X1h + (size_t)n * BC, g_X2h + (size_t)n * BC };
    const unsigned short* xl[3] = { g_X0l + (size_t)n * BC, g_X1l + (size_t)n * BC, g_X2l + (size_t)n * BC };
    const unsigned short* wh = g_wuh + (size_t)n * KIO_U;
    const unsigned short* wl = g_wul + (size_t)n * KIO_U;

    float acc[2][4][4];
    #pragma unroll
    for (int i = 0; i < 2; i++)
        #pragma unroll
        for (int j = 0; j < 4; j++)
            #pragma unroll
            for (int q = 0; q < 4; q++) acc[i][j][q] = 0.f;

    const int arow = wm * 32 + (lane & 15);
    const int axor = (arow & 7) << 4;
    const int agco = (lane >> 4) << 4;
    const int brow = (lane & 7) + (((lane >> 3) & 1) << 3);
    const int bxor = (lane & 7) << 4;
    const int bgrp = (lane >> 4) << 4;

    #pragma unroll 1
    for (int q = 0; q < 6; q++) {
        const int t = q >> 1;
        const int c0 = (q & 1) << 6;
        // A: 64 rows x 128B
        #pragma unroll
        for (int i = 0; i < 4; i++) {
            int lin = tid + (i << 7);
            int r = lin >> 3;
            int cb = (lin & 7) << 4;
            uint32_t dsw = r * 128 + (cb ^ ((r & 7) << 4));
            CP_ASYNC16(su + dsw,        (const char*)(xh[t] + r * 128 + c0) + cb);
            CP_ASYNC16(su + 8192 + dsw, (const char*)(xl[t] + r * 128 + c0) + cb);
        }
        // B: 64 rows x 128B
        #pragma unroll
        for (int i = 0; i < 4; i++) {
            int lin = tid + (i << 7);
            int kr = lin >> 3;
            int cb = (lin & 7) << 4;
            uint32_t dsw = kr * 128 + (cb ^ ((kr & 7) << 4));
            CP_ASYNC16(su + 16384 + dsw, (const char*)(wh + (size_t)(q * 64 + kr) * 64) + cb);
            CP_ASYNC16(su + 24576 + dsw, (const char*)(wl + (size_t)(q * 64 + kr) * 64) + cb);
        }
        CP_COMMIT();
        CP_WAIT0();
        __syncthreads();

        #pragma unroll
        for (int ks = 0; ks < 4; ks++) {
            const int c = ks << 5;
            uint32_t ah[2][4], al[2][4], bh[4][2], bl[4][2];
            #pragma unroll
            for (int mt = 0; mt < 2; mt++) {
                uint32_t ao = (uint32_t)((arow + mt * 16) * 128) + (uint32_t)((c + agco) ^ axor);
                ldsm_x4(ah[mt][0], ah[mt][1], ah[mt][2], ah[mt][3], su + ao);
                ldsm_x4(al[mt][0], al[mt][1], al[mt][2], al[mt][3], su + 8192 + ao);
            }
            #pragma unroll
            for (int nb = 0; nb < 2; nb++) {
                uint32_t bo = (uint32_t)((ks * 16 + brow) * 128)
                            + (uint32_t)((wn * 64 + nb * 32 + bgrp) ^ bxor);
                ldsm_x4_t(bh[2 * nb][0], bh[2 * nb][1], bh[2 * nb + 1][0], bh[2 * nb + 1][1],
                          su + 16384 + bo);
                ldsm_x4_t(bl[2 * nb][0], bl[2 * nb][1], bl[2 * nb + 1][0], bl[2 * nb + 1][1],
                          su + 24576 + bo);
            }
            #pragma unroll
            for (int mt = 0; mt < 2; mt++)
                #pragma unroll
                for (int nt = 0; nt < 4; nt++) {
                    mma16816(acc[mt][nt], ah[mt], bh[nt]);
                    mma16816(acc[mt][nt], ah[mt], bl[nt]);
                    mma16816(acc[mt][nt], al[mt], bh[nt]);
                }
        }
        __syncthreads();
    }

    // epilogue: bias + tanh -> GRU out
    const int g = lane >> 2, t4 = lane & 3;
    #pragma unroll
    for (int mt = 0; mt < 2; mt++) {
        int b0 = wm * 32 + mt * 16 + g;
        #pragma unroll
        for (int nt = 0; nt < 4; nt++) {
            int o = wn * 32 + nt * 8 + 2 * t4;
            float bi0 = g_bu[n * 64 + o];
            float bi1 = g_bu[n * 64 + o + 1];
            #pragma unroll
            for (int half = 0; half < 2; half++) {
                int b = b0 + half * 8;
                float hc0 = tanhf(acc[mt][nt][2 * half]     + bi0);
                float hc1 = tanhf(acc[mt][nt][2 * half + 1] + bi1);
                int idx = b * (NN * HH) + n * HH + o;
                float r0 = g_r[idx],     st0 = state[idx];
                float r1 = g_r[idx + 1], st1 = state[idx + 1];
                dout[idx]     = r0 * st0 + (1.0f - r0) * hc0;
                dout[idx + 1] = r1 * st1 + (1.0f - r1) * hc1;
            }
        }
    }
}

// ---------------- launch ----------------
extern "C" void kernel_launch(void* const* d_in, const int* in_sizes, int n_in,
                              void* d_out, int out_size)
{
    const float* x         = (const float*)d_in[0];
    const float* state     = (const float*)d_in[2];
    const float* node_emb  = (const float*)d_in[3];
    const float* time_emb  = (const float*)d_in[5];
    const float* gate_W    = (const float*)d_in[6];
    const float* gate_b    = (const float*)d_in[7];
    const float* gate_lnw  = (const float*)d_in[8];
    const float* gate_lnb  = (const float*)d_in[9];
    const float* update_W  = (const float*)d_in[10];
    const float* update_b  = (const float*)d_in[11];
    const float* update_lnw= (const float*)d_in[12];
    const float* update_lnb= (const float*)d_in[13];
    float* out = (float*)d_out;

    float *Xin;
    unsigned short *Sgh, *Sgl, *Suh, *Sul, *XTh, *XTl, *YTh, *YTl;
    unsigned short *X1h, *X1l, *X2h, *X2l;
    cudaGetSymbolAddress((void**)&Xin, g_Xin);
    cudaGetSymbolAddress((void**)&Sgh, g_Sgh);
    cudaGetSymbolAddress((void**)&Sgl, g_Sgl);
    cudaGetSymbolAddress((void**)&Suh, g_Suh);
    cudaGetSymbolAddress((void**)&Sul, g_Sul);
    cudaGetSymbolAddress((void**)&XTh, g_XTh);
    cudaGetSymbolAddress((void**)&XTl, g_XTl);
    cudaGetSymbolAddress((void**)&YTh, g_YTh);
    cudaGetSymbolAddress((void**)&YTl, g_YTl);
    cudaGetSymbolAddress((void**)&X1h, g_X1h);
    cudaGetSymbolAddress((void**)&X1l, g_X1l);
    cudaGetSymbolAddress((void**)&X2h, g_X2h);
    cudaGetSymbolAddress((void**)&X2l, g_X2l);

    cudaFuncSetAttribute(k_mmagemm, cudaFuncAttributeMaxDynamicSharedMemorySize, TCG_SMEM);

    k_prep<<<NN, 32>>>(node_emb, time_emb, gate_lnw, gate_lnb, update_lnw, update_lnb,
                       gate_b, update_b);
    k_supports<<<dim3(NN, 2), 256>>>();
    k_wgen<<<dim3(KIO_G / 256, NN / 32), 256>>>(gate_W, 0);
    k_wgen<<<dim3(KIO_U / 256, NN / 32), 256>>>(update_W, 1);

    dim3 gg(BC / 128, NN / 128);

    // ---- gate magcn ----
    k_build_xin<<<(NN * BC / 4) / 256, 256>>>(x, state, 0);
    k_splitT<<<dim3(BC / 32, NN / 32), dim3(32, 8)>>>(Xin, XTh, XTl);
    k_mmagemm<<<gg, 256, TCG_SMEM>>>(Sgh, Sgl, XTh, XTl, nullptr, X1h, X1l, YTh, YTl, 0);
    k_mmagemm<<<gg, 256, TCG_SMEM>>>(Sgh, Sgl, YTh, YTl, Xin, X2h, X2l, nullptr, nullptr, 1);
    k_tc_gate<<<NN, 256>>>();

    // ---- update magcn ----
    k_build_xin<<<(NN * BC / 4) / 256, 256>>>(x, state, 1);
    k_splitT<<<dim3(BC / 32, NN / 32), dim3(32, 8)>>>(Xin, XTh, XTl);
    k_mmagemm<<<gg, 256, TCG_SMEM>>>(Suh, Sul, XTh, XTl, nullptr, X1h, X1l, YTh, YTl, 0);
    k_mmagemm<<<gg, 256, TCG_SMEM>>>(Suh, Sul, YTh, YTl, Xin, X2h, X2l, nullptr, nullptr, 1);
    k_tc_upd<<<NN, 128>>>(state, out);
}

// round 5
// speedup vs baseline: 2.6326x; 1.1908x over previous
#include <cuda_runtime.h>
#include <cuda_fp16.h>
#include <math.h>
#include <stdint.h>

#define NN 1024
#define BB 64
#define CC 64
#define HH 64
#define DD 16
#define CIN 128
#define BC 8192            // BB * CIN
#define KIO_G 49152        // 384*128
#define KIO_U 24576        // 384*64

// ---------------- scratch (static device globals; no allocation) ----------------
__device__ float g_eg[NN * DD];
__device__ float g_eu[NN * DD];
__device__ float g_bg[NN * 128];
__device__ float g_bu[NN * 64];
__device__ float g_z[BB * NN * HH];
__device__ float g_r[BB * NN * HH];

// fp16 split buffers (u16)
__device__ unsigned short g_Sgh[NN * NN];
__device__ unsigned short g_Sgl[NN * NN];
__device__ unsigned short g_Suh[NN * NN];
__device__ unsigned short g_Sul[NN * NN];
__device__ unsigned short g_XTh[BC * NN];   // transposed X0h  [col][k]
__device__ unsigned short g_YTh[BC * NN];   // transposed split(y1) hi [col][k]
// x stages untransposed [n][b*128+c] for node GEMMs
__device__ unsigned short g_X0h[NN * BC];
__device__ unsigned short g_X0l[NN * BC];
__device__ unsigned short g_X1h[NN * BC];
__device__ unsigned short g_X1l[NN * BC];
__device__ unsigned short g_X2h[NN * BC];
__device__ unsigned short g_X2l[NN * BC];
// per-node weights split [n][kidx][o]
__device__ unsigned short g_wgh[NN * KIO_G];
__device__ unsigned short g_wgl[NN * KIO_G];
__device__ unsigned short g_wuh[NN * KIO_U];
__device__ unsigned short g_wul[NN * KIO_U];

// ---------------- helpers ----------------
__device__ __forceinline__ uint32_t smem_to_u32(const void* p) {
    uint32_t a;
    asm("{ .reg .u64 t; cvta.to.shared.u64 t, %1; cvt.u32.u64 %0, t; }" : "=r"(a) : "l"(p));
    return a;
}

#define CP_ASYNC16(dst, src) \
    asm volatile("cp.async.cg.shared.global [%0], [%1], 16;" :: "r"(dst), "l"(src))
#define CP_COMMIT()  asm volatile("cp.async.commit_group;" ::: "memory")
#define CP_WAIT0()   asm volatile("cp.async.wait_group 0;" ::: "memory")

__device__ __forceinline__ void ldsm_x4(uint32_t& r0, uint32_t& r1, uint32_t& r2, uint32_t& r3,
                                        uint32_t addr) {
    asm volatile("ldmatrix.sync.aligned.m8n8.x4.shared.b16 {%0,%1,%2,%3}, [%4];"
                 : "=r"(r0), "=r"(r1), "=r"(r2), "=r"(r3) : "r"(addr));
}
__device__ __forceinline__ void ldsm_x4_t(uint32_t& r0, uint32_t& r1, uint32_t& r2, uint32_t& r3,
                                          uint32_t addr) {
    asm volatile("ldmatrix.sync.aligned.m8n8.x4.trans.shared.b16 {%0,%1,%2,%3}, [%4];"
                 : "=r"(r0), "=r"(r1), "=r"(r2), "=r"(r3) : "r"(addr));
}

__device__ __forceinline__ void mma16816(float* c, const uint32_t* a, const uint32_t* b) {
    asm volatile("mma.sync.aligned.m16n8k16.row.col.f32.f16.f16.f32 "
                 "{%0,%1,%2,%3}, {%4,%5,%6,%7}, {%8,%9}, {%0,%1,%2,%3};"
                 : "+f"(c[0]), "+f"(c[1]), "+f"(c[2]), "+f"(c[3])
                 : "r"(a[0]), "r"(a[1]), "r"(a[2]), "r"(a[3]), "r"(b[0]), "r"(b[1]));
}

__device__ __forceinline__ void f16split(float x, unsigned short& h, unsigned short& l) {
    __half hb = __float2half_rn(x);
    __half lb = __float2half_rn(x - __half2float(hb));
    h = *reinterpret_cast<unsigned short*>(&hb);
    l = *reinterpret_cast<unsigned short*>(&lb);
}
__device__ __forceinline__ float f16join(unsigned short h, unsigned short l) {
    return __half2float(*reinterpret_cast<__half*>(&h)) +
           __half2float(*reinterpret_cast<__half*>(&l));
}

// ---------------- 1) e = LN(node_emb + time_emb), bias = e @ b_pool ----------------
__global__ void k_prep(const float* __restrict__ ne, const float* __restrict__ te,
                       const float* __restrict__ gw, const float* __restrict__ gbln,
                       const float* __restrict__ uw, const float* __restrict__ ubln,
                       const float* __restrict__ gate_b, const float* __restrict__ update_b)
{
    int n = blockIdx.x;
    int lane = threadIdx.x;          // 32 threads
    int d = lane & 15;
    float v = ne[n * DD + d] + te[d];

    float s = v;
    #pragma unroll
    for (int off = 16; off > 0; off >>= 1) s += __shfl_xor_sync(0xffffffffu, s, off);
    float mean = s * (1.0f / 32.0f);
    float dv = v - mean;
    float q = dv * dv;
    #pragma unroll
    for (int off = 16; off > 0; off >>= 1) q += __shfl_xor_sync(0xffffffffu, q, off);
    float var = q * (1.0f / 32.0f);
    float inv = rsqrtf(var + 1e-12f);

    float eg = dv * inv * gw[d] + gbln[d];
    float eu = dv * inv * uw[d] + ubln[d];
    if (lane < 16) { g_eg[n * DD + d] = eg; g_eu[n * DD + d] = eu; }

    for (int o = lane; o < 128; o += 32) {
        float b = 0.f;
        #pragma unroll
        for (int dd = 0; dd < 16; dd++)
            b += __shfl_sync(0xffffffffu, eg, dd) * gate_b[dd * 128 + o];
        g_bg[n * 128 + o] = b;
    }
    for (int o = lane; o < 64; o += 32) {
        float b = 0.f;
        #pragma unroll
        for (int dd = 0; dd < 16; dd++)
            b += __shfl_sync(0xffffffffu, eu, dd) * update_b[dd * 64 + o];
        g_bu[n * 64 + o] = b;
    }
}

// ---------------- 2) S = softmax(e e^T), fp16 hi/lo split ----------------
__global__ void k_supports()
{
    int n = blockIdx.x;
    int which = blockIdx.y;
    const float* e = which ? g_eu : g_eg;
    unsigned short* Sh = which ? g_Suh : g_Sgh;
    unsigned short* Sl = which ? g_Sul : g_Sgl;

    __shared__ float en[16];
    __shared__ float red[256];
    int tid = threadIdx.x;
    if (tid < 16) en[tid] = e[n * DD + tid];
    __syncthreads();

    float lv[4];
    float mx = -1e30f;
    #pragma unroll
    for (int i = 0; i < 4; i++) {
        int m = tid + i * 256;
        const float* em = &e[m * DD];
        float dot = 0.f;
        #pragma unroll
        for (int dd = 0; dd < 16; dd++) dot += en[dd] * em[dd];
        lv[i] = dot;
        mx = fmaxf(mx, dot);
    }
    red[tid] = mx; __syncthreads();
    for (int s = 128; s > 0; s >>= 1) {
        if (tid < s) red[tid] = fmaxf(red[tid], red[tid + s]);
        __syncthreads();
    }
    mx = red[0];
    __syncthreads();

    float sum = 0.f;
    #pragma unroll
    for (int i = 0; i < 4; i++) { lv[i] = expf(lv[i] - mx); sum += lv[i]; }
    red[tid] = sum; __syncthreads();
    for (int s = 128; s > 0; s >>= 1) {
        if (tid < s) red[tid] += red[tid + s];
        __syncthreads();
    }
    float invs = 1.0f / red[0];
    #pragma unroll
    for (int i = 0; i < 4; i++) {
        float v = lv[i] * invs;
        int idx = n * NN + tid + i * 256;
        unsigned short h, l;
        f16split(v, h, l);
        Sh[idx] = h; Sl[idx] = l;
    }
}

// ---------------- 3) per-node weights, fp16 split, [n][kidx][o] ----------------
__global__ void k_wgen(const float* __restrict__ Wp, int which)
{
    const int KIO = which ? KIO_U : KIO_G;
    unsigned short* wh = which ? g_wuh : g_wgh;
    unsigned short* wl = which ? g_wul : g_wgl;
    const float* e = which ? g_eu : g_eg;

    int tid = threadIdx.x;
    int kio = blockIdx.x * 256 + tid;
    int n0 = blockIdx.y * 32;

    __shared__ float es[512];
    es[tid] = e[n0 * DD + tid];
    es[tid + 256] = e[n0 * DD + 256 + tid];
    __syncthreads();

    float wr[16];
    #pragma unroll
    for (int dd = 0; dd < 16; dd++) wr[dd] = Wp[dd * KIO + kio];

    #pragma unroll
    for (int j = 0; j < 32; j++) {
        float a = 0.f;
        #pragma unroll
        for (int dd = 0; dd < 16; dd++) a += es[j * 16 + dd] * wr[dd];
        unsigned short h, l;
        f16split(a, h, l);
        size_t o = (size_t)(n0 + j) * KIO + kio;
        wh[o] = h; wl[o] = l;
    }
}

// ---------------- 4) build X0 splits only ----------------
__global__ void k_build_xin(const float* __restrict__ x, const float* __restrict__ state, int mode)
{
    int t = blockIdx.x * 256 + threadIdx.x;
    int n = t >> 11;
    int j = t & 2047;
    int b = j >> 5;
    int c = (j & 31) << 2;

    float4 v;
    if (c < 64) {
        v = *(const float4*)&x[b * (NN * CC) + n * CC + c];
    } else {
        int cc = c - 64;
        float4 s4 = *(const float4*)&state[b * (NN * HH) + n * HH + cc];
        if (mode) {
            float4 z4 = *(const float4*)&g_z[b * (NN * HH) + n * HH + cc];
            v.x = z4.x * s4.x; v.y = z4.y * s4.y; v.z = z4.z * s4.z; v.w = z4.w * s4.w;
        } else {
            v = s4;
        }
    }
    int o = n * BC + b * CIN + c;
    ushort4 h4, l4;
    f16split(v.x, h4.x, l4.x); f16split(v.y, h4.y, l4.y);
    f16split(v.z, h4.z, l4.z); f16split(v.w, h4.w, l4.w);
    *(ushort4*)&g_X0h[o] = h4;
    *(ushort4*)&g_X0l[o] = l4;
}

// ---------------- 4b) u16 transpose: X0h[1024][8192] -> XTh[8192][1024] ----------------
__global__ void k_transpose(const unsigned short* __restrict__ in,
                            unsigned short* __restrict__ outp)
{
    __shared__ unsigned short t[32][34];
    int bc = blockIdx.x << 5;   // col tile (8192 dim)
    int bn = blockIdx.y << 5;   // row tile (1024 dim)
    int x = threadIdx.x, y = threadIdx.y;  // 32 x 8
    #pragma unroll
    for (int i = 0; i < 4; i++)
        t[y + i * 8][x] = in[(bn + y + i * 8) * BC + bc + x];
    __syncthreads();
    #pragma unroll
    for (int i = 0; i < 4; i++)
        outp[(bc + y + i * 8) * NN + bn + x] = t[x][y + i * 8];
}

// ---------------- 5) big tensor GEMM (2-term): acc = (Ah+Al) @ Bh ----------------
// mode 0: emit X1h/X1l = split(acc) row-major, CTh = fp16(acc) transposed [col][row]
// mode 1: emit X2h/X2l = split(2*acc - (D0h+D0l)) row-major
#define STAGE_BYTES 49152
#define TCG_SMEM 98304

__global__ void __launch_bounds__(256, 1)
k_mmagemm(const unsigned short* __restrict__ Ah, const unsigned short* __restrict__ Al,
          const unsigned short* __restrict__ Bh,
          const unsigned short* __restrict__ D0h, const unsigned short* __restrict__ D0l,
          unsigned short* __restrict__ Xh, unsigned short* __restrict__ Xl,
          unsigned short* __restrict__ CTh,
          int mode)
{
    extern __shared__ char smem[];
    const uint32_t smem_u = smem_to_u32(smem);
    const int tid = threadIdx.x;
    const int wid = tid >> 5;
    const int lane = tid & 31;
    const int brow = blockIdx.y << 7;
    const int bcol = blockIdx.x << 7;
    const int wm = wid & 1;
    const int wn = wid >> 1;

    const unsigned short* srcs[3];
    srcs[0] = Ah + (size_t)brow * NN;
    srcs[1] = Al + (size_t)brow * NN;
    srcs[2] = Bh + (size_t)bcol * NN;

    float acc[4][4][4];
    #pragma unroll
    for (int i = 0; i < 4; i++)
        #pragma unroll
        for (int j = 0; j < 4; j++)
            #pragma unroll
            for (int q = 0; q < 4; q++) acc[i][j][q] = 0.f;

    const int arow = wm * 64 + (lane & 15);
    const int axor = (arow & 7) << 4;
    const int agco = (lane >> 4) << 4;
    const int bn   = wn * 32 + ((lane >> 4) << 3) + (lane & 7);
    const int bxor = (bn & 7) << 4;
    const int bko  = ((lane >> 3) & 1) << 4;

    auto load_stage = [&](int buf, int kk) {
        uint32_t dst0 = smem_u + buf * STAGE_BYTES;
        #pragma unroll
        for (int i = 0; i < 12; i++) {
            int lin = tid + (i << 8);            // 0..3071
            int arr = lin >> 10;
            int r = (lin >> 3) & 127;
            int cb = (lin & 7) << 4;
            const char* src = (const char*)(srcs[arr] + (size_t)r * NN + kk) + cb;
            uint32_t d = dst0 + arr * 16384 + r * 128 + (cb ^ ((r & 7) << 4));
            CP_ASYNC16(d, src);
        }
        CP_COMMIT();
    };

    load_stage(0, 0);

    #pragma unroll 1
    for (int s = 0; s < 16; s++) {
        const int buf = s & 1;
        CP_WAIT0();
        __syncthreads();
        if (s + 1 < 16) load_stage(1 - buf, (s + 1) << 6);

        const uint32_t sb = smem_u + buf * STAGE_BYTES;
        #pragma unroll
        for (int ks = 0; ks < 4; ks++) {
            const int c = ks << 5;
            uint32_t ah[4][4], al[4][4], bh[4][2];
            #pragma unroll
            for (int mt = 0; mt < 4; mt++) {
                uint32_t ao = (uint32_t)((arow + mt * 16) * 128) + (uint32_t)((c + agco) ^ axor);
                ldsm_x4(ah[mt][0], ah[mt][1], ah[mt][2], ah[mt][3], sb + ao);
                ldsm_x4(al[mt][0], al[mt][1], al[mt][2], al[mt][3], sb + 16384 + ao);
            }
            #pragma unroll
            for (int nb = 0; nb < 2; nb++) {
                uint32_t bo = (uint32_t)((bn + nb * 16) * 128) + (uint32_t)((c + bko) ^ bxor);
                ldsm_x4(bh[2 * nb][0], bh[2 * nb][1], bh[2 * nb + 1][0], bh[2 * nb + 1][1],
                        sb + 32768 + bo);
            }
            #pragma unroll
            for (int mt = 0; mt < 4; mt++)
                #pragma unroll
                for (int nt = 0; nt < 4; nt++) {
                    mma16816(acc[mt][nt], ah[mt], bh[nt]);
                    mma16816(acc[mt][nt], al[mt], bh[nt]);
                }
        }
        __syncthreads();
    }

    // ---- epilogue via smem (128 x 129 fp32) ----
    float* sf = (float*)smem;
    __syncthreads();
    {
        int g = lane >> 2, t4 = lane & 3;
        #pragma unroll
        for (int mt = 0; mt < 4; mt++) {
            int m0 = wm * 64 + mt * 16 + g;
            #pragma unroll
            for (int nt = 0; nt < 4; nt++) {
                int n0 = wn * 32 + nt * 8 + 2 * t4;
                sf[m0 * 129 + n0]           = acc[mt][nt][0];
                sf[m0 * 129 + n0 + 1]       = acc[mt][nt][1];
                sf[(m0 + 8) * 129 + n0]     = acc[mt][nt][2];
                sf[(m0 + 8) * 129 + n0 + 1] = acc[mt][nt][3];
            }
        }
    }
    __syncthreads();

    if (mode == 0) {
        #pragma unroll 4
        for (int it = 0; it < 64; it++) {
            int idx = tid + (it << 8);
            int m = idx >> 7, j = idx & 127;
            float v = sf[m * 129 + j];
            unsigned short h, l;
            f16split(v, h, l);
            size_t o = (size_t)(brow + m) * BC + bcol + j;
            Xh[o] = h; Xl[o] = l;
        }
        #pragma unroll 4
        for (int it = 0; it < 64; it++) {
            int idx = tid + (it << 8);
            int j = idx >> 7, m = idx & 127;
            float v = sf[m * 129 + j];
            __half hh = __float2half_rn(v);
            CTh[(size_t)(bcol + j) * NN + brow + m] = *reinterpret_cast<unsigned short*>(&hh);
        }
    } else {
        #pragma unroll 4
        for (int it = 0; it < 64; it++) {
            int idx = tid + (it << 8);
            int m = idx >> 7, j = idx & 127;
            size_t o = (size_t)(brow + m) * BC + bcol + j;
            float d = f16join(D0h[o], D0l[o]);
            float v = 2.0f * sf[m * 129 + j] - d;
            unsigned short h, l;
            f16split(v, h, l);
            Xh[o] = h; Xl[o] = l;
        }
    }
}

// ---------------- 6) tensor node GEMM gate: per node (64x384)@(384x128) -> sigmoid -> z,r ----------------
__global__ void __launch_bounds__(256)
k_tc_gate()
{
    __shared__ char sm[49152];  // Ah 8K | Al 8K | Bh 16K | Bl 16K
    const uint32_t su = smem_to_u32(sm);
    const int n = blockIdx.x;
    const int tid = threadIdx.x;
    const int wid = tid >> 5, lane = tid & 31;
    const int wm = wid & 1, wn = wid >> 1;

    const unsigned short* xh[3] = { g_X0h + (size_t)n * BC, g_X1h + (size_t)n * BC, g_X2h + (size_t)n * BC };
    const unsigned short* xl[3] = { g_X0l + (size_t)n * BC, g_X1l + (size_t)n * BC, g_X2l + (size_t)n * BC };
    const unsigned short* wh = g_wgh + (size_t)n * KIO_G;
    const unsigned short* wl = g_wgl + (size_t)n * KIO_G;

    float acc[2][4][4];
    #pragma unroll
    for (int i = 0; i < 2; i++)
        #pragma unroll
        for (int j = 0; j < 4; j++)
            #pragma unroll
            for (int q = 0; q < 4; q++) acc[i][j][q] = 0.f;

    const int arow = wm * 32 + (lane & 15);
    const int axor = (arow & 7) << 4;
    const int agco = (lane >> 4) << 4;
    const int brow = (lane & 7) + (((lane >> 3) & 1) << 3);
    const int bxor = (lane & 7) << 4;
    const int bgrp = (lane >> 4) << 4;

    #pragma unroll 1
    for (int q = 0; q < 6; q++) {
        const int t = q >> 1;
        const int c0 = (q & 1) << 6;        // element offset within stage row
        // A: 64 rows x 128B (hi, lo)
        #pragma unroll
        for (int i = 0; i < 2; i++) {
            int lin = tid + (i << 8);
            int r = lin >> 3;
            int cb = (lin & 7) << 4;
            uint32_t dsw = r * 128 + (cb ^ ((r & 7) << 4));
            CP_ASYNC16(su + dsw,        (const char*)(xh[t] + r * 128 + c0) + cb);
            CP_ASYNC16(su + 8192 + dsw, (const char*)(xl[t] + r * 128 + c0) + cb);
        }
        // B: 64 rows x 256B (hi, lo)
        #pragma unroll
        for (int i = 0; i < 4; i++) {
            int lin = tid + (i << 8);
            int kr = lin >> 4;
            int cb = (lin & 15) << 4;
            uint32_t dsw = kr * 256 + (cb ^ ((kr & 7) << 4));
            const char* sh = (const char*)(wh + (size_t)(q * 64 + kr) * 128) + cb;
            const char* sl = (const char*)(wl + (size_t)(q * 64 + kr) * 128) + cb;
            CP_ASYNC16(su + 16384 + dsw, sh);
            CP_ASYNC16(su + 32768 + dsw, sl);
        }
        CP_COMMIT();
        CP_WAIT0();
        __syncthreads();

        #pragma unroll
        for (int ks = 0; ks < 4; ks++) {
            const int c = ks << 5;
            uint32_t ah[2][4], al[2][4], bh[4][2], bl[4][2];
            #pragma unroll
            for (int mt = 0; mt < 2; mt++) {
                uint32_t ao = (uint32_t)((arow + mt * 16) * 128) + (uint32_t)((c + agco) ^ axor);
                ldsm_x4(ah[mt][0], ah[mt][1], ah[mt][2], ah[mt][3], su + ao);
                ldsm_x4(al[mt][0], al[mt][1], al[mt][2], al[mt][3], su + 8192 + ao);
            }
            #pragma unroll
            for (int nb = 0; nb < 2; nb++) {
                uint32_t bo = (uint32_t)((ks * 16 + brow) * 256)
                            + (uint32_t)((wn * 64 + nb * 32 + bgrp) ^ bxor);
                ldsm_x4_t(bh[2 * nb][0], bh[2 * nb][1], bh[2 * nb + 1][0], bh[2 * nb + 1][1],
                          su + 16384 + bo);
                ldsm_x4_t(bl[2 * nb][0], bl[2 * nb][1], bl[2 * nb + 1][0], bl[2 * nb + 1][1],
                          su + 32768 + bo);
            }
            #pragma unroll
            for (int mt = 0; mt < 2; mt++)
                #pragma unroll
                for (int nt = 0; nt < 4; nt++) {
                    mma16816(acc[mt][nt], ah[mt], bh[nt]);
                    mma16816(acc[mt][nt], ah[mt], bl[nt]);
                    mma16816(acc[mt][nt], al[mt], bh[nt]);
                }
        }
        __syncthreads();
    }

    // epilogue: bias + sigmoid -> z (o<64), r (o>=64)
    const int g = lane >> 2, t4 = lane & 3;
    #pragma unroll
    for (int mt = 0; mt < 2; mt++) {
        int b0 = wm * 32 + mt * 16 + g;
        #pragma unroll
        for (int nt = 0; nt < 4; nt++) {
            int o = wn * 32 + nt * 8 + 2 * t4;
            float bi0 = g_bg[n * 128 + o];
            float bi1 = g_bg[n * 128 + o + 1];
            #pragma unroll
            for (int half = 0; half < 2; half++) {
                int b = b0 + half * 8;
                float v0 = acc[mt][nt][2 * half]     + bi0;
                float v1 = acc[mt][nt][2 * half + 1] + bi1;
                float s0 = 1.0f / (1.0f + expf(-v0));
                float s1 = 1.0f / (1.0f + expf(-v1));
                int base = b * (NN * HH) + n * HH;
                if (o < 64) { g_z[base + o] = s0; g_z[base + o + 1] = s1; }
                else        { g_r[base + o - 64] = s0; g_r[base + o - 63] = s1; }
            }
        }
    }
}

// ---------------- 7) tensor node GEMM update: per node (64x384)@(384x64) -> tanh -> GRU out ----------------
__global__ void __launch_bounds__(128)
k_tc_upd(const float* __restrict__ state, float* __restrict__ dout)
{
    __shared__ char sm[32768];  // Ah 8K | Al 8K | Bh 8K | Bl 8K
    const uint32_t su = smem_to_u32(sm);
    const int n = blockIdx.x;
    const int tid = threadIdx.x;
    const int wid = tid >> 5, lane = tid & 31;
    const int wm = wid & 1, wn = wid >> 1;

    const unsigned short* xh[3] = { g_X0h + (size_t)n * BC, g_X1h + (size_t)n * BC, g_X2h + (size_t)n * BC };
    const unsigned short* xl[3] = { g_X0l + (size_t)n * BC, g_X1l + (size_t)n * BC, g_X2l + (size_t)n * BC };
    const unsigned short* wh = g_wuh + (size_t)n * KIO_U;
    const unsigned short* wl = g_wul + (size_t)n * KIO_U;

    float acc[2][4][4];
    #pragma unroll
    for (int i = 0; i < 2; i++)
        #pragma unroll
        for (int j = 0; j < 4; j++)
            #pragma unroll
            for (int q = 0; q < 4; q++) acc[i][j][q] = 0.f;

    const int arow = wm * 32 + (lane & 15);
    const int axor = (arow & 7) << 4;
    const int agco = (lane >> 4) << 4;
    const int brow = (lane & 7) + (((lane >> 3) & 1) << 3);
    const int bxor = (lane & 7) << 4;
    const int bgrp = (lane >> 4) << 4;

    #pragma unroll 1
    for (int q = 0; q < 6; q++) {
        const int t = q >> 1;
        const int c0 = (q & 1) << 6;
        // A: 64 rows x 128B
        #pragma unroll
        for (int i = 0; i < 4; i++) {
            int lin = tid + (i << 7);
            int r = lin >> 3;
            int cb = (lin & 7) << 4;
            uint32_t dsw = r * 128 + (cb ^ ((r & 7) << 4));
            CP_ASYNC16(su + dsw,        (const char*)(xh[t] + r * 128 + c0) + cb);
            CP_ASYNC16(su + 8192 + dsw, (const char*)(xl[t] + r * 128 + c0) + cb);
        }
        // B: 64 rows x 128B
        #pragma unroll
        for (int i = 0; i < 4; i++) {
            int lin = tid + (i << 7);
            int kr = lin >> 3;
            int cb = (lin & 7) << 4;
            uint32_t dsw = kr * 128 + (cb ^ ((kr & 7) << 4));
            CP_ASYNC16(su + 16384 + dsw, (const char*)(wh + (size_t)(q * 64 + kr) * 64) + cb);
            CP_ASYNC16(su + 24576 + dsw, (const char*)(wl + (size_t)(q * 64 + kr) * 64) + cb);
        }
        CP_COMMIT();
        CP_WAIT0();
        __syncthreads();

        #pragma unroll
        for (int ks = 0; ks < 4; ks++) {
            const int c = ks << 5;
            uint32_t ah[2][4], al[2][4], bh[4][2], bl[4][2];
            #pragma unroll
            for (int mt = 0; mt < 2; mt++) {
                uint32_t ao = (uint32_t)((arow + mt * 16) * 128) + (uint32_t)((c + agco) ^ axor);
                ldsm_x4(ah[mt][0], ah[mt][1], ah[mt][2], ah[mt][3], su + ao);
                ldsm_x4(al[mt][0], al[mt][1], al[mt][2], al[mt][3], su + 8192 + ao);
            }
            #pragma unroll
            for (int nb = 0; nb < 2; nb++) {
                uint32_t bo = (uint32_t)((ks * 16 + brow) * 128)
                            + (uint32_t)((wn * 64 + nb * 32 + bgrp) ^ bxor);
                ldsm_x4_t(bh[2 * nb][0], bh[2 * nb][1], bh[2 * nb + 1][0], bh[2 * nb + 1][1],
                          su + 16384 + bo);
                ldsm_x4_t(bl[2 * nb][0], bl[2 * nb][1], bl[2 * nb + 1][0], bl[2 * nb + 1][1],
                          su + 24576 + bo);
            }
            #pragma unroll
            for (int mt = 0; mt < 2; mt++)
                #pragma unroll
                for (int nt = 0; nt < 4; nt++) {
                    mma16816(acc[mt][nt], ah[mt], bh[nt]);
                    mma16816(acc[mt][nt], ah[mt], bl[nt]);
                    mma16816(acc[mt][nt], al[mt], bh[nt]);
                }
        }
        __syncthreads();
    }

    // epilogue: bias + tanh -> GRU out
    const int g = lane >> 2, t4 = lane & 3;
    #pragma unroll
    for (int mt = 0; mt < 2; mt++) {
        int b0 = wm * 32 + mt * 16 + g;
        #pragma unroll
        for (int nt = 0; nt < 4; nt++) {
            int o = wn * 32 + nt * 8 + 2 * t4;
            float bi0 = g_bu[n * 64 + o];
            float bi1 = g_bu[n * 64 + o + 1];
            #pragma unroll
            for (int half = 0; half < 2; half++) {
                int b = b0 + half * 8;
                float hc0 = tanhf(acc[mt][nt][2 * half]     + bi0);
                float hc1 = tanhf(acc[mt][nt][2 * half + 1] + bi1);
                int idx = b * (NN * HH) + n * HH + o;
                float r0 = g_r[idx],     st0 = state[idx];
                float r1 = g_r[idx + 1], st1 = state[idx + 1];
                dout[idx]     = r0 * st0 + (1.0f - r0) * hc0;
                dout[idx + 1] = r1 * st1 + (1.0f - r1) * hc1;
            }
        }
    }
}

// ---------------- launch ----------------
extern "C" void kernel_launch(void* const* d_in, const int* in_sizes, int n_in,
                              void* d_out, int out_size)
{
    const float* x         = (const float*)d_in[0];
    const float* state     = (const float*)d_in[2];
    const float* node_emb  = (const float*)d_in[3];
    const float* time_emb  = (const float*)d_in[5];
    const float* gate_W    = (const float*)d_in[6];
    const float* gate_b    = (const float*)d_in[7];
    const float* gate_lnw  = (const float*)d_in[8];
    const float* gate_lnb  = (const float*)d_in[9];
    const float* update_W  = (const float*)d_in[10];
    const float* update_b  = (const float*)d_in[11];
    const float* update_lnw= (const float*)d_in[12];
    const float* update_lnb= (const float*)d_in[13];
    float* out = (float*)d_out;

    unsigned short *Sgh, *Sgl, *Suh, *Sul, *XTh, *YTh;
    unsigned short *X0h, *X0l, *X1h, *X1l, *X2h, *X2l;
    cudaGetSymbolAddress((void**)&Sgh, g_Sgh);
    cudaGetSymbolAddress((void**)&Sgl, g_Sgl);
    cudaGetSymbolAddress((void**)&Suh, g_Suh);
    cudaGetSymbolAddress((void**)&Sul, g_Sul);
    cudaGetSymbolAddress((void**)&XTh, g_XTh);
    cudaGetSymbolAddress((void**)&YTh, g_YTh);
    cudaGetSymbolAddress((void**)&X0h, g_X0h);
    cudaGetSymbolAddress((void**)&X0l, g_X0l);
    cudaGetSymbolAddress((void**)&X1h, g_X1h);
    cudaGetSymbolAddress((void**)&X1l, g_X1l);
    cudaGetSymbolAddress((void**)&X2h, g_X2h);
    cudaGetSymbolAddress((void**)&X2l, g_X2l);

    cudaFuncSetAttribute(k_mmagemm, cudaFuncAttributeMaxDynamicSharedMemorySize, TCG_SMEM);

    k_prep<<<NN, 32>>>(node_emb, time_emb, gate_lnw, gate_lnb, update_lnw, update_lnb,
                       gate_b, update_b);
    k_supports<<<dim3(NN, 2), 256>>>();
    k_wgen<<<dim3(KIO_G / 256, NN / 32), 256>>>(gate_W, 0);
    k_wgen<<<dim3(KIO_U / 256, NN / 32), 256>>>(update_W, 1);

    dim3 gg(BC / 128, NN / 128);

    // ---- gate magcn ----
    k_build_xin<<<(NN * BC / 4) / 256, 256>>>(x, state, 0);
    k_transpose<<<dim3(BC / 32, NN / 32), dim3(32, 8)>>>(X0h, XTh);
    k_mmagemm<<<gg, 256, TCG_SMEM>>>(Sgh, Sgl, XTh, nullptr, nullptr, X1h, X1l, YTh, 0);
    k_mmagemm<<<gg, 256, TCG_SMEM>>>(Sgh, Sgl, YTh, X0h, X0l, X2h, X2l, nullptr, 1);
    k_tc_gate<<<NN, 256>>>();

    // ---- update magcn ----
    k_build_xin<<<(NN * BC / 4) / 256, 256>>>(x, state, 1);
    k_transpose<<<dim3(BC / 32, NN / 32), dim3(32, 8)>>>(X0h, XTh);
    k_mmagemm<<<gg, 256, TCG_SMEM>>>(Suh, Sul, XTh, nullptr, nullptr, X1h, X1l, YTh, 0);
    k_mmagemm<<<gg, 256, TCG_SMEM>>>(Suh, Sul, YTh, X0h, X0l, X2h, X2l, nullptr, 1);
    k_tc_upd<<<NN, 128>>>(state, out);
}

// round 6
// speedup vs baseline: 3.9959x; 1.5178x over previous
#include <cuda_runtime.h>
#include <cuda_fp16.h>
#include <math.h>
#include <stdint.h>

#define NN 1024
#define BB 64
#define CC 64
#define HH 64
#define DD 16
#define CIN 128
#define BC 8192            // BB * CIN
#define KIO_G 49152        // 384*128
#define KIO_U 24576        // 384*64

// ---------------- scratch (static device globals; no allocation) ----------------
__device__ float g_eg[NN * DD];
__device__ float g_eu[NN * DD];
__device__ float g_bg[NN * 128];
__device__ float g_bu[NN * 64];
__device__ float g_z[BB * NN * HH];
__device__ float g_r[BB * NN * HH];

// fp16 buffers (u16)
__device__ unsigned short g_Sgh[NN * NN];
__device__ unsigned short g_Suh[NN * NN];
__device__ unsigned short g_XTh[BC * NN];   // transposed X0h  [col][k]
__device__ unsigned short g_YTh[BC * NN];   // transposed fp16(y1) [col][k]
// x stages untransposed [n][b*128+c] for node GEMMs (hi/lo split kept — A-side accuracy)
__device__ unsigned short g_X0h[NN * BC];
__device__ unsigned short g_X0l[NN * BC];
__device__ unsigned short g_X1h[NN * BC];
__device__ unsigned short g_X1l[NN * BC];
__device__ unsigned short g_X2h[NN * BC];
__device__ unsigned short g_X2l[NN * BC];
// per-node weights fp16 (hi only) [n][kidx][o]
__device__ unsigned short g_wgh[NN * KIO_G];
__device__ unsigned short g_wuh[NN * KIO_U];

// ---------------- helpers ----------------
__device__ __forceinline__ uint32_t smem_to_u32(const void* p) {
    uint32_t a;
    asm("{ .reg .u64 t; cvta.to.shared.u64 t, %1; cvt.u32.u64 %0, t; }" : "=r"(a) : "l"(p));
    return a;
}

#define CP_ASYNC16(dst, src) \
    asm volatile("cp.async.cg.shared.global [%0], [%1], 16;" :: "r"(dst), "l"(src))
#define CP_COMMIT()  asm volatile("cp.async.commit_group;" ::: "memory")
#define CP_WAIT0()   asm volatile("cp.async.wait_group 0;" ::: "memory")

__device__ __forceinline__ void ldsm_x4(uint32_t& r0, uint32_t& r1, uint32_t& r2, uint32_t& r3,
                                        uint32_t addr) {
    asm volatile("ldmatrix.sync.aligned.m8n8.x4.shared.b16 {%0,%1,%2,%3}, [%4];"
                 : "=r"(r0), "=r"(r1), "=r"(r2), "=r"(r3) : "r"(addr));
}
__device__ __forceinline__ void ldsm_x4_t(uint32_t& r0, uint32_t& r1, uint32_t& r2, uint32_t& r3,
                                          uint32_t addr) {
    asm volatile("ldmatrix.sync.aligned.m8n8.x4.trans.shared.b16 {%0,%1,%2,%3}, [%4];"
                 : "=r"(r0), "=r"(r1), "=r"(r2), "=r"(r3) : "r"(addr));
}

__device__ __forceinline__ void mma16816(float* c, const uint32_t* a, const uint32_t* b) {
    asm volatile("mma.sync.aligned.m16n8k16.row.col.f32.f16.f16.f32 "
                 "{%0,%1,%2,%3}, {%4,%5,%6,%7}, {%8,%9}, {%0,%1,%2,%3};"
                 : "+f"(c[0]), "+f"(c[1]), "+f"(c[2]), "+f"(c[3])
                 : "r"(a[0]), "r"(a[1]), "r"(a[2]), "r"(a[3]), "r"(b[0]), "r"(b[1]));
}

__device__ __forceinline__ void f16split(float x, unsigned short& h, unsigned short& l) {
    __half hb = __float2half_rn(x);
    __half lb = __float2half_rn(x - __half2float(hb));
    h = *reinterpret_cast<unsigned short*>(&hb);
    l = *reinterpret_cast<unsigned short*>(&lb);
}
__device__ __forceinline__ float f16join(unsigned short h, unsigned short l) {
    return __half2float(*reinterpret_cast<__half*>(&h)) +
           __half2float(*reinterpret_cast<__half*>(&l));
}

// ---------------- 1) e = LN(node_emb + time_emb), bias = e @ b_pool ----------------
__global__ void k_prep(const float* __restrict__ ne, const float* __restrict__ te,
                       const float* __restrict__ gw, const float* __restrict__ gbln,
                       const float* __restrict__ uw, const float* __restrict__ ubln,
                       const float* __restrict__ gate_b, const float* __restrict__ update_b)
{
    int n = blockIdx.x;
    int lane = threadIdx.x;          // 32 threads
    int d = lane & 15;
    float v = ne[n * DD + d] + te[d];

    float s = v;
    #pragma unroll
    for (int off = 16; off > 0; off >>= 1) s += __shfl_xor_sync(0xffffffffu, s, off);
    float mean = s * (1.0f / 32.0f);
    float dv = v - mean;
    float q = dv * dv;
    #pragma unroll
    for (int off = 16; off > 0; off >>= 1) q += __shfl_xor_sync(0xffffffffu, q, off);
    float var = q * (1.0f / 32.0f);
    float inv = rsqrtf(var + 1e-12f);

    float eg = dv * inv * gw[d] + gbln[d];
    float eu = dv * inv * uw[d] + ubln[d];
    if (lane < 16) { g_eg[n * DD + d] = eg; g_eu[n * DD + d] = eu; }

    for (int o = lane; o < 128; o += 32) {
        float b = 0.f;
        #pragma unroll
        for (int dd = 0; dd < 16; dd++)
            b += __shfl_sync(0xffffffffu, eg, dd) * gate_b[dd * 128 + o];
        g_bg[n * 128 + o] = b;
    }
    for (int o = lane; o < 64; o += 32) {
        float b = 0.f;
        #pragma unroll
        for (int dd = 0; dd < 16; dd++)
            b += __shfl_sync(0xffffffffu, eu, dd) * update_b[dd * 64 + o];
        g_bu[n * 64 + o] = b;
    }
}

// ---------------- 2) S = softmax(e e^T), fp16 ----------------
__global__ void k_supports()
{
    int n = blockIdx.x;
    int which = blockIdx.y;
    const float* e = which ? g_eu : g_eg;
    unsigned short* Sh = which ? g_Suh : g_Sgh;

    __shared__ float en[16];
    __shared__ float red[256];
    int tid = threadIdx.x;
    if (tid < 16) en[tid] = e[n * DD + tid];
    __syncthreads();

    float lv[4];
    float mx = -1e30f;
    #pragma unroll
    for (int i = 0; i < 4; i++) {
        int m = tid + i * 256;
        const float* em = &e[m * DD];
        float dot = 0.f;
        #pragma unroll
        for (int dd = 0; dd < 16; dd++) dot += en[dd] * em[dd];
        lv[i] = dot;
        mx = fmaxf(mx, dot);
    }
    red[tid] = mx; __syncthreads();
    for (int s = 128; s > 0; s >>= 1) {
        if (tid < s) red[tid] = fmaxf(red[tid], red[tid + s]);
        __syncthreads();
    }
    mx = red[0];
    __syncthreads();

    float sum = 0.f;
    #pragma unroll
    for (int i = 0; i < 4; i++) { lv[i] = expf(lv[i] - mx); sum += lv[i]; }
    red[tid] = sum; __syncthreads();
    for (int s = 128; s > 0; s >>= 1) {
        if (tid < s) red[tid] += red[tid + s];
        __syncthreads();
    }
    float invs = 1.0f / red[0];
    #pragma unroll
    for (int i = 0; i < 4; i++) {
        float v = lv[i] * invs;
        __half hh = __float2half_rn(v);
        Sh[n * NN + tid + i * 256] = *reinterpret_cast<unsigned short*>(&hh);
    }
}

// ---------------- 3) per-node weights, fp16 hi only, [n][kidx][o] ----------------
__global__ void k_wgen(const float* __restrict__ Wp, int which)
{
    const int KIO = which ? KIO_U : KIO_G;
    unsigned short* wh = which ? g_wuh : g_wgh;
    const float* e = which ? g_eu : g_eg;

    int tid = threadIdx.x;
    int kio = blockIdx.x * 256 + tid;
    int n0 = blockIdx.y * 32;

    __shared__ float es[512];
    es[tid] = e[n0 * DD + tid];
    es[tid + 256] = e[n0 * DD + 256 + tid];
    __syncthreads();

    float wr[16];
    #pragma unroll
    for (int dd = 0; dd < 16; dd++) wr[dd] = Wp[dd * KIO + kio];

    #pragma unroll
    for (int j = 0; j < 32; j++) {
        float a = 0.f;
        #pragma unroll
        for (int dd = 0; dd < 16; dd++) a += es[j * 16 + dd] * wr[dd];
        __half hh = __float2half_rn(a);
        wh[(size_t)(n0 + j) * KIO + kio] = *reinterpret_cast<unsigned short*>(&hh);
    }
}

// ---------------- 4) build X0 splits ----------------
__global__ void k_build_xin(const float* __restrict__ x, const float* __restrict__ state, int mode)
{
    int t = blockIdx.x * 256 + threadIdx.x;
    int n = t >> 11;
    int j = t & 2047;
    int b = j >> 5;
    int c = (j & 31) << 2;

    float4 v;
    if (c < 64) {
        v = *(const float4*)&x[b * (NN * CC) + n * CC + c];
    } else {
        int cc = c - 64;
        float4 s4 = *(const float4*)&state[b * (NN * HH) + n * HH + cc];
        if (mode) {
            float4 z4 = *(const float4*)&g_z[b * (NN * HH) + n * HH + cc];
            v.x = z4.x * s4.x; v.y = z4.y * s4.y; v.z = z4.z * s4.z; v.w = z4.w * s4.w;
        } else {
            v = s4;
        }
    }
    int o = n * BC + b * CIN + c;
    ushort4 h4, l4;
    f16split(v.x, h4.x, l4.x); f16split(v.y, h4.y, l4.y);
    f16split(v.z, h4.z, l4.z); f16split(v.w, h4.w, l4.w);
    *(ushort4*)&g_X0h[o] = h4;
    *(ushort4*)&g_X0l[o] = l4;
}

// ---------------- 4b) u16 transpose: X0h[1024][8192] -> XTh[8192][1024] ----------------
__global__ void k_transpose(const unsigned short* __restrict__ in,
                            unsigned short* __restrict__ outp)
{
    __shared__ unsigned short t[32][34];
    int bc = blockIdx.x << 5;
    int bn = blockIdx.y << 5;
    int x = threadIdx.x, y = threadIdx.y;  // 32 x 8
    #pragma unroll
    for (int i = 0; i < 4; i++)
        t[y + i * 8][x] = in[(bn + y + i * 8) * BC + bc + x];
    __syncthreads();
    #pragma unroll
    for (int i = 0; i < 4; i++)
        outp[(bc + y + i * 8) * NN + bn + x] = t[x][y + i * 8];
}

// ---------------- 5) big tensor GEMM (1-term fp16): acc = Ah @ Bh ----------------
// mode 0: X1h/X1l = split(acc) row-major; CTh = fp16(acc) transposed [col][row]
// mode 1: X2h/X2l = split(2*acc - (D0h+D0l)) row-major
#define STAGE_BYTES 32768
#define TCG_SMEM 66560   // >= 128*129*4 epilogue floats

__global__ void __launch_bounds__(256, 2)
k_mmagemm(const unsigned short* __restrict__ Ah,
          const unsigned short* __restrict__ Bh,
          const unsigned short* __restrict__ D0h, const unsigned short* __restrict__ D0l,
          unsigned short* __restrict__ Xh, unsigned short* __restrict__ Xl,
          unsigned short* __restrict__ CTh,
          int mode)
{
    extern __shared__ char smem[];
    const uint32_t smem_u = smem_to_u32(smem);
    const int tid = threadIdx.x;
    const int wid = tid >> 5;
    const int lane = tid & 31;
    const int brow = blockIdx.y << 7;
    const int bcol = blockIdx.x << 7;
    const int wm = wid & 1;
    const int wn = wid >> 1;

    const unsigned short* srcs[2];
    srcs[0] = Ah + (size_t)brow * NN;
    srcs[1] = Bh + (size_t)bcol * NN;

    float acc[4][4][4];
    #pragma unroll
    for (int i = 0; i < 4; i++)
        #pragma unroll
        for (int j = 0; j < 4; j++)
            #pragma unroll
            for (int q = 0; q < 4; q++) acc[i][j][q] = 0.f;

    const int arow = wm * 64 + (lane & 15);
    const int axor = (arow & 7) << 4;
    const int agco = (lane >> 4) << 4;
    const int bn   = wn * 32 + ((lane >> 4) << 3) + (lane & 7);
    const int bxor = (bn & 7) << 4;
    const int bko  = ((lane >> 3) & 1) << 4;

    auto load_stage = [&](int buf, int kk) {
        uint32_t dst0 = smem_u + buf * STAGE_BYTES;
        #pragma unroll
        for (int i = 0; i < 8; i++) {
            int lin = tid + (i << 8);            // 0..2047
            int arr = lin >> 10;
            int r = (lin >> 3) & 127;
            int cb = (lin & 7) << 4;
            const char* src = (const char*)(srcs[arr] + (size_t)r * NN + kk) + cb;
            uint32_t d = dst0 + arr * 16384 + r * 128 + (cb ^ ((r & 7) << 4));
            CP_ASYNC16(d, src);
        }
        CP_COMMIT();
    };

    load_stage(0, 0);

    #pragma unroll 1
    for (int s = 0; s < 16; s++) {
        const int buf = s & 1;
        CP_WAIT0();
        __syncthreads();
        if (s + 1 < 16) load_stage(1 - buf, (s + 1) << 6);

        const uint32_t sb = smem_u + buf * STAGE_BYTES;
        #pragma unroll
        for (int ks = 0; ks < 4; ks++) {
            const int c = ks << 5;
            uint32_t ah[4][4], bh[4][2];
            #pragma unroll
            for (int mt = 0; mt < 4; mt++) {
                uint32_t ao = (uint32_t)((arow + mt * 16) * 128) + (uint32_t)((c + agco) ^ axor);
                ldsm_x4(ah[mt][0], ah[mt][1], ah[mt][2], ah[mt][3], sb + ao);
            }
            #pragma unroll
            for (int nb = 0; nb < 2; nb++) {
                uint32_t bo = (uint32_t)((bn + nb * 16) * 128) + (uint32_t)((c + bko) ^ bxor);
                ldsm_x4(bh[2 * nb][0], bh[2 * nb][1], bh[2 * nb + 1][0], bh[2 * nb + 1][1],
                        sb + 16384 + bo);
            }
            #pragma unroll
            for (int mt = 0; mt < 4; mt++)
                #pragma unroll
                for (int nt = 0; nt < 4; nt++)
                    mma16816(acc[mt][nt], ah[mt], bh[nt]);
        }
        __syncthreads();
    }

    // ---- epilogue via smem (128 x 129 fp32) ----
    float* sf = (float*)smem;
    __syncthreads();
    {
        int g = lane >> 2, t4 = lane & 3;
        #pragma unroll
        for (int mt = 0; mt < 4; mt++) {
            int m0 = wm * 64 + mt * 16 + g;
            #pragma unroll
            for (int nt = 0; nt < 4; nt++) {
                int n0 = wn * 32 + nt * 8 + 2 * t4;
                sf[m0 * 129 + n0]           = acc[mt][nt][0];
                sf[m0 * 129 + n0 + 1]       = acc[mt][nt][1];
                sf[(m0 + 8) * 129 + n0]     = acc[mt][nt][2];
                sf[(m0 + 8) * 129 + n0 + 1] = acc[mt][nt][3];
            }
        }
    }
    __syncthreads();

    if (mode == 0) {
        #pragma unroll 4
        for (int it = 0; it < 64; it++) {
            int idx = tid + (it << 8);
            int m = idx >> 7, j = idx & 127;
            float v = sf[m * 129 + j];
            unsigned short h, l;
            f16split(v, h, l);
            size_t o = (size_t)(brow + m) * BC + bcol + j;
            Xh[o] = h; Xl[o] = l;
        }
        #pragma unroll 4
        for (int it = 0; it < 64; it++) {
            int idx = tid + (it << 8);
            int j = idx >> 7, m = idx & 127;
            float v = sf[m * 129 + j];
            __half hh = __float2half_rn(v);
            CTh[(size_t)(bcol + j) * NN + brow + m] = *reinterpret_cast<unsigned short*>(&hh);
        }
    } else {
        #pragma unroll 4
        for (int it = 0; it < 64; it++) {
            int idx = tid + (it << 8);
            int m = idx >> 7, j = idx & 127;
            size_t o = (size_t)(brow + m) * BC + bcol + j;
            float d = f16join(D0h[o], D0l[o]);
            float v = 2.0f * sf[m * 129 + j] - d;
            unsigned short h, l;
            f16split(v, h, l);
            Xh[o] = h; Xl[o] = l;
        }
    }
}

// ---------------- 6) node GEMM gate (2-term): (64x384)@(384x128) -> sigmoid -> z,r ----------------
__global__ void __launch_bounds__(256)
k_tc_gate()
{
    __shared__ char sm[32768];  // Ah 8K | Al 8K | Bh 16K
    const uint32_t su = smem_to_u32(sm);
    const int n = blockIdx.x;
    const int tid = threadIdx.x;
    const int wid = tid >> 5, lane = tid & 31;
    const int wm = wid & 1, wn = wid >> 1;

    const unsigned short* xh[3] = { g_X0h + (size_t)n * BC, g_X1h + (size_t)n * BC, g_X2h + (size_t)n * BC };
    const unsigned short* xl[3] = { g_X0l + (size_t)n * BC, g_X1l + (size_t)n * BC, g_X2l + (size_t)n * BC };
    const unsigned short* wh = g_wgh + (size_t)n * KIO_G;

    float acc[2][4][4];
    #pragma unroll
    for (int i = 0; i < 2; i++)
        #pragma unroll
        for (int j = 0; j < 4; j++)
            #pragma unroll
            for (int q = 0; q < 4; q++) acc[i][j][q] = 0.f;

    const int arow = wm * 32 + (lane & 15);
    const int axor = (arow & 7) << 4;
    const int agco = (lane >> 4) << 4;
    const int brow = (lane & 7) + (((lane >> 3) & 1) << 3);
    const int bxor = (lane & 7) << 4;
    const int bgrp = (lane >> 4) << 4;

    #pragma unroll 1
    for (int q = 0; q < 6; q++) {
        const int t = q >> 1;
        const int c0 = (q & 1) << 6;
        // A: 64 rows x 128B (hi, lo)
        #pragma unroll
        for (int i = 0; i < 2; i++) {
            int lin = tid + (i << 8);
            int r = lin >> 3;
            int cb = (lin & 7) << 4;
            uint32_t dsw = r * 128 + (cb ^ ((r & 7) << 4));
            CP_ASYNC16(su + dsw,        (const char*)(xh[t] + r * 128 + c0) + cb);
            CP_ASYNC16(su + 8192 + dsw, (const char*)(xl[t] + r * 128 + c0) + cb);
        }
        // B: 64 rows x 256B (hi only)
        #pragma unroll
        for (int i = 0; i < 4; i++) {
            int lin = tid + (i << 8);
            int kr = lin >> 4;
            int cb = (lin & 15) << 4;
            uint32_t dsw = kr * 256 + (cb ^ ((kr & 7) << 4));
            CP_ASYNC16(su + 16384 + dsw, (const char*)(wh + (size_t)(q * 64 + kr) * 128) + cb);
        }
        CP_COMMIT();
        CP_WAIT0();
        __syncthreads();

        #pragma unroll
        for (int ks = 0; ks < 4; ks++) {
            const int c = ks << 5;
            uint32_t ah[2][4], al[2][4], bh[4][2];
            #pragma unroll
            for (int mt = 0; mt < 2; mt++) {
                uint32_t ao = (uint32_t)((arow + mt * 16) * 128) + (uint32_t)((c + agco) ^ axor);
                ldsm_x4(ah[mt][0], ah[mt][1], ah[mt][2], ah[mt][3], su + ao);
                ldsm_x4(al[mt][0], al[mt][1], al[mt][2], al[mt][3], su + 8192 + ao);
            }
            #pragma unroll
            for (int nb = 0; nb < 2; nb++) {
                uint32_t bo = (uint32_t)((ks * 16 + brow) * 256)
                            + (uint32_t)((wn * 64 + nb * 32 + bgrp) ^ bxor);
                ldsm_x4_t(bh[2 * nb][0], bh[2 * nb][1], bh[2 * nb + 1][0], bh[2 * nb + 1][1],
                          su + 16384 + bo);
            }
            #pragma unroll
            for (int mt = 0; mt < 2; mt++)
                #pragma unroll
                for (int nt = 0; nt < 4; nt++) {
                    mma16816(acc[mt][nt], ah[mt], bh[nt]);
                    mma16816(acc[mt][nt], al[mt], bh[nt]);
                }
        }
        __syncthreads();
    }

    const int g = lane >> 2, t4 = lane & 3;
    #pragma unroll
    for (int mt = 0; mt < 2; mt++) {
        int b0 = wm * 32 + mt * 16 + g;
        #pragma unroll
        for (int nt = 0; nt < 4; nt++) {
            int o = wn * 32 + nt * 8 + 2 * t4;
            float bi0 = g_bg[n * 128 + o];
            float bi1 = g_bg[n * 128 + o + 1];
            #pragma unroll
            for (int half = 0; half < 2; half++) {
                int b = b0 + half * 8;
                float v0 = acc[mt][nt][2 * half]     + bi0;
                float v1 = acc[mt][nt][2 * half + 1] + bi1;
                float s0 = 1.0f / (1.0f + expf(-v0));
                float s1 = 1.0f / (1.0f + expf(-v1));
                int base = b * (NN * HH) + n * HH;
                if (o < 64) { g_z[base + o] = s0; g_z[base + o + 1] = s1; }
                else        { g_r[base + o - 64] = s0; g_r[base + o - 63] = s1; }
            }
        }
    }
}

// ---------------- 7) node GEMM update (2-term): (64x384)@(384x64) -> tanh -> GRU out ----------------
__global__ void __launch_bounds__(128)
k_tc_upd(const float* __restrict__ state, float* __restrict__ dout)
{
    __shared__ char sm[24576];  // Ah 8K | Al 8K | Bh 8K
    const uint32_t su = smem_to_u32(sm);
    const int n = blockIdx.x;
    const int tid = threadIdx.x;
    const int wid = tid >> 5, lane = tid & 31;
    const int wm = wid & 1, wn = wid >> 1;

    const unsigned short* xh[3] = { g_X0h + (size_t)n * BC, g_X1h + (size_t)n * BC, g_X2h + (size_t)n * BC };
    const unsigned short* xl[3] = { g_X0l + (size_t)n * BC, g_X1l + (size_t)n * BC, g_X2l + (size_t)n * BC };
    const unsigned short* wh = g_wuh + (size_t)n * KIO_U;

    float acc[2][4][4];
    #pragma unroll
    for (int i = 0; i < 2; i++)
        #pragma unroll
        for (int j = 0; j < 4; j++)
            #pragma unroll
            for (int q = 0; q < 4; q++) acc[i][j][q] = 0.f;

    const int arow = wm * 32 + (lane & 15);
    const int axor = (arow & 7) << 4;
    const int agco = (lane >> 4) << 4;
    const int brow = (lane & 7) + (((lane >> 3) & 1) << 3);
    const int bxor = (lane & 7) << 4;
    const int bgrp = (lane >> 4) << 4;

    #pragma unroll 1
    for (int q = 0; q < 6; q++) {
        const int t = q >> 1;
        const int c0 = (q & 1) << 6;
        // A: 64 rows x 128B (hi, lo)
        #pragma unroll
        for (int i = 0; i < 4; i++) {
            int lin = tid + (i << 7);
            int r = lin >> 3;
            int cb = (lin & 7) << 4;
            uint32_t dsw = r * 128 + (cb ^ ((r & 7) << 4));
            CP_ASYNC16(su + dsw,        (const char*)(xh[t] + r * 128 + c0) + cb);
            CP_ASYNC16(su + 8192 + dsw, (const char*)(xl[t] + r * 128 + c0) + cb);
        }
        // B: 64 rows x 128B (hi only)
        #pragma unroll
        for (int i = 0; i < 4; i++) {
            int lin = tid + (i << 7);
            int kr = lin >> 3;
            int cb = (lin & 7) << 4;
            uint32_t dsw = kr * 128 + (cb ^ ((kr & 7) << 4));
            CP_ASYNC16(su + 16384 + dsw, (const char*)(wh + (size_t)(q * 64 + kr) * 64) + cb);
        }
        CP_COMMIT();
        CP_WAIT0();
        __syncthreads();

        #pragma unroll
        for (int ks = 0; ks < 4; ks++) {
            const int c = ks << 5;
            uint32_t ah[2][4], al[2][4], bh[4][2];
            #pragma unroll
            for (int mt = 0; mt < 2; mt++) {
                uint32_t ao = (uint32_t)((arow + mt * 16) * 128) + (uint32_t)((c + agco) ^ axor);
                ldsm_x4(ah[mt][0], ah[mt][1], ah[mt][2], ah[mt][3], su + ao);
                ldsm_x4(al[mt][0], al[mt][1], al[mt][2], al[mt][3], su + 8192 + ao);
            }
            #pragma unroll
            for (int nb = 0; nb < 2; nb++) {
                uint32_t bo = (uint32_t)((ks * 16 + brow) * 128)
                            + (uint32_t)((wn * 64 + nb * 32 + bgrp) ^ bxor);
                ldsm_x4_t(bh[2 * nb][0], bh[2 * nb][1], bh[2 * nb + 1][0], bh[2 * nb + 1][1],
                          su + 16384 + bo);
            }
            #pragma unroll
            for (int mt = 0; mt < 2; mt++)
                #pragma unroll
                for (int nt = 0; nt < 4; nt++) {
                    mma16816(acc[mt][nt], ah[mt], bh[nt]);
                    mma16816(acc[mt][nt], al[mt], bh[nt]);
                }
        }
        __syncthreads();
    }

    const int g = lane >> 2, t4 = lane & 3;
    #pragma unroll
    for (int mt = 0; mt < 2; mt++) {
        int b0 = wm * 32 + mt * 16 + g;
        #pragma unroll
        for (int nt = 0; nt < 4; nt++) {
            int o = wn * 32 + nt * 8 + 2 * t4;
            float bi0 = g_bu[n * 64 + o];
            float bi1 = g_bu[n * 64 + o + 1];
            #pragma unroll
            for (int half = 0; half < 2; half++) {
                int b = b0 + half * 8;
                float hc0 = tanhf(acc[mt][nt][2 * half]     + bi0);
                float hc1 = tanhf(acc[mt][nt][2 * half + 1] + bi1);
                int idx = b * (NN * HH) + n * HH + o;
                float r0 = g_r[idx],     st0 = state[idx];
                float r1 = g_r[idx + 1], st1 = state[idx + 1];
                dout[idx]     = r0 * st0 + (1.0f - r0) * hc0;
                dout[idx + 1] = r1 * st1 + (1.0f - r1) * hc1;
            }
        }
    }
}

// ---------------- launch ----------------
extern "C" void kernel_launch(void* const* d_in, const int* in_sizes, int n_in,
                              void* d_out, int out_size)
{
    const float* x         = (const float*)d_in[0];
    const float* state     = (const float*)d_in[2];
    const float* node_emb  = (const float*)d_in[3];
    const float* time_emb  = (const float*)d_in[5];
    const float* gate_W    = (const float*)d_in[6];
    const float* gate_b    = (const float*)d_in[7];
    const float* gate_lnw  = (const float*)d_in[8];
    const float* gate_lnb  = (const float*)d_in[9];
    const float* update_W  = (const float*)d_in[10];
    const float* update_b  = (const float*)d_in[11];
    const float* update_lnw= (const float*)d_in[12];
    const float* update_lnb= (const float*)d_in[13];
    float* out = (float*)d_out;

    unsigned short *Sgh, *Suh, *XTh, *YTh;
    unsigned short *X0h, *X0l, *X1h, *X1l, *X2h, *X2l;
    cudaGetSymbolAddress((void**)&Sgh, g_Sgh);
    cudaGetSymbolAddress((void**)&Suh, g_Suh);
    cudaGetSymbolAddress((void**)&XTh, g_XTh);
    cudaGetSymbolAddress((void**)&YTh, g_YTh);
    cudaGetSymbolAddress((void**)&X0h, g_X0h);
    cudaGetSymbolAddress((void**)&X0l, g_X0l);
    cudaGetSymbolAddress((void**)&X1h, g_X1h);
    cudaGetSymbolAddress((void**)&X1l, g_X1l);
    cudaGetSymbolAddress((void**)&X2h, g_X2h);
    cudaGetSymbolAddress((void**)&X2l, g_X2l);

    cudaFuncSetAttribute(k_mmagemm, cudaFuncAttributeMaxDynamicSharedMemorySize, TCG_SMEM);

    k_prep<<<NN, 32>>>(node_emb, time_emb, gate_lnw, gate_lnb, update_lnw, update_lnb,
                       gate_b, update_b);
    k_supports<<<dim3(NN, 2), 256>>>();
    k_wgen<<<dim3(KIO_G / 256, NN / 32), 256>>>(gate_W, 0);
    k_wgen<<<dim3(KIO_U / 256, NN / 32), 256>>>(update_W, 1);

    dim3 gg(BC / 128, NN / 128);

    // ---- gate magcn ----
    k_build_xin<<<(NN * BC / 4) / 256, 256>>>(x, state, 0);
    k_transpose<<<dim3(BC / 32, NN / 32), dim3(32, 8)>>>(X0h, XTh);
    k_mmagemm<<<gg, 256, TCG_SMEM>>>(Sgh, XTh, nullptr, nullptr, X1h, X1l, YTh, 0);
    k_mmagemm<<<gg, 256, TCG_SMEM>>>(Sgh, YTh, X0h, X0l, X2h, X2l, nullptr, 1);
    k_tc_gate<<<NN, 256>>>();

    // ---- update magcn ----
    k_build_xin<<<(NN * BC / 4) / 256, 256>>>(x, state, 1);
    k_transpose<<<dim3(BC / 32, NN / 32), dim3(32, 8)>>>(X0h, XTh);
    k_mmagemm<<<gg, 256, TCG_SMEM>>>(Suh, XTh, nullptr, nullptr, X1h, X1l, YTh, 0);
    k_mmagemm<<<gg, 256, TCG_SMEM>>>(Suh, YTh, X0h, X0l, X2h, X2l, nullptr, 1);
    k_tc_upd<<<NN, 128>>>(state, out);
}

// round 7
// speedup vs baseline: 4.0285x; 1.0082x over previous
#include <cuda_runtime.h>
#include <cuda_fp16.h>
#include <math.h>
#include <stdint.h>

#define NN 1024
#define BB 64
#define CC 64
#define HH 64
#define DD 16
#define CIN 128
#define BC 8192            // BB * CIN
#define KIO_G 49152        // 384*128
#define KIO_U 24576        // 384*64

// ---------------- scratch ----------------
__device__ float g_eg[NN * DD];
__device__ float g_eu[NN * DD];
__device__ float g_bg[NN * 128];
__device__ float g_bu[NN * 64];
__device__ float g_r[BB * NN * HH];

__device__ unsigned short g_Sgh[NN * NN];
__device__ unsigned short g_Suh[NN * NN];
__device__ unsigned short g_XTh[BC * NN];   // transposed X0h [col][k]
__device__ unsigned short g_YTh[BC * NN];   // transposed fp16(y1) [col][k]
__device__ unsigned short g_X0h[NN * BC];
__device__ unsigned short g_X0l[NN * BC];
__device__ unsigned short g_X1h[NN * BC];
__device__ unsigned short g_X1l[NN * BC];
__device__ unsigned short g_X2h[NN * BC];
__device__ unsigned short g_X2l[NN * BC];
__device__ unsigned short g_wgh[NN * KIO_G];
__device__ unsigned short g_wuh[NN * KIO_U];

// ---------------- helpers ----------------
__device__ __forceinline__ uint32_t smem_to_u32(const void* p) {
    uint32_t a;
    asm("{ .reg .u64 t; cvta.to.shared.u64 t, %1; cvt.u32.u64 %0, t; }" : "=r"(a) : "l"(p));
    return a;
}

#define CP_ASYNC16(dst, src) \
    asm volatile("cp.async.cg.shared.global [%0], [%1], 16;" :: "r"(dst), "l"(src))
#define CP_COMMIT()  asm volatile("cp.async.commit_group;" ::: "memory")
#define CP_WAIT0()   asm volatile("cp.async.wait_group 0;" ::: "memory")
#define CP_WAIT1()   asm volatile("cp.async.wait_group 1;" ::: "memory")

__device__ __forceinline__ void ldsm_x4(uint32_t& r0, uint32_t& r1, uint32_t& r2, uint32_t& r3,
                                        uint32_t addr) {
    asm volatile("ldmatrix.sync.aligned.m8n8.x4.shared.b16 {%0,%1,%2,%3}, [%4];"
                 : "=r"(r0), "=r"(r1), "=r"(r2), "=r"(r3) : "r"(addr));
}
__device__ __forceinline__ void ldsm_x4_t(uint32_t& r0, uint32_t& r1, uint32_t& r2, uint32_t& r3,
                                          uint32_t addr) {
    asm volatile("ldmatrix.sync.aligned.m8n8.x4.trans.shared.b16 {%0,%1,%2,%3}, [%4];"
                 : "=r"(r0), "=r"(r1), "=r"(r2), "=r"(r3) : "r"(addr));
}

__device__ __forceinline__ void mma16816(float* c, const uint32_t* a, const uint32_t* b) {
    asm volatile("mma.sync.aligned.m16n8k16.row.col.f32.f16.f16.f32 "
                 "{%0,%1,%2,%3}, {%4,%5,%6,%7}, {%8,%9}, {%0,%1,%2,%3};"
                 : "+f"(c[0]), "+f"(c[1]), "+f"(c[2]), "+f"(c[3])
                 : "r"(a[0]), "r"(a[1]), "r"(a[2]), "r"(a[3]), "r"(b[0]), "r"(b[1]));
}

__device__ __forceinline__ void f16split(float x, unsigned short& h, unsigned short& l) {
    __half hb = __float2half_rn(x);
    __half lb = __float2half_rn(x - __half2float(hb));
    h = *reinterpret_cast<unsigned short*>(&hb);
    l = *reinterpret_cast<unsigned short*>(&lb);
}
__device__ __forceinline__ float f16join(unsigned short h, unsigned short l) {
    return __half2float(*reinterpret_cast<__half*>(&h)) +
           __half2float(*reinterpret_cast<__half*>(&l));
}

// ---------------- 1) e = LN(node_emb + time_emb), bias = e @ b_pool ----------------
__global__ void k_prep(const float* __restrict__ ne, const float* __restrict__ te,
                       const float* __restrict__ gw, const float* __restrict__ gbln,
                       const float* __restrict__ uw, const float* __restrict__ ubln,
                       const float* __restrict__ gate_b, const float* __restrict__ update_b)
{
    int n = blockIdx.x;
    int lane = threadIdx.x;
    int d = lane & 15;
    float v = ne[n * DD + d] + te[d];

    float s = v;
    #pragma unroll
    for (int off = 16; off > 0; off >>= 1) s += __shfl_xor_sync(0xffffffffu, s, off);
    float mean = s * (1.0f / 32.0f);
    float dv = v - mean;
    float q = dv * dv;
    #pragma unroll
    for (int off = 16; off > 0; off >>= 1) q += __shfl_xor_sync(0xffffffffu, q, off);
    float var = q * (1.0f / 32.0f);
    float inv = rsqrtf(var + 1e-12f);

    float eg = dv * inv * gw[d] + gbln[d];
    float eu = dv * inv * uw[d] + ubln[d];
    if (lane < 16) { g_eg[n * DD + d] = eg; g_eu[n * DD + d] = eu; }

    for (int o = lane; o < 128; o += 32) {
        float b = 0.f;
        #pragma unroll
        for (int dd = 0; dd < 16; dd++)
            b += __shfl_sync(0xffffffffu, eg, dd) * gate_b[dd * 128 + o];
        g_bg[n * 128 + o] = b;
    }
    for (int o = lane; o < 64; o += 32) {
        float b = 0.f;
        #pragma unroll
        for (int dd = 0; dd < 16; dd++)
            b += __shfl_sync(0xffffffffu, eu, dd) * update_b[dd * 64 + o];
        g_bu[n * 64 + o] = b;
    }
}

// ---------------- 2) S = softmax(e e^T), fp16 ----------------
__global__ void k_supports()
{
    int n = blockIdx.x;
    int which = blockIdx.y;
    const float* e = which ? g_eu : g_eg;
    unsigned short* Sh = which ? g_Suh : g_Sgh;

    __shared__ float en[16];
    __shared__ float red[256];
    int tid = threadIdx.x;
    if (tid < 16) en[tid] = e[n * DD + tid];
    __syncthreads();

    float lv[4];
    float mx = -1e30f;
    #pragma unroll
    for (int i = 0; i < 4; i++) {
        int m = tid + i * 256;
        const float* em = &e[m * DD];
        float dot = 0.f;
        #pragma unroll
        for (int dd = 0; dd < 16; dd++) dot += en[dd] * em[dd];
        lv[i] = dot;
        mx = fmaxf(mx, dot);
    }
    red[tid] = mx; __syncthreads();
    for (int s = 128; s > 0; s >>= 1) {
        if (tid < s) red[tid] = fmaxf(red[tid], red[tid + s]);
        __syncthreads();
    }
    mx = red[0];
    __syncthreads();

    float sum = 0.f;
    #pragma unroll
    for (int i = 0; i < 4; i++) { lv[i] = expf(lv[i] - mx); sum += lv[i]; }
    red[tid] = sum; __syncthreads();
    for (int s = 128; s > 0; s >>= 1) {
        if (tid < s) red[tid] += red[tid + s];
        __syncthreads();
    }
    float invs = 1.0f / red[0];
    #pragma unroll
    for (int i = 0; i < 4; i++) {
        float v = lv[i] * invs;
        __half hh = __float2half_rn(v);
        Sh[n * NN + tid + i * 256] = *reinterpret_cast<unsigned short*>(&hh);
    }
}

// ---------------- 3) per-node weights, fp16, [n][kidx][o] ----------------
__global__ void k_wgen(const float* __restrict__ Wp, int which)
{
    const int KIO = which ? KIO_U : KIO_G;
    unsigned short* wh = which ? g_wuh : g_wgh;
    const float* e = which ? g_eu : g_eg;

    int tid = threadIdx.x;
    int kio = blockIdx.x * 256 + tid;
    int n0 = blockIdx.y * 32;

    __shared__ float es[512];
    es[tid] = e[n0 * DD + tid];
    es[tid + 256] = e[n0 * DD + 256 + tid];
    __syncthreads();

    float wr[16];
    #pragma unroll
    for (int dd = 0; dd < 16; dd++) wr[dd] = Wp[dd * KIO + kio];

    #pragma unroll
    for (int j = 0; j < 32; j++) {
        float a = 0.f;
        #pragma unroll
        for (int dd = 0; dd < 16; dd++) a += es[j * 16 + dd] * wr[dd];
        __half hh = __float2half_rn(a);
        wh[(size_t)(n0 + j) * KIO + kio] = *reinterpret_cast<unsigned short*>(&hh);
    }
}

// ---------------- 4) build X0 = split(concat(x, state)) ----------------
__global__ void k_build_xin(const float* __restrict__ x, const float* __restrict__ state)
{
    int t = blockIdx.x * 256 + threadIdx.x;
    int n = t >> 11;
    int j = t & 2047;
    int b = j >> 5;
    int c = (j & 31) << 2;

    float4 v;
    if (c < 64) {
        v = *(const float4*)&x[b * (NN * CC) + n * CC + c];
    } else {
        v = *(const float4*)&state[b * (NN * HH) + n * HH + (c - 64)];
    }
    int o = n * BC + b * CIN + c;
    ushort4 h4, l4;
    f16split(v.x, h4.x, l4.x); f16split(v.y, h4.y, l4.y);
    f16split(v.z, h4.z, l4.z); f16split(v.w, h4.w, l4.w);
    *(ushort4*)&g_X0h[o] = h4;
    *(ushort4*)&g_X0l[o] = l4;
}

// ---------------- 4b) u16 transpose (full or state-half rows) ----------------
__global__ void k_transpose(const unsigned short* __restrict__ in,
                            unsigned short* __restrict__ outp, int half)
{
    __shared__ unsigned short t[32][34];
    int tilex = half ? (((blockIdx.x >> 1) << 2) + 2 + (blockIdx.x & 1)) : blockIdx.x;
    int bc = tilex << 5;
    int bn = blockIdx.y << 5;
    int x = threadIdx.x, y = threadIdx.y;  // 32 x 8
    #pragma unroll
    for (int i = 0; i < 4; i++)
        t[y + i * 8][x] = in[(bn + y + i * 8) * BC + bc + x];
    __syncthreads();
    #pragma unroll
    for (int i = 0; i < 4; i++)
        outp[(bc + y + i * 8) * NN + bn + x] = t[x][y + i * 8];
}

// ---------------- 5) big tensor GEMM (1-term fp16): acc = Ah @ Bh ----------------
#define STAGE_BYTES 32768
#define TCG_SMEM 66560

__global__ void __launch_bounds__(256, 2)
k_mmagemm(const unsigned short* __restrict__ Ah,
          const unsigned short* __restrict__ Bh,
          const unsigned short* __restrict__ D0h, const unsigned short* __restrict__ D0l,
          unsigned short* __restrict__ Xh, unsigned short* __restrict__ Xl,
          unsigned short* __restrict__ CTh,
          int mode)
{
    extern __shared__ char smem[];
    const uint32_t smem_u = smem_to_u32(smem);
    const int tid = threadIdx.x;
    const int wid = tid >> 5;
    const int lane = tid & 31;
    const int brow = blockIdx.y << 7;
    const int bcol = blockIdx.x << 7;
    const int wm = wid & 1;
    const int wn = wid >> 1;

    const unsigned short* srcs[2];
    srcs[0] = Ah + (size_t)brow * NN;
    srcs[1] = Bh + (size_t)bcol * NN;

    float acc[4][4][4];
    #pragma unroll
    for (int i = 0; i < 4; i++)
        #pragma unroll
        for (int j = 0; j < 4; j++)
            #pragma unroll
            for (int q = 0; q < 4; q++) acc[i][j][q] = 0.f;

    const int arow = wm * 64 + (lane & 15);
    const int axor = (arow & 7) << 4;
    const int agco = (lane >> 4) << 4;
    const int bn   = wn * 32 + ((lane >> 4) << 3) + (lane & 7);
    const int bxor = (bn & 7) << 4;
    const int bko  = ((lane >> 3) & 1) << 4;

    auto load_stage = [&](int buf, int kk) {
        uint32_t dst0 = smem_u + buf * STAGE_BYTES;
        #pragma unroll
        for (int i = 0; i < 8; i++) {
            int lin = tid + (i << 8);
            int arr = lin >> 10;
            int r = (lin >> 3) & 127;
            int cb = (lin & 7) << 4;
            const char* src = (const char*)(srcs[arr] + (size_t)r * NN + kk) + cb;
            uint32_t d = dst0 + arr * 16384 + r * 128 + (cb ^ ((r & 7) << 4));
            CP_ASYNC16(d, src);
        }
        CP_COMMIT();
    };

    load_stage(0, 0);

    #pragma unroll 1
    for (int s = 0; s < 16; s++) {
        const int buf = s & 1;
        CP_WAIT0();
        __syncthreads();
        if (s + 1 < 16) load_stage(1 - buf, (s + 1) << 6);

        const uint32_t sb = smem_u + buf * STAGE_BYTES;
        #pragma unroll
        for (int ks = 0; ks < 4; ks++) {
            const int c = ks << 5;
            uint32_t ah[4][4], bh[4][2];
            #pragma unroll
            for (int mt = 0; mt < 4; mt++) {
                uint32_t ao = (uint32_t)((arow + mt * 16) * 128) + (uint32_t)((c + agco) ^ axor);
                ldsm_x4(ah[mt][0], ah[mt][1], ah[mt][2], ah[mt][3], sb + ao);
            }
            #pragma unroll
            for (int nb = 0; nb < 2; nb++) {
                uint32_t bo = (uint32_t)((bn + nb * 16) * 128) + (uint32_t)((c + bko) ^ bxor);
                ldsm_x4(bh[2 * nb][0], bh[2 * nb][1], bh[2 * nb + 1][0], bh[2 * nb + 1][1],
                        sb + 16384 + bo);
            }
            #pragma unroll
            for (int mt = 0; mt < 4; mt++)
                #pragma unroll
                for (int nt = 0; nt < 4; nt++)
                    mma16816(acc[mt][nt], ah[mt], bh[nt]);
        }
        __syncthreads();
    }

    float* sf = (float*)smem;
    __syncthreads();
    {
        int g = lane >> 2, t4 = lane & 3;
        #pragma unroll
        for (int mt = 0; mt < 4; mt++) {
            int m0 = wm * 64 + mt * 16 + g;
            #pragma unroll
            for (int nt = 0; nt < 4; nt++) {
                int n0 = wn * 32 + nt * 8 + 2 * t4;
                sf[m0 * 129 + n0]           = acc[mt][nt][0];
                sf[m0 * 129 + n0 + 1]       = acc[mt][nt][1];
                sf[(m0 + 8) * 129 + n0]     = acc[mt][nt][2];
                sf[(m0 + 8) * 129 + n0 + 1] = acc[mt][nt][3];
            }
        }
    }
    __syncthreads();

    if (mode == 0) {
        #pragma unroll 4
        for (int it = 0; it < 64; it++) {
            int idx = tid + (it << 8);
            int m = idx >> 7, j = idx & 127;
            float v = sf[m * 129 + j];
            unsigned short h, l;
            f16split(v, h, l);
            size_t o = (size_t)(brow + m) * BC + bcol + j;
            Xh[o] = h; Xl[o] = l;
        }
        #pragma unroll 4
        for (int it = 0; it < 64; it++) {
            int idx = tid + (it << 8);
            int j = idx >> 7, m = idx & 127;
            float v = sf[m * 129 + j];
            __half hh = __float2half_rn(v);
            CTh[(size_t)(bcol + j) * NN + brow + m] = *reinterpret_cast<unsigned short*>(&hh);
        }
    } else {
        #pragma unroll 4
        for (int it = 0; it < 64; it++) {
            int idx = tid + (it << 8);
            int m = idx >> 7, j = idx & 127;
            size_t o = (size_t)(brow + m) * BC + bcol + j;
            float d = f16join(D0h[o], D0l[o]);
            float v = 2.0f * sf[m * 129 + j] - d;
            unsigned short h, l;
            f16split(v, h, l);
            Xh[o] = h; Xl[o] = l;
        }
    }
}

// ---------------- 6) node GEMM gate (2-term, double-buffered) ----------------
// epilogue: o<64 -> z*state written into X0 state-half splits; o>=64 -> g_r
#define GATE_STAGE 32768
#define GATE_SMEM 65536

__global__ void __launch_bounds__(256)
k_tc_gate(const float* __restrict__ state)
{
    extern __shared__ char sm[];
    const uint32_t su = smem_to_u32(sm);
    const int n = blockIdx.x;
    const int tid = threadIdx.x;
    const int wid = tid >> 5, lane = tid & 31;
    const int wm = wid & 1, wn = wid >> 1;

    const unsigned short* xh[3] = { g_X0h + (size_t)n * BC, g_X1h + (size_t)n * BC, g_X2h + (size_t)n * BC };
    const unsigned short* xl[3] = { g_X0l + (size_t)n * BC, g_X1l + (size_t)n * BC, g_X2l + (size_t)n * BC };
    const unsigned short* wh = g_wgh + (size_t)n * KIO_G;

    float acc[2][4][4];
    #pragma unroll
    for (int i = 0; i < 2; i++)
        #pragma unroll
        for (int j = 0; j < 4; j++)
            #pragma unroll
            for (int q = 0; q < 4; q++) acc[i][j][q] = 0.f;

    const int arow = wm * 32 + (lane & 15);
    const int axor = (arow & 7) << 4;
    const int agco = (lane >> 4) << 4;
    const int brow = (lane & 7) + (((lane >> 3) & 1) << 3);
    const int bxor = (lane & 7) << 4;
    const int bgrp = (lane >> 4) << 4;

    auto load_stage = [&](int buf, int q) {
        const int t = q >> 1;
        const int c0 = (q & 1) << 6;
        uint32_t b0 = su + buf * GATE_STAGE;
        #pragma unroll
        for (int i = 0; i < 2; i++) {
            int lin = tid + (i << 8);
            int r = lin >> 3;
            int cb = (lin & 7) << 4;
            uint32_t dsw = r * 128 + (cb ^ ((r & 7) << 4));
            CP_ASYNC16(b0 + dsw,        (const char*)(xh[t] + r * 128 + c0) + cb);
            CP_ASYNC16(b0 + 8192 + dsw, (const char*)(xl[t] + r * 128 + c0) + cb);
        }
        #pragma unroll
        for (int i = 0; i < 4; i++) {
            int lin = tid + (i << 8);
            int kr = lin >> 4;
            int cb = (lin & 15) << 4;
            uint32_t dsw = kr * 256 + (cb ^ ((kr & 7) << 4));
            CP_ASYNC16(b0 + 16384 + dsw, (const char*)(wh + (size_t)(q * 64 + kr) * 128) + cb);
        }
        CP_COMMIT();
    };

    load_stage(0, 0);

    #pragma unroll 1
    for (int q = 0; q < 6; q++) {
        const int buf = q & 1;
        if (q + 1 < 6) { load_stage(1 - buf, q + 1); CP_WAIT1(); }
        else           { CP_WAIT0(); }
        __syncthreads();

        const uint32_t sb = su + buf * GATE_STAGE;
        #pragma unroll
        for (int ks = 0; ks < 4; ks++) {
            const int c = ks << 5;
            uint32_t ah[2][4], al[2][4], bh[4][2];
            #pragma unroll
            for (int mt = 0; mt < 2; mt++) {
                uint32_t ao = (uint32_t)((arow + mt * 16) * 128) + (uint32_t)((c + agco) ^ axor);
                ldsm_x4(ah[mt][0], ah[mt][1], ah[mt][2], ah[mt][3], sb + ao);
                ldsm_x4(al[mt][0], al[mt][1], al[mt][2], al[mt][3], sb + 8192 + ao);
            }
            #pragma unroll
            for (int nb = 0; nb < 2; nb++) {
                uint32_t bo = (uint32_t)((ks * 16 + brow) * 256)
                            + (uint32_t)((wn * 64 + nb * 32 + bgrp) ^ bxor);
                ldsm_x4_t(bh[2 * nb][0], bh[2 * nb][1], bh[2 * nb + 1][0], bh[2 * nb + 1][1],
                          sb + 16384 + bo);
            }
            #pragma unroll
            for (int mt = 0; mt < 2; mt++)
                #pragma unroll
                for (int nt = 0; nt < 4; nt++) {
                    mma16816(acc[mt][nt], ah[mt], bh[nt]);
                    mma16816(acc[mt][nt], al[mt], bh[nt]);
                }
        }
        __syncthreads();
    }

    const int g = lane >> 2, t4 = lane & 3;
    #pragma unroll
    for (int mt = 0; mt < 2; mt++) {
        int b0 = wm * 32 + mt * 16 + g;
        #pragma unroll
        for (int nt = 0; nt < 4; nt++) {
            int o = wn * 32 + nt * 8 + 2 * t4;
            float bi0 = g_bg[n * 128 + o];
            float bi1 = g_bg[n * 128 + o + 1];
            #pragma unroll
            for (int half = 0; half < 2; half++) {
                int b = b0 + half * 8;
                float v0 = acc[mt][nt][2 * half]     + bi0;
                float v1 = acc[mt][nt][2 * half + 1] + bi1;
                float s0 = 1.0f / (1.0f + expf(-v0));
                float s1 = 1.0f / (1.0f + expf(-v1));
                if (o < 64) {
                    // z*state -> X0 state-half splits
                    int sidx = b * (NN * HH) + n * HH + o;
                    float zs0 = s0 * state[sidx];
                    float zs1 = s1 * state[sidx + 1];
                    unsigned short h0, l0, h1, l1;
                    f16split(zs0, h0, l0); f16split(zs1, h1, l1);
                    int xo = n * BC + b * CIN + 64 + o;
                    g_X0h[xo] = h0; g_X0h[xo + 1] = h1;
                    g_X0l[xo] = l0; g_X0l[xo + 1] = l1;
                } else {
                    int base = b * (NN * HH) + n * HH + (o - 64);
                    g_r[base] = s0; g_r[base + 1] = s1;
                }
            }
        }
    }
}

// ---------------- 7) node GEMM update (2-term, double-buffered) ----------------
#define UPD_STAGE 24576

__global__ void __launch_bounds__(128)
k_tc_upd(const float* __restrict__ state, float* __restrict__ dout)
{
    __shared__ char sm[2 * UPD_STAGE];
    const uint32_t su = smem_to_u32(sm);
    const int n = blockIdx.x;
    const int tid = threadIdx.x;
    const int wid = tid >> 5, lane = tid & 31;
    const int wm = wid & 1, wn = wid >> 1;

    const unsigned short* xh[3] = { g_X0h + (size_t)n * BC, g_X1h + (size_t)n * BC, g_X2h + (size_t)n * BC };
    const unsigned short* xl[3] = { g_X0l + (size_t)n * BC, g_X1l + (size_t)n * BC, g_X2l + (size_t)n * BC };
    const unsigned short* wh = g_wuh + (size_t)n * KIO_U;

    float acc[2][4][4];
    #pragma unroll
    for (int i = 0; i < 2; i++)
        #pragma unroll
        for (int j = 0; j < 4; j++)
            #pragma unroll
            for (int q = 0; q < 4; q++) acc[i][j][q] = 0.f;

    const int arow = wm * 32 + (lane & 15);
    const int axor = (arow & 7) << 4;
    const int agco = (lane >> 4) << 4;
    const int brow = (lane & 7) + (((lane >> 3) & 1) << 3);
    const int bxor = (lane & 7) << 4;
    const int bgrp = (lane >> 4) << 4;

    auto load_stage = [&](int buf, int q) {
        const int t = q >> 1;
        const int c0 = (q & 1) << 6;
        uint32_t b0 = su + buf * UPD_STAGE;
        #pragma unroll
        for (int i = 0; i < 4; i++) {
            int lin = tid + (i << 7);
            int r = lin >> 3;
            int cb = (lin & 7) << 4;
            uint32_t dsw = r * 128 + (cb ^ ((r & 7) << 4));
            CP_ASYNC16(b0 + dsw,        (const char*)(xh[t] + r * 128 + c0) + cb);
            CP_ASYNC16(b0 + 8192 + dsw, (const char*)(xl[t] + r * 128 + c0) + cb);
        }
        #pragma unroll
        for (int i = 0; i < 4; i++) {
            int lin = tid + (i << 7);
            int kr = lin >> 3;
            int cb = (lin & 7) << 4;
            uint32_t dsw = kr * 128 + (cb ^ ((kr & 7) << 4));
            CP_ASYNC16(b0 + 16384 + dsw, (const char*)(wh + (size_t)(q * 64 + kr) * 64) + cb);
        }
        CP_COMMIT();
    };

    load_stage(0, 0);

    #pragma unroll 1
    for (int q = 0; q < 6; q++) {
        const int buf = q & 1;
        if (q + 1 < 6) { load_stage(1 - buf, q + 1); CP_WAIT1(); }
        else           { CP_WAIT0(); }
        __syncthreads();

        const uint32_t sb = su + buf * UPD_STAGE;
        #pragma unroll
        for (int ks = 0; ks < 4; ks++) {
            const int c = ks << 5;
            uint32_t ah[2][4], al[2][4], bh[4][2];
            #pragma unroll
            for (int mt = 0; mt < 2; mt++) {
                uint32_t ao = (uint32_t)((arow + mt * 16) * 128) + (uint32_t)((c + agco) ^ axor);
                ldsm_x4(ah[mt][0], ah[mt][1], ah[mt][2], ah[mt][3], sb + ao);
                ldsm_x4(al[mt][0], al[mt][1], al[mt][2], al[mt][3], sb + 8192 + ao);
            }
            #pragma unroll
            for (int nb = 0; nb < 2; nb++) {
                uint32_t bo = (uint32_t)((ks * 16 + brow) * 128)
                            + (uint32_t)((wn * 64 + nb * 32 + bgrp) ^ bxor);
                ldsm_x4_t(bh[2 * nb][0], bh[2 * nb][1], bh[2 * nb + 1][0], bh[2 * nb + 1][1],
                          sb + 16384 + bo);
            }
            #pragma unroll
            for (int mt = 0; mt < 2; mt++)
                #pragma unroll
                for (int nt = 0; nt < 4; nt++) {
                    mma16816(acc[mt][nt], ah[mt], bh[nt]);
                    mma16816(acc[mt][nt], al[mt], bh[nt]);
                }
        }
        __syncthreads();
    }

    const int g = lane >> 2, t4 = lane & 3;
    #pragma unroll
    for (int mt = 0; mt < 2; mt++) {
        int b0 = wm * 32 + mt * 16 + g;
        #pragma unroll
        for (int nt = 0; nt < 4; nt++) {
            int o = wn * 32 + nt * 8 + 2 * t4;
            float bi0 = g_bu[n * 64 + o];
            float bi1 = g_bu[n * 64 + o + 1];
            #pragma unroll
            for (int half = 0; half < 2; half++) {
                int b = b0 + half * 8;
                float hc0 = tanhf(acc[mt][nt][2 * half]     + bi0);
                float hc1 = tanhf(acc[mt][nt][2 * half + 1] + bi1);
                int idx = b * (NN * HH) + n * HH + o;
                float r0 = g_r[idx],     st0 = state[idx];
                float r1 = g_r[idx + 1], st1 = state[idx + 1];
                dout[idx]     = r0 * st0 + (1.0f - r0) * hc0;
                dout[idx + 1] = r1 * st1 + (1.0f - r1) * hc1;
            }
        }
    }
}

// ---------------- launch ----------------
extern "C" void kernel_launch(void* const* d_in, const int* in_sizes, int n_in,
                              void* d_out, int out_size)
{
    const float* x         = (const float*)d_in[0];
    const float* state     = (const float*)d_in[2];
    const float* node_emb  = (const float*)d_in[3];
    const float* time_emb  = (const float*)d_in[5];
    const float* gate_W    = (const float*)d_in[6];
    const float* gate_b    = (const float*)d_in[7];
    const float* gate_lnw  = (const float*)d_in[8];
    const float* gate_lnb  = (const float*)d_in[9];
    const float* update_W  = (const float*)d_in[10];
    const float* update_b  = (const float*)d_in[11];
    const float* update_lnw= (const float*)d_in[12];
    const float* update_lnb= (const float*)d_in[13];
    float* out = (float*)d_out;

    unsigned short *Sgh, *Suh, *XTh, *YTh;
    unsigned short *X0h, *X0l, *X1h, *X1l, *X2h, *X2l;
    cudaGetSymbolAddress((void**)&Sgh, g_Sgh);
    cudaGetSymbolAddress((void**)&Suh, g_Suh);
    cudaGetSymbolAddress((void**)&XTh, g_XTh);
    cudaGetSymbolAddress((void**)&YTh, g_YTh);
    cudaGetSymbolAddress((void**)&X0h, g_X0h);
    cudaGetSymbolAddress((void**)&X0l, g_X0l);
    cudaGetSymbolAddress((void**)&X1h, g_X1h);
    cudaGetSymbolAddress((void**)&X1l, g_X1l);
    cudaGetSymbolAddress((void**)&X2h, g_X2h);
    cudaGetSymbolAddress((void**)&X2l, g_X2l);

    cudaFuncSetAttribute(k_mmagemm, cudaFuncAttributeMaxDynamicSharedMemorySize, TCG_SMEM);
    cudaFuncSetAttribute(k_tc_gate, cudaFuncAttributeMaxDynamicSharedMemorySize, GATE_SMEM);

    k_prep<<<NN, 32>>>(node_emb, time_emb, gate_lnw, gate_lnb, update_lnw, update_lnb,
                       gate_b, update_b);
    k_supports<<<dim3(NN, 2), 256>>>();
    k_wgen<<<dim3(KIO_G / 256, NN / 32), 256>>>(gate_W, 0);
    k_wgen<<<dim3(KIO_U / 256, NN / 32), 256>>>(update_W, 1);

    dim3 gg(BC / 128, NN / 128);

    // ---- gate magcn ----
    k_build_xin<<<(NN * BC / 4) / 256, 256>>>(x, state);
    k_transpose<<<dim3(BC / 32, NN / 32), dim3(32, 8)>>>(X0h, XTh, 0);
    k_mmagemm<<<gg, 256, TCG_SMEM>>>(Sgh, XTh, nullptr, nullptr, X1h, X1l, YTh, 0);
    k_mmagemm<<<gg, 256, TCG_SMEM>>>(Sgh, YTh, X0h, X0l, X2h, X2l, nullptr, 1);
    k_tc_gate<<<NN, 256, GATE_SMEM>>>(state);   // writes z*state into X0 state-half + g_r

    // ---- update magcn ----
    k_transpose<<<dim3(BC / 64, NN / 32), dim3(32, 8)>>>(X0h, XTh, 1);  // state-half only
    k_mmagemm<<<gg, 256, TCG_SMEM>>>(Suh, XTh, nullptr, nullptr, X1h, X1l, YTh, 0);
    k_mmagemm<<<gg, 256, TCG_SMEM>>>(Suh, YTh, X0h, X0l, X2h, X2l, nullptr, 1);
    k_tc_upd<<<NN, 128>>>(state, out);
}

// round 8
// speedup vs baseline: 4.2434x; 1.0533x over previous
#include <cuda_runtime.h>
#include <cuda_fp16.h>
#include <math.h>
#include <stdint.h>

#define NN 1024
#define BB 64
#define CC 64
#define HH 64
#define DD 16
#define CIN 128
#define BC 8192            // BB * CIN
#define KIO_G 49152        // 384*128
#define KIO_U 24576        // 384*64

// ---------------- scratch ----------------
__device__ float g_eg[NN * DD];
__device__ float g_eu[NN * DD];
__device__ float g_bg[NN * 128];
__device__ float g_bu[NN * 64];
__device__ float g_r[BB * NN * HH];

__device__ unsigned short g_Sgh[NN * NN];
__device__ unsigned short g_Suh[NN * NN];
__device__ unsigned short g_STt[NN * NN];   // scratch S^T
__device__ unsigned short g_T2g[NN * NN];   // 2*Sg^2 - I (fp16)
__device__ unsigned short g_T2u[NN * NN];   // 2*Su^2 - I (fp16)
__device__ unsigned short g_XTh[BC * NN];   // transposed X0h [col][k]
__device__ unsigned short g_X0h[NN * BC];
__device__ unsigned short g_X0l[NN * BC];
__device__ unsigned short g_X1h[NN * BC];
__device__ unsigned short g_X1l[NN * BC];
__device__ unsigned short g_X2h[NN * BC];
__device__ unsigned short g_X2l[NN * BC];
__device__ unsigned short g_wgh[NN * KIO_G];
__device__ unsigned short g_wuh[NN * KIO_U];

// ---------------- helpers ----------------
__device__ __forceinline__ uint32_t smem_to_u32(const void* p) {
    uint32_t a;
    asm("{ .reg .u64 t; cvta.to.shared.u64 t, %1; cvt.u32.u64 %0, t; }" : "=r"(a) : "l"(p));
    return a;
}

#define CP_ASYNC16(dst, src) \
    asm volatile("cp.async.cg.shared.global [%0], [%1], 16;" :: "r"(dst), "l"(src))
#define CP_COMMIT()  asm volatile("cp.async.commit_group;" ::: "memory")
#define CP_WAIT0()   asm volatile("cp.async.wait_group 0;" ::: "memory")
#define CP_WAIT1()   asm volatile("cp.async.wait_group 1;" ::: "memory")

__device__ __forceinline__ void ldsm_x4(uint32_t& r0, uint32_t& r1, uint32_t& r2, uint32_t& r3,
                                        uint32_t addr) {
    asm volatile("ldmatrix.sync.aligned.m8n8.x4.shared.b16 {%0,%1,%2,%3}, [%4];"
                 : "=r"(r0), "=r"(r1), "=r"(r2), "=r"(r3) : "r"(addr));
}
__device__ __forceinline__ void ldsm_x4_t(uint32_t& r0, uint32_t& r1, uint32_t& r2, uint32_t& r3,
                                          uint32_t addr) {
    asm volatile("ldmatrix.sync.aligned.m8n8.x4.trans.shared.b16 {%0,%1,%2,%3}, [%4];"
                 : "=r"(r0), "=r"(r1), "=r"(r2), "=r"(r3) : "r"(addr));
}

__device__ __forceinline__ void mma16816(float* c, const uint32_t* a, const uint32_t* b) {
    asm volatile("mma.sync.aligned.m16n8k16.row.col.f32.f16.f16.f32 "
                 "{%0,%1,%2,%3}, {%4,%5,%6,%7}, {%8,%9}, {%0,%1,%2,%3};"
                 : "+f"(c[0]), "+f"(c[1]), "+f"(c[2]), "+f"(c[3])
                 : "r"(a[0]), "r"(a[1]), "r"(a[2]), "r"(a[3]), "r"(b[0]), "r"(b[1]));
}

__device__ __forceinline__ void f16split(float x, unsigned short& h, unsigned short& l) {
    __half hb = __float2half_rn(x);
    __half lb = __float2half_rn(x - __half2float(hb));
    h = *reinterpret_cast<unsigned short*>(&hb);
    l = *reinterpret_cast<unsigned short*>(&lb);
}

// ---------------- 1) e = LN(node_emb + time_emb), bias = e @ b_pool ----------------
__global__ void k_prep(const float* __restrict__ ne, const float* __restrict__ te,
                       const float* __restrict__ gw, const float* __restrict__ gbln,
                       const float* __restrict__ uw, const float* __restrict__ ubln,
                       const float* __restrict__ gate_b, const float* __restrict__ update_b)
{
    int n = blockIdx.x;
    int lane = threadIdx.x;
    int d = lane & 15;
    float v = ne[n * DD + d] + te[d];

    float s = v;
    #pragma unroll
    for (int off = 16; off > 0; off >>= 1) s += __shfl_xor_sync(0xffffffffu, s, off);
    float mean = s * (1.0f / 32.0f);
    float dv = v - mean;
    float q = dv * dv;
    #pragma unroll
    for (int off = 16; off > 0; off >>= 1) q += __shfl_xor_sync(0xffffffffu, q, off);
    float var = q * (1.0f / 32.0f);
    float inv = rsqrtf(var + 1e-12f);

    float eg = dv * inv * gw[d] + gbln[d];
    float eu = dv * inv * uw[d] + ubln[d];
    if (lane < 16) { g_eg[n * DD + d] = eg; g_eu[n * DD + d] = eu; }

    for (int o = lane; o < 128; o += 32) {
        float b = 0.f;
        #pragma unroll
        for (int dd = 0; dd < 16; dd++)
            b += __shfl_sync(0xffffffffu, eg, dd) * gate_b[dd * 128 + o];
        g_bg[n * 128 + o] = b;
    }
    for (int o = lane; o < 64; o += 32) {
        float b = 0.f;
        #pragma unroll
        for (int dd = 0; dd < 16; dd++)
            b += __shfl_sync(0xffffffffu, eu, dd) * update_b[dd * 64 + o];
        g_bu[n * 64 + o] = b;
    }
}

// ---------------- 2) S = softmax(e e^T), fp16 ----------------
__global__ void k_supports()
{
    int n = blockIdx.x;
    int which = blockIdx.y;
    const float* e = which ? g_eu : g_eg;
    unsigned short* Sh = which ? g_Suh : g_Sgh;

    __shared__ float en[16];
    __shared__ float red[256];
    int tid = threadIdx.x;
    if (tid < 16) en[tid] = e[n * DD + tid];
    __syncthreads();

    float lv[4];
    float mx = -1e30f;
    #pragma unroll
    for (int i = 0; i < 4; i++) {
        int m = tid + i * 256;
        const float* em = &e[m * DD];
        float dot = 0.f;
        #pragma unroll
        for (int dd = 0; dd < 16; dd++) dot += en[dd] * em[dd];
        lv[i] = dot;
        mx = fmaxf(mx, dot);
    }
    red[tid] = mx; __syncthreads();
    for (int s = 128; s > 0; s >>= 1) {
        if (tid < s) red[tid] = fmaxf(red[tid], red[tid + s]);
        __syncthreads();
    }
    mx = red[0];
    __syncthreads();

    float sum = 0.f;
    #pragma unroll
    for (int i = 0; i < 4; i++) { lv[i] = expf(lv[i] - mx); sum += lv[i]; }
    red[tid] = sum; __syncthreads();
    for (int s = 128; s > 0; s >>= 1) {
        if (tid < s) red[tid] += red[tid + s];
        __syncthreads();
    }
    float invs = 1.0f / red[0];
    #pragma unroll
    for (int i = 0; i < 4; i++) {
        float v = lv[i] * invs;
        __half hh = __float2half_rn(v);
        Sh[n * NN + tid + i * 256] = *reinterpret_cast<unsigned short*>(&hh);
    }
}

// ---------------- 3) tensor-core wgen: W[n,kio] = e[n,:] @ Wp[:,kio] ----------------
// 2-term A (e hi+lo), B = fp16(Wp). Block: 64 nodes x 512 kio, 256 threads.
__global__ void __launch_bounds__(256)
k_wgen_mma(const float* __restrict__ Wp, int which)
{
    const int KIO = which ? KIO_U : KIO_G;
    unsigned short* wh = which ? g_wuh : g_wgh;
    const float* e = which ? g_eu : g_eg;

    __shared__ char sm[16384 + 2048 + 2048];   // Bs [16][512]f16 | eh [64][16] | el [64][16]
    const uint32_t su = smem_to_u32(sm);
    const int tid = threadIdx.x;
    const int wid = tid >> 5, lane = tid & 31;
    const int kio0 = blockIdx.x << 9;
    const int n0 = blockIdx.y << 6;

    // load e (64 nodes x 16) -> hi/lo fp16
    {
        float4 v = *(const float4*)&e[n0 * DD + tid * 4];
        ushort4 h4, l4;
        f16split(v.x, h4.x, l4.x); f16split(v.y, h4.y, l4.y);
        f16split(v.z, h4.z, l4.z); f16split(v.w, h4.w, l4.w);
        *(ushort4*)(sm + 16384 + tid * 8) = h4;
        *(ushort4*)(sm + 18432 + tid * 8) = l4;
    }
    // load Wp chunk 16 x 512 fp32 -> fp16 smem (swizzled 1024B rows)
    #pragma unroll
    for (int i = 0; i < 8; i++) {
        int lin = tid + (i << 8);          // 0..2047 float4s
        int r = lin >> 7;
        int cf4 = lin & 127;
        float4 v = *(const float4*)&Wp[(size_t)r * KIO + kio0 + cf4 * 4];
        __half2 p0 = __floats2half2_rn(v.x, v.y);
        __half2 p1 = __floats2half2_rn(v.z, v.w);
        uint2 pk = { *reinterpret_cast<uint32_t*>(&p0), *reinterpret_cast<uint32_t*>(&p1) };
        uint32_t cb = (uint32_t)(cf4 * 8);
        *(uint2*)(sm + r * 1024 + (cb ^ ((r & 7) << 4))) = pk;
    }
    __syncthreads();

    const int mw = wid & 3;        // m-tile (16 nodes)
    const int nhalf = wid >> 2;    // 0/1 -> 256 kio each
    const int g = lane >> 2, t4 = lane & 3;

    uint32_t a_h[4], a_l[4];
    {
        uint32_t ao = (uint32_t)((mw * 16 + (lane & 15)) * 32 + ((lane >> 4) << 4));
        ldsm_x4(a_h[0], a_h[1], a_h[2], a_h[3], su + 16384 + ao);
        ldsm_x4(a_l[0], a_l[1], a_l[2], a_l[3], su + 18432 + ao);
    }

    const int brow = (lane & 7) + (((lane >> 3) & 1) << 3);
    const uint32_t bxor = (uint32_t)((brow & 7) << 4);
    const uint32_t bgrp = (uint32_t)((lane >> 4) << 4);

    #pragma unroll
    for (int nt2 = 0; nt2 < 16; nt2++) {
        uint32_t b[2][2];
        uint32_t bo = (uint32_t)(brow * 1024) + ((uint32_t)(nhalf * 512 + nt2 * 32 + bgrp) ^ bxor);
        ldsm_x4_t(b[0][0], b[0][1], b[1][0], b[1][1], su + bo);
        #pragma unroll
        for (int t = 0; t < 2; t++) {
            float c[4] = {0.f, 0.f, 0.f, 0.f};
            mma16816(c, a_h, b[t]);
            mma16816(c, a_l, b[t]);
            int node = n0 + mw * 16 + g;
            int kio = kio0 + nhalf * 256 + nt2 * 16 + t * 8 + 2 * t4;
            __half2 p0 = __floats2half2_rn(c[0], c[1]);
            __half2 p1 = __floats2half2_rn(c[2], c[3]);
            *(uint32_t*)(wh + (size_t)node * KIO + kio)       = *reinterpret_cast<uint32_t*>(&p0);
            *(uint32_t*)(wh + (size_t)(node + 8) * KIO + kio) = *reinterpret_cast<uint32_t*>(&p1);
        }
    }
}

// ---------------- 4) build X0 = split(concat(x, state)) ----------------
__global__ void k_build_xin(const float* __restrict__ x, const float* __restrict__ state)
{
    int t = blockIdx.x * 256 + threadIdx.x;
    int n = t >> 11;
    int j = t & 2047;
    int b = j >> 5;
    int c = (j & 31) << 2;

    float4 v;
    if (c < 64) {
        v = *(const float4*)&x[b * (NN * CC) + n * CC + c];
    } else {
        v = *(const float4*)&state[b * (NN * HH) + n * HH + (c - 64)];
    }
    int o = n * BC + b * CIN + c;
    ushort4 h4, l4;
    f16split(v.x, h4.x, l4.x); f16split(v.y, h4.y, l4.y);
    f16split(v.z, h4.z, l4.z); f16split(v.w, h4.w, l4.w);
    *(ushort4*)&g_X0h[o] = h4;
    *(ushort4*)&g_X0l[o] = l4;
}

// ---------------- 4b) u16 transposes ----------------
__global__ void k_transposeX(const unsigned short* __restrict__ in,
                             unsigned short* __restrict__ outp, int half)
{
    __shared__ unsigned short t[32][34];
    int tilex = half ? (((blockIdx.x >> 1) << 2) + 2 + (blockIdx.x & 1)) : blockIdx.x;
    int bc = tilex << 5;
    int bn = blockIdx.y << 5;
    int x = threadIdx.x, y = threadIdx.y;  // 32 x 8
    #pragma unroll
    for (int i = 0; i < 4; i++)
        t[y + i * 8][x] = in[(bn + y + i * 8) * BC + bc + x];
    __syncthreads();
    #pragma unroll
    for (int i = 0; i < 4; i++)
        outp[(bc + y + i * 8) * NN + bn + x] = t[x][y + i * 8];
}

__global__ void k_transposeS(const unsigned short* __restrict__ in,
                             unsigned short* __restrict__ outp)
{
    __shared__ unsigned short t[32][34];
    int bc = blockIdx.x << 5;
    int bn = blockIdx.y << 5;
    int x = threadIdx.x, y = threadIdx.y;
    #pragma unroll
    for (int i = 0; i < 4; i++)
        t[y + i * 8][x] = in[(bn + y + i * 8) * NN + bc + x];
    __syncthreads();
    #pragma unroll
    for (int i = 0; i < 4; i++)
        outp[(bc + y + i * 8) * NN + bn + x] = t[x][y + i * 8];
}

// ---------------- 4c) T2 = 2*S@S - I (fp16), via S and S^T ----------------
#define SS_STAGE 32768
#define SS_SMEM  65536

__global__ void __launch_bounds__(256, 2)
k_ss(const unsigned short* __restrict__ Sh, const unsigned short* __restrict__ STt,
     unsigned short* __restrict__ T2)
{
    extern __shared__ char smem[];
    const uint32_t smem_u = smem_to_u32(smem);
    const int tid = threadIdx.x;
    const int wid = tid >> 5, lane = tid & 31;
    const int brow = blockIdx.y << 7;
    const int bcol = blockIdx.x << 7;
    const int wm = wid & 1, wn = wid >> 1;

    const unsigned short* srcs[2];
    srcs[0] = Sh + (size_t)brow * NN;
    srcs[1] = STt + (size_t)bcol * NN;

    float acc[4][4][4];
    #pragma unroll
    for (int i = 0; i < 4; i++)
        #pragma unroll
        for (int j = 0; j < 4; j++)
            #pragma unroll
            for (int q = 0; q < 4; q++) acc[i][j][q] = 0.f;

    const int arow = wm * 64 + (lane & 15);
    const int axor = (arow & 7) << 4;
    const int agco = (lane >> 4) << 4;
    const int bn   = wn * 32 + ((lane >> 4) << 3) + (lane & 7);
    const int bxor = (bn & 7) << 4;
    const int bko  = ((lane >> 3) & 1) << 4;

    auto load_stage = [&](int buf, int kk) {
        uint32_t dst0 = smem_u + buf * SS_STAGE;
        #pragma unroll
        for (int i = 0; i < 8; i++) {
            int lin = tid + (i << 8);
            int arr = lin >> 10;
            int r = (lin >> 3) & 127;
            int cb = (lin & 7) << 4;
            const char* src = (const char*)(srcs[arr] + (size_t)r * NN + kk) + cb;
            uint32_t d = dst0 + arr * 16384 + r * 128 + (cb ^ ((r & 7) << 4));
            CP_ASYNC16(d, src);
        }
        CP_COMMIT();
    };

    load_stage(0, 0);

    #pragma unroll 1
    for (int s = 0; s < 16; s++) {
        const int buf = s & 1;
        CP_WAIT0();
        __syncthreads();
        if (s + 1 < 16) load_stage(1 - buf, (s + 1) << 6);

        const uint32_t sb = smem_u + buf * SS_STAGE;
        #pragma unroll
        for (int ks = 0; ks < 4; ks++) {
            const int c = ks << 5;
            uint32_t ah[4][4], bh[4][2];
            #pragma unroll
            for (int mt = 0; mt < 4; mt++) {
                uint32_t ao = (uint32_t)((arow + mt * 16) * 128) + (uint32_t)((c + agco) ^ axor);
                ldsm_x4(ah[mt][0], ah[mt][1], ah[mt][2], ah[mt][3], sb + ao);
            }
            #pragma unroll
            for (int nb = 0; nb < 2; nb++) {
                uint32_t bo = (uint32_t)((bn + nb * 16) * 128) + (uint32_t)((c + bko) ^ bxor);
                ldsm_x4(bh[2 * nb][0], bh[2 * nb][1], bh[2 * nb + 1][0], bh[2 * nb + 1][1],
                        sb + 16384 + bo);
            }
            #pragma unroll
            for (int mt = 0; mt < 4; mt++)
                #pragma unroll
                for (int nt = 0; nt < 4; nt++)
                    mma16816(acc[mt][nt], ah[mt], bh[nt]);
        }
        __syncthreads();
    }

    // epilogue: T2 = 2*acc - I, fp16, direct writes
    const int g = lane >> 2, t4 = lane & 3;
    #pragma unroll
    for (int mt = 0; mt < 4; mt++) {
        #pragma unroll
        for (int nt = 0; nt < 4; nt++) {
            int m0 = wm * 64 + mt * 16 + g;
            int n0c = wn * 32 + nt * 8 + 2 * t4;
            #pragma unroll
            for (int half = 0; half < 2; half++) {
                int m = m0 + half * 8;
                int row = brow + m, col = bcol + n0c;
                float v0 = 2.0f * acc[mt][nt][2 * half]     - (row == col ? 1.0f : 0.0f);
                float v1 = 2.0f * acc[mt][nt][2 * half + 1] - (row == col + 1 ? 1.0f : 0.0f);
                __half2 p = __floats2half2_rn(v0, v1);
                *(uint32_t*)(T2 + (size_t)row * NN + col) = *reinterpret_cast<uint32_t*>(&p);
            }
        }
    }
}

// ---------------- 5) fused big GEMM: [Y1;Y2] = [S;T2] @ X ----------------
#define STAGE_BYTES 32768
#define TCG_SMEM 66560

__global__ void __launch_bounds__(256, 2)
k_mmagemm2(const unsigned short* __restrict__ A1,   // S   [1024][1024]
           const unsigned short* __restrict__ A2,   // T2  [1024][1024]
           const unsigned short* __restrict__ Bh,   // X^T [8192][1024]
           unsigned short* __restrict__ O1h, unsigned short* __restrict__ O1l,
           unsigned short* __restrict__ O2h, unsigned short* __restrict__ O2l)
{
    extern __shared__ char smem[];
    const uint32_t smem_u = smem_to_u32(smem);
    const int tid = threadIdx.x;
    const int wid = tid >> 5;
    const int lane = tid & 31;
    const int by = blockIdx.y;                 // 0..15
    const int rowA = (by & 7) << 7;            // row within S or T2
    const int bcol = blockIdx.x << 7;
    const int wm = wid & 1;
    const int wn = wid >> 1;

    const unsigned short* Aarr = (by < 8) ? A1 : A2;
    unsigned short* Xh = (by < 8) ? O1h : O2h;
    unsigned short* Xl = (by < 8) ? O1l : O2l;

    const unsigned short* srcs[2];
    srcs[0] = Aarr + (size_t)rowA * NN;
    srcs[1] = Bh + (size_t)bcol * NN;

    float acc[4][4][4];
    #pragma unroll
    for (int i = 0; i < 4; i++)
        #pragma unroll
        for (int j = 0; j < 4; j++)
            #pragma unroll
            for (int q = 0; q < 4; q++) acc[i][j][q] = 0.f;

    const int arow = wm * 64 + (lane & 15);
    const int axor = (arow & 7) << 4;
    const int agco = (lane >> 4) << 4;
    const int bn   = wn * 32 + ((lane >> 4) << 3) + (lane & 7);
    const int bxor = (bn & 7) << 4;
    const int bko  = ((lane >> 3) & 1) << 4;

    auto load_stage = [&](int buf, int kk) {
        uint32_t dst0 = smem_u + buf * STAGE_BYTES;
        #pragma unroll
        for (int i = 0; i < 8; i++) {
            int lin = tid + (i << 8);
            int arr = lin >> 10;
            int r = (lin >> 3) & 127;
            int cb = (lin & 7) << 4;
            const char* src = (const char*)(srcs[arr] + (size_t)r * NN + kk) + cb;
            uint32_t d = dst0 + arr * 16384 + r * 128 + (cb ^ ((r & 7) << 4));
            CP_ASYNC16(d, src);
        }
        CP_COMMIT();
    };

    load_stage(0, 0);

    #pragma unroll 1
    for (int s = 0; s < 16; s++) {
        const int buf = s & 1;
        CP_WAIT0();
        __syncthreads();
        if (s + 1 < 16) load_stage(1 - buf, (s + 1) << 6);

        const uint32_t sb = smem_u + buf * STAGE_BYTES;
        #pragma unroll
        for (int ks = 0; ks < 4; ks++) {
            const int c = ks << 5;
            uint32_t ah[4][4], bh[4][2];
            #pragma unroll
            for (int mt = 0; mt < 4; mt++) {
                uint32_t ao = (uint32_t)((arow + mt * 16) * 128) + (uint32_t)((c + agco) ^ axor);
                ldsm_x4(ah[mt][0], ah[mt][1], ah[mt][2], ah[mt][3], sb + ao);
            }
            #pragma unroll
            for (int nb = 0; nb < 2; nb++) {
                uint32_t bo = (uint32_t)((bn + nb * 16) * 128) + (uint32_t)((c + bko) ^ bxor);
                ldsm_x4(bh[2 * nb][0], bh[2 * nb][1], bh[2 * nb + 1][0], bh[2 * nb + 1][1],
                        sb + 16384 + bo);
            }
            #pragma unroll
            for (int mt = 0; mt < 4; mt++)
                #pragma unroll
                for (int nt = 0; nt < 4; nt++)
                    mma16816(acc[mt][nt], ah[mt], bh[nt]);
        }
        __syncthreads();
    }

    // epilogue via smem (128 x 129 fp32), split writes
    float* sf = (float*)smem;
    __syncthreads();
    {
        int g = lane >> 2, t4 = lane & 3;
        #pragma unroll
        for (int mt = 0; mt < 4; mt++) {
            int m0 = wm * 64 + mt * 16 + g;
            #pragma unroll
            for (int nt = 0; nt < 4; nt++) {
                int n0 = wn * 32 + nt * 8 + 2 * t4;
                sf[m0 * 129 + n0]           = acc[mt][nt][0];
                sf[m0 * 129 + n0 + 1]       = acc[mt][nt][1];
                sf[(m0 + 8) * 129 + n0]     = acc[mt][nt][2];
                sf[(m0 + 8) * 129 + n0 + 1] = acc[mt][nt][3];
            }
        }
    }
    __syncthreads();

    #pragma unroll 4
    for (int it = 0; it < 64; it++) {
        int idx = tid + (it << 8);
        int m = idx >> 7, j = idx & 127;
        float v = sf[m * 129 + j];
        unsigned short h, l;
        f16split(v, h, l);
        size_t o = (size_t)(rowA + m) * BC + bcol + j;
        Xh[o] = h; Xl[o] = l;
    }
}

// ---------------- 6) node GEMM gate (2-term, double-buffered) ----------------
#define GATE_STAGE 32768
#define GATE_SMEM 65536

__global__ void __launch_bounds__(256)
k_tc_gate(const float* __restrict__ state)
{
    extern __shared__ char sm[];
    const uint32_t su = smem_to_u32(sm);
    const int n = blockIdx.x;
    const int tid = threadIdx.x;
    const int wid = tid >> 5, lane = tid & 31;
    const int wm = wid & 1, wn = wid >> 1;

    const unsigned short* xh[3] = { g_X0h + (size_t)n * BC, g_X1h + (size_t)n * BC, g_X2h + (size_t)n * BC };
    const unsigned short* xl[3] = { g_X0l + (size_t)n * BC, g_X1l + (size_t)n * BC, g_X2l + (size_t)n * BC };
    const unsigned short* wh = g_wgh + (size_t)n * KIO_G;

    float acc[2][4][4];
    #pragma unroll
    for (int i = 0; i < 2; i++)
        #pragma unroll
        for (int j = 0; j < 4; j++)
            #pragma unroll
            for (int q = 0; q < 4; q++) acc[i][j][q] = 0.f;

    const int arow = wm * 32 + (lane & 15);
    const int axor = (arow & 7) << 4;
    const int agco = (lane >> 4) << 4;
    const int brow = (lane & 7) + (((lane >> 3) & 1) << 3);
    const int bxor = (lane & 7) << 4;
    const int bgrp = (lane >> 4) << 4;

    auto load_stage = [&](int buf, int q) {
        const int t = q >> 1;
        const int c0 = (q & 1) << 6;
        uint32_t b0 = su + buf * GATE_STAGE;
        #pragma unroll
        for (int i = 0; i < 2; i++) {
            int lin = tid + (i << 8);
            int r = lin >> 3;
            int cb = (lin & 7) << 4;
            uint32_t dsw = r * 128 + (cb ^ ((r & 7) << 4));
            CP_ASYNC16(b0 + dsw,        (const char*)(xh[t] + r * 128 + c0) + cb);
            CP_ASYNC16(b0 + 8192 + dsw, (const char*)(xl[t] + r * 128 + c0) + cb);
        }
        #pragma unroll
        for (int i = 0; i < 4; i++) {
            int lin = tid + (i << 8);
            int kr = lin >> 4;
            int cb = (lin & 15) << 4;
            uint32_t dsw = kr * 256 + (cb ^ ((kr & 7) << 4));
            CP_ASYNC16(b0 + 16384 + dsw, (const char*)(wh + (size_t)(q * 64 + kr) * 128) + cb);
        }
        CP_COMMIT();
    };

    load_stage(0, 0);

    #pragma unroll 1
    for (int q = 0; q < 6; q++) {
        const int buf = q & 1;
        if (q + 1 < 6) { load_stage(1 - buf, q + 1); CP_WAIT1(); }
        else           { CP_WAIT0(); }
        __syncthreads();

        const uint32_t sb = su + buf * GATE_STAGE;
        #pragma unroll
        for (int ks = 0; ks < 4; ks++) {
            const int c = ks << 5;
            uint32_t ah[2][4], al[2][4], bh[4][2];
            #pragma unroll
            for (int mt = 0; mt < 2; mt++) {
                uint32_t ao = (uint32_t)((arow + mt * 16) * 128) + (uint32_t)((c + agco) ^ axor);
                ldsm_x4(ah[mt][0], ah[mt][1], ah[mt][2], ah[mt][3], sb + ao);
                ldsm_x4(al[mt][0], al[mt][1], al[mt][2], al[mt][3], sb + 8192 + ao);
            }
            #pragma unroll
            for (int nb = 0; nb < 2; nb++) {
                uint32_t bo = (uint32_t)((ks * 16 + brow) * 256)
                            + (uint32_t)((wn * 64 + nb * 32 + bgrp) ^ bxor);
                ldsm_x4_t(bh[2 * nb][0], bh[2 * nb][1], bh[2 * nb + 1][0], bh[2 * nb + 1][1],
                          sb + 16384 + bo);
            }
            #pragma unroll
            for (int mt = 0; mt < 2; mt++)
                #pragma unroll
                for (int nt = 0; nt < 4; nt++) {
                    mma16816(acc[mt][nt], ah[mt], bh[nt]);
                    mma16816(acc[mt][nt], al[mt], bh[nt]);
                }
        }
        __syncthreads();
    }

    const int g = lane >> 2, t4 = lane & 3;
    #pragma unroll
    for (int mt = 0; mt < 2; mt++) {
        int b0 = wm * 32 + mt * 16 + g;
        #pragma unroll
        for (int nt = 0; nt < 4; nt++) {
            int o = wn * 32 + nt * 8 + 2 * t4;
            float bi0 = g_bg[n * 128 + o];
            float bi1 = g_bg[n * 128 + o + 1];
            #pragma unroll
            for (int half = 0; half < 2; half++) {
                int b = b0 + half * 8;
                float v0 = acc[mt][nt][2 * half]     + bi0;
                float v1 = acc[mt][nt][2 * half + 1] + bi1;
                float s0 = 1.0f / (1.0f + expf(-v0));
                float s1 = 1.0f / (1.0f + expf(-v1));
                if (o < 64) {
                    int sidx = b * (NN * HH) + n * HH + o;
                    float zs0 = s0 * state[sidx];
                    float zs1 = s1 * state[sidx + 1];
                    unsigned short h0, l0, h1, l1;
                    f16split(zs0, h0, l0); f16split(zs1, h1, l1);
                    int xo = n * BC + b * CIN + 64 + o;
                    g_X0h[xo] = h0; g_X0h[xo + 1] = h1;
                    g_X0l[xo] = l0; g_X0l[xo + 1] = l1;
                } else {
                    int base = b * (NN * HH) + n * HH + (o - 64);
                    g_r[base] = s0; g_r[base + 1] = s1;
                }
            }
        }
    }
}

// ---------------- 7) node GEMM update (2-term, double-buffered) ----------------
#define UPD_STAGE 24576

__global__ void __launch_bounds__(128)
k_tc_upd(const float* __restrict__ state, float* __restrict__ dout)
{
    __shared__ char sm[2 * UPD_STAGE];
    const uint32_t su = smem_to_u32(sm);
    const int n = blockIdx.x;
    const int tid = threadIdx.x;
    const int wid = tid >> 5, lane = tid & 31;
    const int wm = wid & 1, wn = wid >> 1;

    const unsigned short* xh[3] = { g_X0h + (size_t)n * BC, g_X1h + (size_t)n * BC, g_X2h + (size_t)n * BC };
    const unsigned short* xl[3] = { g_X0l + (size_t)n * BC, g_X1l + (size_t)n * BC, g_X2l + (size_t)n * BC };
    const unsigned short* wh = g_wuh + (size_t)n * KIO_U;

    float acc[2][4][4];
    #pragma unroll
    for (int i = 0; i < 2; i++)
        #pragma unroll
        for (int j = 0; j < 4; j++)
            #pragma unroll
            for (int q = 0; q < 4; q++) acc[i][j][q] = 0.f;

    const int arow = wm * 32 + (lane & 15);
    const int axor = (arow & 7) << 4;
    const int agco = (lane >> 4) << 4;
    const int brow = (lane & 7) + (((lane >> 3) & 1) << 3);
    const int bxor = (lane & 7) << 4;
    const int bgrp = (lane >> 4) << 4;

    auto load_stage = [&](int buf, int q) {
        const int t = q >> 1;
        const int c0 = (q & 1) << 6;
        uint32_t b0 = su + buf * UPD_STAGE;
        #pragma unroll
        for (int i = 0; i < 4; i++) {
            int lin = tid + (i << 7);
            int r = lin >> 3;
            int cb = (lin & 7) << 4;
            uint32_t dsw = r * 128 + (cb ^ ((r & 7) << 4));
            CP_ASYNC16(b0 + dsw,        (const char*)(xh[t] + r * 128 + c0) + cb);
            CP_ASYNC16(b0 + 8192 + dsw, (const char*)(xl[t] + r * 128 + c0) + cb);
        }
        #pragma unroll
        for (int i = 0; i < 4; i++) {
            int lin = tid + (i << 7);
            int kr = lin >> 3;
            int cb = (lin & 7) << 4;
            uint32_t dsw = kr * 128 + (cb ^ ((kr & 7) << 4));
            CP_ASYNC16(b0 + 16384 + dsw, (const char*)(wh + (size_t)(q * 64 + kr) * 64) + cb);
        }
        CP_COMMIT();
    };

    load_stage(0, 0);

    #pragma unroll 1
    for (int q = 0; q < 6; q++) {
        const int buf = q & 1;
        if (q + 1 < 6) { load_stage(1 - buf, q + 1); CP_WAIT1(); }
        else           { CP_WAIT0(); }
        __syncthreads();

        const uint32_t sb = su + buf * UPD_STAGE;
        #pragma unroll
        for (int ks = 0; ks < 4; ks++) {
            const int c = ks << 5;
            uint32_t ah[2][4], al[2][4], bh[4][2];
            #pragma unroll
            for (int mt = 0; mt < 2; mt++) {
                uint32_t ao = (uint32_t)((arow + mt * 16) * 128) + (uint32_t)((c + agco) ^ axor);
                ldsm_x4(ah[mt][0], ah[mt][1], ah[mt][2], ah[mt][3], sb + ao);
                ldsm_x4(al[mt][0], al[mt][1], al[mt][2], al[mt][3], sb + 8192 + ao);
            }
            #pragma unroll
            for (int nb = 0; nb < 2; nb++) {
                uint32_t bo = (uint32_t)((ks * 16 + brow) * 128)
                            + (uint32_t)((wn * 64 + nb * 32 + bgrp) ^ bxor);
                ldsm_x4_t(bh[2 * nb][0], bh[2 * nb][1], bh[2 * nb + 1][0], bh[2 * nb + 1][1],
                          sb + 16384 + bo);
            }
            #pragma unroll
            for (int mt = 0; mt < 2; mt++)
                #pragma unroll
                for (int nt = 0; nt < 4; nt++) {
                    mma16816(acc[mt][nt], ah[mt], bh[nt]);
                    mma16816(acc[mt][nt], al[mt], bh[nt]);
                }
        }
        __syncthreads();
    }

    const int g = lane >> 2, t4 = lane & 3;
    #pragma unroll
    for (int mt = 0; mt < 2; mt++) {
        int b0 = wm * 32 + mt * 16 + g;
        #pragma unroll
        for (int nt = 0; nt < 4; nt++) {
            int o = wn * 32 + nt * 8 + 2 * t4;
            float bi0 = g_bu[n * 64 + o];
            float bi1 = g_bu[n * 64 + o + 1];
            #pragma unroll
            for (int half = 0; half < 2; half++) {
                int b = b0 + half * 8;
                float hc0 = tanhf(acc[mt][nt][2 * half]     + bi0);
                float hc1 = tanhf(acc[mt][nt][2 * half + 1] + bi1);
                int idx = b * (NN * HH) + n * HH + o;
                float r0 = g_r[idx],     st0 = state[idx];
                float r1 = g_r[idx + 1], st1 = state[idx + 1];
                dout[idx]     = r0 * st0 + (1.0f - r0) * hc0;
                dout[idx + 1] = r1 * st1 + (1.0f - r1) * hc1;
            }
        }
    }
}

// ---------------- launch ----------------
extern "C" void kernel_launch(void* const* d_in, const int* in_sizes, int n_in,
                              void* d_out, int out_size)
{
    const float* x         = (const float*)d_in[0];
    const float* state     = (const float*)d_in[2];
    const float* node_emb  = (const float*)d_in[3];
    const float* time_emb  = (const float*)d_in[5];
    const float* gate_W    = (const float*)d_in[6];
    const float* gate_b    = (const float*)d_in[7];
    const float* gate_lnw  = (const float*)d_in[8];
    const float* gate_lnb  = (const float*)d_in[9];
    const float* update_W  = (const float*)d_in[10];
    const float* update_b  = (const float*)d_in[11];
    const float* update_lnw= (const float*)d_in[12];
    const float* update_lnb= (const float*)d_in[13];
    float* out = (float*)d_out;

    unsigned short *Sgh, *Suh, *STt, *T2g, *T2u, *XTh;
    unsigned short *X0h, *X1h, *X1l, *X2h, *X2l;
    cudaGetSymbolAddress((void**)&Sgh, g_Sgh);
    cudaGetSymbolAddress((void**)&Suh, g_Suh);
    cudaGetSymbolAddress((void**)&STt, g_STt);
    cudaGetSymbolAddress((void**)&T2g, g_T2g);
    cudaGetSymbolAddress((void**)&T2u, g_T2u);
    cudaGetSymbolAddress((void**)&XTh, g_XTh);
    cudaGetSymbolAddress((void**)&X0h, g_X0h);
    cudaGetSymbolAddress((void**)&X1h, g_X1h);
    cudaGetSymbolAddress((void**)&X1l, g_X1l);
    cudaGetSymbolAddress((void**)&X2h, g_X2h);
    cudaGetSymbolAddress((void**)&X2l, g_X2l);

    cudaFuncSetAttribute(k_mmagemm2, cudaFuncAttributeMaxDynamicSharedMemorySize, TCG_SMEM);
    cudaFuncSetAttribute(k_ss, cudaFuncAttributeMaxDynamicSharedMemorySize, SS_SMEM);
    cudaFuncSetAttribute(k_tc_gate, cudaFuncAttributeMaxDynamicSharedMemorySize, GATE_SMEM);

    k_prep<<<NN, 32>>>(node_emb, time_emb, gate_lnw, gate_lnb, update_lnw, update_lnb,
                       gate_b, update_b);
    k_supports<<<dim3(NN, 2), 256>>>();

    // T2 matrices: 2*S@S - I  (fp16)
    k_transposeS<<<dim3(32, 32), dim3(32, 8)>>>(Sgh, STt);
    k_ss<<<dim3(8, 8), 256, SS_SMEM>>>(Sgh, STt, T2g);
    k_transposeS<<<dim3(32, 32), dim3(32, 8)>>>(Suh, STt);
    k_ss<<<dim3(8, 8), 256, SS_SMEM>>>(Suh, STt, T2u);

    // per-node weights via tensor cores
    k_wgen_mma<<<dim3(KIO_G / 512, NN / 64), 256>>>(gate_W, 0);
    k_wgen_mma<<<dim3(KIO_U / 512, NN / 64), 256>>>(update_W, 1);

    dim3 gg2(BC / 128, 16);

    // ---- gate magcn ----
    k_build_xin<<<(NN * BC / 4) / 256, 256>>>(x, state);
    k_transposeX<<<dim3(BC / 32, NN / 32), dim3(32, 8)>>>(X0h, XTh, 0);
    k_mmagemm2<<<gg2, 256, TCG_SMEM>>>(Sgh, T2g, XTh, X1h, X1l, X2h, X2l);
    k_tc_gate<<<NN, 256, GATE_SMEM>>>(state);   // z*state -> X0 state-half; r -> g_r

    // ---- update magcn ----
    k_transposeX<<<dim3(BC / 64, NN / 32), dim3(32, 8)>>>(X0h, XTh, 1);  // state-half only
    k_mmagemm2<<<gg2, 256, TCG_SMEM>>>(Suh, T2u, XTh, X1h, X1l, X2h, X2l);
    k_tc_upd<<<NN, 128>>>(state, out);
}

// round 9
// speedup vs baseline: 4.5071x; 1.0621x over previous
#include <cuda_runtime.h>
#include <cuda_fp16.h>
#include <math.h>
#include <stdint.h>

#define NN 1024
#define BB 64
#define CC 64
#define HH 64
#define DD 16
#define CIN 128
#define BC 8192            // BB * CIN
#define KIO_G 49152        // 384*128
#define KIO_U 24576        // 384*64

// ---------------- scratch ----------------
__device__ float g_eg[NN * DD];
__device__ float g_eu[NN * DD];
__device__ float g_bg[NN * 128];
__device__ float g_bu[NN * 64];
__device__ float g_r[BB * NN * HH];

__device__ unsigned short g_Sgh[NN * NN];
__device__ unsigned short g_Suh[NN * NN];
__device__ unsigned short g_STg[NN * NN];   // Sg^T
__device__ unsigned short g_STu[NN * NN];   // Su^T
__device__ unsigned short g_T2g[NN * NN];   // 2*Sg^2 - I (fp16)
__device__ unsigned short g_T2u[NN * NN];   // 2*Su^2 - I (fp16)
__device__ unsigned short g_XTh[BC * NN];   // transposed X0h [col][k]
__device__ unsigned short g_X0h[NN * BC];
__device__ unsigned short g_X0l[NN * BC];
__device__ unsigned short g_X1h[NN * BC];
__device__ unsigned short g_X1l[NN * BC];
__device__ unsigned short g_X2h[NN * BC];
__device__ unsigned short g_X2l[NN * BC];
__device__ unsigned short g_wgh[NN * KIO_G];
__device__ unsigned short g_wuh[NN * KIO_U];

// ---------------- helpers ----------------
__device__ __forceinline__ uint32_t smem_to_u32(const void* p) {
    uint32_t a;
    asm("{ .reg .u64 t; cvta.to.shared.u64 t, %1; cvt.u32.u64 %0, t; }" : "=r"(a) : "l"(p));
    return a;
}

#define CP_ASYNC16(dst, src) \
    asm volatile("cp.async.cg.shared.global [%0], [%1], 16;" :: "r"(dst), "l"(src))
#define CP_COMMIT()  asm volatile("cp.async.commit_group;" ::: "memory")
#define CP_WAIT0()   asm volatile("cp.async.wait_group 0;" ::: "memory")
#define CP_WAIT1()   asm volatile("cp.async.wait_group 1;" ::: "memory")

__device__ __forceinline__ void ldsm_x4(uint32_t& r0, uint32_t& r1, uint32_t& r2, uint32_t& r3,
                                        uint32_t addr) {
    asm volatile("ldmatrix.sync.aligned.m8n8.x4.shared.b16 {%0,%1,%2,%3}, [%4];"
                 : "=r"(r0), "=r"(r1), "=r"(r2), "=r"(r3) : "r"(addr));
}
__device__ __forceinline__ void ldsm_x4_t(uint32_t& r0, uint32_t& r1, uint32_t& r2, uint32_t& r3,
                                          uint32_t addr) {
    asm volatile("ldmatrix.sync.aligned.m8n8.x4.trans.shared.b16 {%0,%1,%2,%3}, [%4];"
                 : "=r"(r0), "=r"(r1), "=r"(r2), "=r"(r3) : "r"(addr));
}

__device__ __forceinline__ void mma16816(float* c, const uint32_t* a, const uint32_t* b) {
    asm volatile("mma.sync.aligned.m16n8k16.row.col.f32.f16.f16.f32 "
                 "{%0,%1,%2,%3}, {%4,%5,%6,%7}, {%8,%9}, {%0,%1,%2,%3};"
                 : "+f"(c[0]), "+f"(c[1]), "+f"(c[2]), "+f"(c[3])
                 : "r"(a[0]), "r"(a[1]), "r"(a[2]), "r"(a[3]), "r"(b[0]), "r"(b[1]));
}

__device__ __forceinline__ void f16split(float x, unsigned short& h, unsigned short& l) {
    __half hb = __float2half_rn(x);
    __half lb = __float2half_rn(x - __half2float(hb));
    h = *reinterpret_cast<unsigned short*>(&hb);
    l = *reinterpret_cast<unsigned short*>(&lb);
}

// ---------------- 1) e = LN(node_emb + time_emb), bias = e @ b_pool ----------------
__global__ void k_prep(const float* __restrict__ ne, const float* __restrict__ te,
                       const float* __restrict__ gw, const float* __restrict__ gbln,
                       const float* __restrict__ uw, const float* __restrict__ ubln,
                       const float* __restrict__ gate_b, const float* __restrict__ update_b)
{
    int n = blockIdx.x;
    int lane = threadIdx.x;
    int d = lane & 15;
    float v = ne[n * DD + d] + te[d];

    float s = v;
    #pragma unroll
    for (int off = 16; off > 0; off >>= 1) s += __shfl_xor_sync(0xffffffffu, s, off);
    float mean = s * (1.0f / 32.0f);
    float dv = v - mean;
    float q = dv * dv;
    #pragma unroll
    for (int off = 16; off > 0; off >>= 1) q += __shfl_xor_sync(0xffffffffu, q, off);
    float var = q * (1.0f / 32.0f);
    float inv = rsqrtf(var + 1e-12f);

    float eg = dv * inv * gw[d] + gbln[d];
    float eu = dv * inv * uw[d] + ubln[d];
    if (lane < 16) { g_eg[n * DD + d] = eg; g_eu[n * DD + d] = eu; }

    for (int o = lane; o < 128; o += 32) {
        float b = 0.f;
        #pragma unroll
        for (int dd = 0; dd < 16; dd++)
            b += __shfl_sync(0xffffffffu, eg, dd) * gate_b[dd * 128 + o];
        g_bg[n * 128 + o] = b;
    }
    for (int o = lane; o < 64; o += 32) {
        float b = 0.f;
        #pragma unroll
        for (int dd = 0; dd < 16; dd++)
            b += __shfl_sync(0xffffffffu, eu, dd) * update_b[dd * 64 + o];
        g_bu[n * 64 + o] = b;
    }
}

// ---------------- 2) S = softmax(e e^T), fp16 ----------------
__global__ void k_supports()
{
    int n = blockIdx.x;
    int which = blockIdx.y;
    const float* e = which ? g_eu : g_eg;
    unsigned short* Sh = which ? g_Suh : g_Sgh;

    __shared__ float en[16];
    __shared__ float red[256];
    int tid = threadIdx.x;
    if (tid < 16) en[tid] = e[n * DD + tid];
    __syncthreads();

    float lv[4];
    float mx = -1e30f;
    #pragma unroll
    for (int i = 0; i < 4; i++) {
        int m = tid + i * 256;
        const float* em = &e[m * DD];
        float dot = 0.f;
        #pragma unroll
        for (int dd = 0; dd < 16; dd++) dot += en[dd] * em[dd];
        lv[i] = dot;
        mx = fmaxf(mx, dot);
    }
    red[tid] = mx; __syncthreads();
    for (int s = 128; s > 0; s >>= 1) {
        if (tid < s) red[tid] = fmaxf(red[tid], red[tid + s]);
        __syncthreads();
    }
    mx = red[0];
    __syncthreads();

    float sum = 0.f;
    #pragma unroll
    for (int i = 0; i < 4; i++) { lv[i] = expf(lv[i] - mx); sum += lv[i]; }
    red[tid] = sum; __syncthreads();
    for (int s = 128; s > 0; s >>= 1) {
        if (tid < s) red[tid] += red[tid + s];
        __syncthreads();
    }
    float invs = 1.0f / red[0];
    #pragma unroll
    for (int i = 0; i < 4; i++) {
        float v = lv[i] * invs;
        __half hh = __float2half_rn(v);
        Sh[n * NN + tid + i * 256] = *reinterpret_cast<unsigned short*>(&hh);
    }
}

// ---------------- 3) tensor-core wgen (combined gate+update) ----------------
__global__ void __launch_bounds__(256)
k_wgen_mma(const float* __restrict__ gate_W, const float* __restrict__ update_W)
{
    const int bx = blockIdx.x;
    const int which = bx >= (KIO_G / 512);
    const int KIO = which ? KIO_U : KIO_G;
    const float* Wp = which ? update_W : gate_W;
    unsigned short* wh = which ? g_wuh : g_wgh;
    const float* e = which ? g_eu : g_eg;
    const int kio0 = (which ? bx - KIO_G / 512 : bx) << 9;
    const int n0 = blockIdx.y << 6;

    __shared__ char sm[16384 + 2048 + 2048];   // Bs [16][512]f16 | eh | el
    const uint32_t su = smem_to_u32(sm);
    const int tid = threadIdx.x;
    const int wid = tid >> 5, lane = tid & 31;

    {
        float4 v = *(const float4*)&e[n0 * DD + tid * 4];
        ushort4 h4, l4;
        f16split(v.x, h4.x, l4.x); f16split(v.y, h4.y, l4.y);
        f16split(v.z, h4.z, l4.z); f16split(v.w, h4.w, l4.w);
        *(ushort4*)(sm + 16384 + tid * 8) = h4;
        *(ushort4*)(sm + 18432 + tid * 8) = l4;
    }
    #pragma unroll
    for (int i = 0; i < 8; i++) {
        int lin = tid + (i << 8);
        int r = lin >> 7;
        int cf4 = lin & 127;
        float4 v = *(const float4*)&Wp[(size_t)r * KIO + kio0 + cf4 * 4];
        __half2 p0 = __floats2half2_rn(v.x, v.y);
        __half2 p1 = __floats2half2_rn(v.z, v.w);
        uint2 pk = { *reinterpret_cast<uint32_t*>(&p0), *reinterpret_cast<uint32_t*>(&p1) };
        uint32_t cb = (uint32_t)(cf4 * 8);
        *(uint2*)(sm + r * 1024 + (cb ^ ((r & 7) << 4))) = pk;
    }
    __syncthreads();

    const int mw = wid & 3;
    const int nhalf = wid >> 2;
    const int g = lane >> 2, t4 = lane & 3;

    uint32_t a_h[4], a_l[4];
    {
        uint32_t ao = (uint32_t)((mw * 16 + (lane & 15)) * 32 + ((lane >> 4) << 4));
        ldsm_x4(a_h[0], a_h[1], a_h[2], a_h[3], su + 16384 + ao);
        ldsm_x4(a_l[0], a_l[1], a_l[2], a_l[3], su + 18432 + ao);
    }

    const int brow = (lane & 7) + (((lane >> 3) & 1) << 3);
    const uint32_t bxor = (uint32_t)((brow & 7) << 4);
    const uint32_t bgrp = (uint32_t)((lane >> 4) << 4);

    #pragma unroll
    for (int nt2 = 0; nt2 < 16; nt2++) {
        uint32_t b[2][2];
        uint32_t bo = (uint32_t)(brow * 1024) + ((uint32_t)(nhalf * 512 + nt2 * 32 + bgrp) ^ bxor);
        ldsm_x4_t(b[0][0], b[0][1], b[1][0], b[1][1], su + bo);
        #pragma unroll
        for (int t = 0; t < 2; t++) {
            float c[4] = {0.f, 0.f, 0.f, 0.f};
            mma16816(c, a_h, b[t]);
            mma16816(c, a_l, b[t]);
            int node = n0 + mw * 16 + g;
            int kio = kio0 + nhalf * 256 + nt2 * 16 + t * 8 + 2 * t4;
            __half2 p0 = __floats2half2_rn(c[0], c[1]);
            __half2 p1 = __floats2half2_rn(c[2], c[3]);
            *(uint32_t*)(wh + (size_t)node * KIO + kio)       = *reinterpret_cast<uint32_t*>(&p0);
            *(uint32_t*)(wh + (size_t)(node + 8) * KIO + kio) = *reinterpret_cast<uint32_t*>(&p1);
        }
    }
}

// ---------------- 4) build X0 splits + fused XTh transpose ----------------
__global__ void k_build_xin(const float* __restrict__ x, const float* __restrict__ state)
{
    __shared__ unsigned short th[32][34];
    int bc = blockIdx.x << 5;   // col tile (8192 dim); 32 | 128 so single b
    int bn = blockIdx.y << 5;   // node tile
    int tx = threadIdx.x, ty = threadIdx.y;  // 32 x 8
    int b = bc >> 7;
    int c = (bc & 127) + tx;

    #pragma unroll
    for (int i = 0; i < 4; i++) {
        int n = bn + ty + i * 8;
        float v = (c < 64) ? x[b * (NN * CC) + n * CC + c]
                           : state[b * (NN * HH) + n * HH + (c - 64)];
        unsigned short h, l;
        f16split(v, h, l);
        int o = n * BC + bc + tx;
        g_X0h[o] = h;
        g_X0l[o] = l;
        th[ty + i * 8][tx] = h;
    }
    __syncthreads();
    #pragma unroll
    for (int i = 0; i < 4; i++)
        g_XTh[(bc + ty + i * 8) * NN + bn + tx] = th[tx][ty + i * 8];
}

// ---------------- 4b) u16 transposes ----------------
__global__ void k_transposeX(const unsigned short* __restrict__ in,
                             unsigned short* __restrict__ outp)
{
    // state-half columns only
    __shared__ unsigned short t[32][34];
    int tilex = ((blockIdx.x >> 1) << 2) + 2 + (blockIdx.x & 1);
    int bc = tilex << 5;
    int bn = blockIdx.y << 5;
    int x = threadIdx.x, y = threadIdx.y;
    #pragma unroll
    for (int i = 0; i < 4; i++)
        t[y + i * 8][x] = in[(bn + y + i * 8) * BC + bc + x];
    __syncthreads();
    #pragma unroll
    for (int i = 0; i < 4; i++)
        outp[(bc + y + i * 8) * NN + bn + x] = t[x][y + i * 8];
}

__global__ void k_transposeS()
{
    __shared__ unsigned short t[32][34];
    const unsigned short* in = blockIdx.z ? g_Suh : g_Sgh;
    unsigned short* outp = blockIdx.z ? g_STu : g_STg;
    int bc = blockIdx.x << 5;
    int bn = blockIdx.y << 5;
    int x = threadIdx.x, y = threadIdx.y;
    #pragma unroll
    for (int i = 0; i < 4; i++)
        t[y + i * 8][x] = in[(bn + y + i * 8) * NN + bc + x];
    __syncthreads();
    #pragma unroll
    for (int i = 0; i < 4; i++)
        outp[(bc + y + i * 8) * NN + bn + x] = t[x][y + i * 8];
}

// ---------------- 4c) T2 = 2*S@S - I (fp16), both matrices in one launch ----------------
#define SS_STAGE 32768
#define SS_SMEM  65536

__global__ void __launch_bounds__(256, 2)
k_ss()
{
    extern __shared__ char smem[];
    const uint32_t smem_u = smem_to_u32(smem);
    const unsigned short* Sh  = blockIdx.z ? g_Suh : g_Sgh;
    const unsigned short* STt = blockIdx.z ? g_STu : g_STg;
    unsigned short* T2 = blockIdx.z ? g_T2u : g_T2g;

    const int tid = threadIdx.x;
    const int wid = tid >> 5, lane = tid & 31;
    const int brow = blockIdx.y << 7;
    const int bcol = blockIdx.x << 7;
    const int wm = wid & 1, wn = wid >> 1;

    const unsigned short* srcs[2];
    srcs[0] = Sh + (size_t)brow * NN;
    srcs[1] = STt + (size_t)bcol * NN;

    float acc[4][4][4];
    #pragma unroll
    for (int i = 0; i < 4; i++)
        #pragma unroll
        for (int j = 0; j < 4; j++)
            #pragma unroll
            for (int q = 0; q < 4; q++) acc[i][j][q] = 0.f;

    const int arow = wm * 64 + (lane & 15);
    const int axor = (arow & 7) << 4;
    const int agco = (lane >> 4) << 4;
    const int bn   = wn * 32 + ((lane >> 4) << 3) + (lane & 7);
    const int bxor = (bn & 7) << 4;
    const int bko  = ((lane >> 3) & 1) << 4;

    auto load_stage = [&](int buf, int kk) {
        uint32_t dst0 = smem_u + buf * SS_STAGE;
        #pragma unroll
        for (int i = 0; i < 8; i++) {
            int lin = tid + (i << 8);
            int arr = lin >> 10;
            int r = (lin >> 3) & 127;
            int cb = (lin & 7) << 4;
            const char* src = (const char*)(srcs[arr] + (size_t)r * NN + kk) + cb;
            uint32_t d = dst0 + arr * 16384 + r * 128 + (cb ^ ((r & 7) << 4));
            CP_ASYNC16(d, src);
        }
        CP_COMMIT();
    };

    load_stage(0, 0);

    #pragma unroll 1
    for (int s = 0; s < 16; s++) {
        const int buf = s & 1;
        CP_WAIT0();
        __syncthreads();
        if (s + 1 < 16) load_stage(1 - buf, (s + 1) << 6);

        const uint32_t sb = smem_u + buf * SS_STAGE;
        #pragma unroll
        for (int ks = 0; ks < 4; ks++) {
            const int c = ks << 5;
            uint32_t ah[4][4], bh[4][2];
            #pragma unroll
            for (int mt = 0; mt < 4; mt++) {
                uint32_t ao = (uint32_t)((arow + mt * 16) * 128) + (uint32_t)((c + agco) ^ axor);
                ldsm_x4(ah[mt][0], ah[mt][1], ah[mt][2], ah[mt][3], sb + ao);
            }
            #pragma unroll
            for (int nb = 0; nb < 2; nb++) {
                uint32_t bo = (uint32_t)((bn + nb * 16) * 128) + (uint32_t)((c + bko) ^ bxor);
                ldsm_x4(bh[2 * nb][0], bh[2 * nb][1], bh[2 * nb + 1][0], bh[2 * nb + 1][1],
                        sb + 16384 + bo);
            }
            #pragma unroll
            for (int mt = 0; mt < 4; mt++)
                #pragma unroll
                for (int nt = 0; nt < 4; nt++)
                    mma16816(acc[mt][nt], ah[mt], bh[nt]);
        }
        __syncthreads();
    }

    const int g = lane >> 2, t4 = lane & 3;
    #pragma unroll
    for (int mt = 0; mt < 4; mt++) {
        #pragma unroll
        for (int nt = 0; nt < 4; nt++) {
            int m0 = wm * 64 + mt * 16 + g;
            int n0c = wn * 32 + nt * 8 + 2 * t4;
            #pragma unroll
            for (int half = 0; half < 2; half++) {
                int m = m0 + half * 8;
                int row = brow + m, col = bcol + n0c;
                float v0 = 2.0f * acc[mt][nt][2 * half]     - (row == col ? 1.0f : 0.0f);
                float v1 = 2.0f * acc[mt][nt][2 * half + 1] - (row == col + 1 ? 1.0f : 0.0f);
                __half2 p = __floats2half2_rn(v0, v1);
                *(uint32_t*)(T2 + (size_t)row * NN + col) = *reinterpret_cast<uint32_t*>(&p);
            }
        }
    }
}

// ---------------- 5) fused big GEMM: [Y1;Y2] = [S;T2] @ X ----------------
#define STAGE_BYTES 32768
#define TCG_SMEM 66560

__global__ void __launch_bounds__(256, 2)
k_mmagemm2(const unsigned short* __restrict__ A1,
           const unsigned short* __restrict__ A2,
           const unsigned short* __restrict__ Bh,
           unsigned short* __restrict__ O1h, unsigned short* __restrict__ O1l,
           unsigned short* __restrict__ O2h, unsigned short* __restrict__ O2l)
{
    extern __shared__ char smem[];
    const uint32_t smem_u = smem_to_u32(smem);
    const int tid = threadIdx.x;
    const int wid = tid >> 5;
    const int lane = tid & 31;
    const int by = blockIdx.y;
    const int rowA = (by & 7) << 7;
    const int bcol = blockIdx.x << 7;
    const int wm = wid & 1;
    const int wn = wid >> 1;

    const unsigned short* Aarr = (by < 8) ? A1 : A2;
    unsigned short* Xh = (by < 8) ? O1h : O2h;
    unsigned short* Xl = (by < 8) ? O1l : O2l;

    const unsigned short* srcs[2];
    srcs[0] = Aarr + (size_t)rowA * NN;
    srcs[1] = Bh + (size_t)bcol * NN;

    float acc[4][4][4];
    #pragma unroll
    for (int i = 0; i < 4; i++)
        #pragma unroll
        for (int j = 0; j < 4; j++)
            #pragma unroll
            for (int q = 0; q < 4; q++) acc[i][j][q] = 0.f;

    const int arow = wm * 64 + (lane & 15);
    const int axor = (arow & 7) << 4;
    const int agco = (lane >> 4) << 4;
    const int bn   = wn * 32 + ((lane >> 4) << 3) + (lane & 7);
    const int bxor = (bn & 7) << 4;
    const int bko  = ((lane >> 3) & 1) << 4;

    auto load_stage = [&](int buf, int kk) {
        uint32_t dst0 = smem_u + buf * STAGE_BYTES;
        #pragma unroll
        for (int i = 0; i < 8; i++) {
            int lin = tid + (i << 8);
            int arr = lin >> 10;
            int r = (lin >> 3) & 127;
            int cb = (lin & 7) << 4;
            const char* src = (const char*)(srcs[arr] + (size_t)r * NN + kk) + cb;
            uint32_t d = dst0 + arr * 16384 + r * 128 + (cb ^ ((r & 7) << 4));
            CP_ASYNC16(d, src);
        }
        CP_COMMIT();
    };

    load_stage(0, 0);

    #pragma unroll 1
    for (int s = 0; s < 16; s++) {
        const int buf = s & 1;
        CP_WAIT0();
        __syncthreads();
        if (s + 1 < 16) load_stage(1 - buf, (s + 1) << 6);

        const uint32_t sb = smem_u + buf * STAGE_BYTES;
        #pragma unroll
        for (int ks = 0; ks < 4; ks++) {
            const int c = ks << 5;
            uint32_t ah[4][4], bh[4][2];
            #pragma unroll
            for (int mt = 0; mt < 4; mt++) {
                uint32_t ao = (uint32_t)((arow + mt * 16) * 128) + (uint32_t)((c + agco) ^ axor);
                ldsm_x4(ah[mt][0], ah[mt][1], ah[mt][2], ah[mt][3], sb + ao);
            }
            #pragma unroll
            for (int nb = 0; nb < 2; nb++) {
                uint32_t bo = (uint32_t)((bn + nb * 16) * 128) + (uint32_t)((c + bko) ^ bxor);
                ldsm_x4(bh[2 * nb][0], bh[2 * nb][1], bh[2 * nb + 1][0], bh[2 * nb + 1][1],
                        sb + 16384 + bo);
            }
            #pragma unroll
            for (int mt = 0; mt < 4; mt++)
                #pragma unroll
                for (int nt = 0; nt < 4; nt++)
                    mma16816(acc[mt][nt], ah[mt], bh[nt]);
        }
        __syncthreads();
    }

    float* sf = (float*)smem;
    __syncthreads();
    {
        int g = lane >> 2, t4 = lane & 3;
        #pragma unroll
        for (int mt = 0; mt < 4; mt++) {
            int m0 = wm * 64 + mt * 16 + g;
            #pragma unroll
            for (int nt = 0; nt < 4; nt++) {
                int n0 = wn * 32 + nt * 8 + 2 * t4;
                sf[m0 * 129 + n0]           = acc[mt][nt][0];
                sf[m0 * 129 + n0 + 1]       = acc[mt][nt][1];
                sf[(m0 + 8) * 129 + n0]     = acc[mt][nt][2];
                sf[(m0 + 8) * 129 + n0 + 1] = acc[mt][nt][3];
            }
        }
    }
    __syncthreads();

    #pragma unroll 4
    for (int it = 0; it < 64; it++) {
        int idx = tid + (it << 8);
        int m = idx >> 7, j = idx & 127;
        float v = sf[m * 129 + j];
        unsigned short h, l;
        f16split(v, h, l);
        size_t o = (size_t)(rowA + m) * BC + bcol + j;
        Xh[o] = h; Xl[o] = l;
    }
}

// ---------------- 6) node GEMM gate (2-term, double-buffered) ----------------
#define GATE_STAGE 32768
#define GATE_SMEM 65536

__global__ void __launch_bounds__(256)
k_tc_gate(const float* __restrict__ state)
{
    extern __shared__ char sm[];
    const uint32_t su = smem_to_u32(sm);
    const int n = blockIdx.x;
    const int tid = threadIdx.x;
    const int wid = tid >> 5, lane = tid & 31;
    const int wm = wid & 1, wn = wid >> 1;

    const unsigned short* xh[3] = { g_X0h + (size_t)n * BC, g_X1h + (size_t)n * BC, g_X2h + (size_t)n * BC };
    const unsigned short* xl[3] = { g_X0l + (size_t)n * BC, g_X1l + (size_t)n * BC, g_X2l + (size_t)n * BC };
    const unsigned short* wh = g_wgh + (size_t)n * KIO_G;

    float acc[2][4][4];
    #pragma unroll
    for (int i = 0; i < 2; i++)
        #pragma unroll
        for (int j = 0; j < 4; j++)
            #pragma unroll
            for (int q = 0; q < 4; q++) acc[i][j][q] = 0.f;

    const int arow = wm * 32 + (lane & 15);
    const int axor = (arow & 7) << 4;
    const int agco = (lane >> 4) << 4;
    const int brow = (lane & 7) + (((lane >> 3) & 1) << 3);
    const int bxor = (lane & 7) << 4;
    const int bgrp = (lane >> 4) << 4;

    auto load_stage = [&](int buf, int q) {
        const int t = q >> 1;
        const int c0 = (q & 1) << 6;
        uint32_t b0 = su + buf * GATE_STAGE;
        #pragma unroll
        for (int i = 0; i < 2; i++) {
            int lin = tid + (i << 8);
            int r = lin >> 3;
            int cb = (lin & 7) << 4;
            uint32_t dsw = r * 128 + (cb ^ ((r & 7) << 4));
            CP_ASYNC16(b0 + dsw,        (const char*)(xh[t] + r * 128 + c0) + cb);
            CP_ASYNC16(b0 + 8192 + dsw, (const char*)(xl[t] + r * 128 + c0) + cb);
        }
        #pragma unroll
        for (int i = 0; i < 4; i++) {
            int lin = tid + (i << 8);
            int kr = lin >> 4;
            int cb = (lin & 15) << 4;
            uint32_t dsw = kr * 256 + (cb ^ ((kr & 7) << 4));
            CP_ASYNC16(b0 + 16384 + dsw, (const char*)(wh + (size_t)(q * 64 + kr) * 128) + cb);
        }
        CP_COMMIT();
    };

    load_stage(0, 0);

    #pragma unroll 1
    for (int q = 0; q < 6; q++) {
        const int buf = q & 1;
        if (q + 1 < 6) { load_stage(1 - buf, q + 1); CP_WAIT1(); }
        else           { CP_WAIT0(); }
        __syncthreads();

        const uint32_t sb = su + buf * GATE_STAGE;
        #pragma unroll
        for (int ks = 0; ks < 4; ks++) {
            const int c = ks << 5;
            uint32_t ah[2][4], al[2][4], bh[4][2];
            #pragma unroll
            for (int mt = 0; mt < 2; mt++) {
                uint32_t ao = (uint32_t)((arow + mt * 16) * 128) + (uint32_t)((c + agco) ^ axor);
                ldsm_x4(ah[mt][0], ah[mt][1], ah[mt][2], ah[mt][3], sb + ao);
                ldsm_x4(al[mt][0], al[mt][1], al[mt][2], al[mt][3], sb + 8192 + ao);
            }
            #pragma unroll
            for (int nb = 0; nb < 2; nb++) {
                uint32_t bo = (uint32_t)((ks * 16 + brow) * 256)
                            + (uint32_t)((wn * 64 + nb * 32 + bgrp) ^ bxor);
                ldsm_x4_t(bh[2 * nb][0], bh[2 * nb][1], bh[2 * nb + 1][0], bh[2 * nb + 1][1],
                          sb + 16384 + bo);
            }
            #pragma unroll
            for (int mt = 0; mt < 2; mt++)
                #pragma unroll
                for (int nt = 0; nt < 4; nt++) {
                    mma16816(acc[mt][nt], ah[mt], bh[nt]);
                    mma16816(acc[mt][nt], al[mt], bh[nt]);
                }
        }
        __syncthreads();
    }

    const int g = lane >> 2, t4 = lane & 3;
    #pragma unroll
    for (int mt = 0; mt < 2; mt++) {
        int b0 = wm * 32 + mt * 16 + g;
        #pragma unroll
        for (int nt = 0; nt < 4; nt++) {
            int o = wn * 32 + nt * 8 + 2 * t4;
            float bi0 = g_bg[n * 128 + o];
            float bi1 = g_bg[n * 128 + o + 1];
            #pragma unroll
            for (int half = 0; half < 2; half++) {
                int b = b0 + half * 8;
                float v0 = acc[mt][nt][2 * half]     + bi0;
                float v1 = acc[mt][nt][2 * half + 1] + bi1;
                float s0 = 1.0f / (1.0f + expf(-v0));
                float s1 = 1.0f / (1.0f + expf(-v1));
                if (o < 64) {
                    int sidx = b * (NN * HH) + n * HH + o;
                    float zs0 = s0 * state[sidx];
                    float zs1 = s1 * state[sidx + 1];
                    unsigned short h0, l0, h1, l1;
                    f16split(zs0, h0, l0); f16split(zs1, h1, l1);
                    int xo = n * BC + b * CIN + 64 + o;
                    g_X0h[xo] = h0; g_X0h[xo + 1] = h1;
                    g_X0l[xo] = l0; g_X0l[xo + 1] = l1;
                } else {
                    int base = b * (NN * HH) + n * HH + (o - 64);
                    g_r[base] = s0; g_r[base + 1] = s1;
                }
            }
        }
    }
}

// ---------------- 7) node GEMM update (2-term, double-buffered) ----------------
#define UPD_STAGE 24576

__global__ void __launch_bounds__(128)
k_tc_upd(const float* __restrict__ state, float* __restrict__ dout)
{
    __shared__ char sm[2 * UPD_STAGE];
    const uint32_t su = smem_to_u32(sm);
    const int n = blockIdx.x;
    const int tid = threadIdx.x;
    const int wid = tid >> 5, lane = tid & 31;
    const int wm = wid & 1, wn = wid >> 1;

    const unsigned short* xh[3] = { g_X0h + (size_t)n * BC, g_X1h + (size_t)n * BC, g_X2h + (size_t)n * BC };
    const unsigned short* xl[3] = { g_X0l + (size_t)n * BC, g_X1l + (size_t)n * BC, g_X2l + (size_t)n * BC };
    const unsigned short* wh = g_wuh + (size_t)n * KIO_U;

    float acc[2][4][4];
    #pragma unroll
    for (int i = 0; i < 2; i++)
        #pragma unroll
        for (int j = 0; j < 4; j++)
            #pragma unroll
            for (int q = 0; q < 4; q++) acc[i][j][q] = 0.f;

    const int arow = wm * 32 + (lane & 15);
    const int axor = (arow & 7) << 4;
    const int agco = (lane >> 4) << 4;
    const int brow = (lane & 7) + (((lane >> 3) & 1) << 3);
    const int bxor = (lane & 7) << 4;
    const int bgrp = (lane >> 4) << 4;

    auto load_stage = [&](int buf, int q) {
        const int t = q >> 1;
        const int c0 = (q & 1) << 6;
        uint32_t b0 = su + buf * UPD_STAGE;
        #pragma unroll
        for (int i = 0; i < 4; i++) {
            int lin = tid + (i << 7);
            int r = lin >> 3;
            int cb = (lin & 7) << 4;
            uint32_t dsw = r * 128 + (cb ^ ((r & 7) << 4));
            CP_ASYNC16(b0 + dsw,        (const char*)(xh[t] + r * 128 + c0) + cb);
            CP_ASYNC16(b0 + 8192 + dsw, (const char*)(xl[t] + r * 128 + c0) + cb);
        }
        #pragma unroll
        for (int i = 0; i < 4; i++) {
            int lin = tid + (i << 7);
            int kr = lin >> 3;
            int cb = (lin & 7) << 4;
            uint32_t dsw = kr * 128 + (cb ^ ((kr & 7) << 4));
            CP_ASYNC16(b0 + 16384 + dsw, (const char*)(wh + (size_t)(q * 64 + kr) * 64) + cb);
        }
        CP_COMMIT();
    };

    load_stage(0, 0);

    #pragma unroll 1
    for (int q = 0; q < 6; q++) {
        const int buf = q & 1;
        if (q + 1 < 6) { load_stage(1 - buf, q + 1); CP_WAIT1(); }
        else           { CP_WAIT0(); }
        __syncthreads();

        const uint32_t sb = su + buf * UPD_STAGE;
        #pragma unroll
        for (int ks = 0; ks < 4; ks++) {
            const int c = ks << 5;
            uint32_t ah[2][4], al[2][4], bh[4][2];
            #pragma unroll
            for (int mt = 0; mt < 2; mt++) {
                uint32_t ao = (uint32_t)((arow + mt * 16) * 128) + (uint32_t)((c + agco) ^ axor);
                ldsm_x4(ah[mt][0], ah[mt][1], ah[mt][2], ah[mt][3], sb + ao);
                ldsm_x4(al[mt][0], al[mt][1], al[mt][2], al[mt][3], sb + 8192 + ao);
            }
            #pragma unroll
            for (int nb = 0; nb < 2; nb++) {
                uint32_t bo = (uint32_t)((ks * 16 + brow) * 128)
                            + (uint32_t)((wn * 64 + nb * 32 + bgrp) ^ bxor);
                ldsm_x4_t(bh[2 * nb][0], bh[2 * nb][1], bh[2 * nb + 1][0], bh[2 * nb + 1][1],
                          sb + 16384 + bo);
            }
            #pragma unroll
            for (int mt = 0; mt < 2; mt++)
                #pragma unroll
                for (int nt = 0; nt < 4; nt++) {
                    mma16816(acc[mt][nt], ah[mt], bh[nt]);
                    mma16816(acc[mt][nt], al[mt], bh[nt]);
                }
        }
        __syncthreads();
    }

    const int g = lane >> 2, t4 = lane & 3;
    #pragma unroll
    for (int mt = 0; mt < 2; mt++) {
        int b0 = wm * 32 + mt * 16 + g;
        #pragma unroll
        for (int nt = 0; nt < 4; nt++) {
            int o = wn * 32 + nt * 8 + 2 * t4;
            float bi0 = g_bu[n * 64 + o];
            float bi1 = g_bu[n * 64 + o + 1];
            #pragma unroll
            for (int half = 0; half < 2; half++) {
                int b = b0 + half * 8;
                float hc0 = tanhf(acc[mt][nt][2 * half]     + bi0);
                float hc1 = tanhf(acc[mt][nt][2 * half + 1] + bi1);
                int idx = b * (NN * HH) + n * HH + o;
                float r0 = g_r[idx],     st0 = state[idx];
                float r1 = g_r[idx + 1], st1 = state[idx + 1];
                dout[idx]     = r0 * st0 + (1.0f - r0) * hc0;
                dout[idx + 1] = r1 * st1 + (1.0f - r1) * hc1;
            }
        }
    }
}

// ---------------- launch ----------------
extern "C" void kernel_launch(void* const* d_in, const int* in_sizes, int n_in,
                              void* d_out, int out_size)
{
    const float* x         = (const float*)d_in[0];
    const float* state     = (const float*)d_in[2];
    const float* node_emb  = (const float*)d_in[3];
    const float* time_emb  = (const float*)d_in[5];
    const float* gate_W    = (const float*)d_in[6];
    const float* gate_b    = (const float*)d_in[7];
    const float* gate_lnw  = (const float*)d_in[8];
    const float* gate_lnb  = (const float*)d_in[9];
    const float* update_W  = (const float*)d_in[10];
    const float* update_b  = (const float*)d_in[11];
    const float* update_lnw= (const float*)d_in[12];
    const float* update_lnb= (const float*)d_in[13];
    float* out = (float*)d_out;

    unsigned short *Sgh, *Suh, *T2g, *T2u, *XTh;
    unsigned short *X0h, *X1h, *X1l, *X2h, *X2l;
    cudaGetSymbolAddress((void**)&Sgh, g_Sgh);
    cudaGetSymbolAddress((void**)&Suh, g_Suh);
    cudaGetSymbolAddress((void**)&T2g, g_T2g);
    cudaGetSymbolAddress((void**)&T2u, g_T2u);
    cudaGetSymbolAddress((void**)&XTh, g_XTh);
    cudaGetSymbolAddress((void**)&X0h, g_X0h);
    cudaGetSymbolAddress((void**)&X1h, g_X1h);
    cudaGetSymbolAddress((void**)&X1l, g_X1l);
    cudaGetSymbolAddress((void**)&X2h, g_X2h);
    cudaGetSymbolAddress((void**)&X2l, g_X2l);

    cudaFuncSetAttribute(k_mmagemm2, cudaFuncAttributeMaxDynamicSharedMemorySize, TCG_SMEM);
    cudaFuncSetAttribute(k_ss, cudaFuncAttributeMaxDynamicSharedMemorySize, SS_SMEM);
    cudaFuncSetAttribute(k_tc_gate, cudaFuncAttributeMaxDynamicSharedMemorySize, GATE_SMEM);

    k_prep<<<NN, 32>>>(node_emb, time_emb, gate_lnw, gate_lnb, update_lnw, update_lnb,
                       gate_b, update_b);
    k_supports<<<dim3(NN, 2), 256>>>();

    // T2 = 2*S@S - I for both matrices, batched
    k_transposeS<<<dim3(32, 32, 2), dim3(32, 8)>>>();
    k_ss<<<dim3(8, 8, 2), 256, SS_SMEM>>>();

    // per-node weights (gate + update in one launch)
    k_wgen_mma<<<dim3(KIO_G / 512 + KIO_U / 512, NN / 64), 256>>>(gate_W, update_W);

    dim3 gg2(BC / 128, 16);

    // ---- gate magcn ----
    k_build_xin<<<dim3(BC / 32, NN / 32), dim3(32, 8)>>>(x, state);   // X0 splits + XTh fused
    k_mmagemm2<<<gg2, 256, TCG_SMEM>>>(Sgh, T2g, XTh, X1h, X1l, X2h, X2l);
    k_tc_gate<<<NN, 256, GATE_SMEM>>>(state);   // z*state -> X0 state-half; r -> g_r

    // ---- update magcn ----
    k_transposeX<<<dim3(BC / 64, NN / 32), dim3(32, 8)>>>(X0h, XTh);  // state-half only
    k_mmagemm2<<<gg2, 256, TCG_SMEM>>>(Suh, T2u, XTh, X1h, X1l, X2h, X2l);
    k_tc_upd<<<NN, 128>>>(state, out);
}

// round 10
// speedup vs baseline: 4.5785x; 1.0158x over previous
#include <cuda_runtime.h>
#include <cuda_fp16.h>
#include <math.h>
#include <stdint.h>

#define NN 1024
#define BB 64
#define CC 64
#define HH 64
#define DD 16
#define CIN 128
#define BC 8192            // BB * CIN
#define KIO_G 49152        // 384*128
#define KIO_U 24576        // 384*64

// ---------------- scratch ----------------
__device__ float g_eg[NN * DD];
__device__ float g_eu[NN * DD];
__device__ float g_bg[NN * 128];
__device__ float g_bu[NN * 64];
__device__ float g_r[BB * NN * HH];

__device__ unsigned short g_Sgh[NN * NN];
__device__ unsigned short g_Suh[NN * NN];
__device__ unsigned short g_STg[NN * NN];   // Sg^T
__device__ unsigned short g_STu[NN * NN];   // Su^T
__device__ unsigned short g_T2g[NN * NN];   // 2*Sg^2 - I (fp16)
__device__ unsigned short g_T2u[NN * NN];   // 2*Su^2 - I (fp16)
__device__ unsigned short g_XTh[BC * NN];   // transposed X0h [col][k]
__device__ unsigned short g_X0h[NN * BC];
__device__ unsigned short g_X0l[NN * BC];
__device__ unsigned short g_X1h[NN * BC];
__device__ unsigned short g_X1l[NN * BC];
__device__ unsigned short g_X2h[NN * BC];
__device__ unsigned short g_X2l[NN * BC];
__device__ unsigned short g_wgh[NN * KIO_G];
__device__ unsigned short g_wuh[NN * KIO_U];

// ---------------- helpers ----------------
__device__ __forceinline__ uint32_t smem_to_u32(const void* p) {
    uint32_t a;
    asm("{ .reg .u64 t; cvta.to.shared.u64 t, %1; cvt.u32.u64 %0, t; }" : "=r"(a) : "l"(p));
    return a;
}

#define CP_ASYNC16(dst, src) \
    asm volatile("cp.async.cg.shared.global [%0], [%1], 16;" :: "r"(dst), "l"(src))
#define CP_COMMIT()  asm volatile("cp.async.commit_group;" ::: "memory")
#define CP_WAIT0()   asm volatile("cp.async.wait_group 0;" ::: "memory")
#define CP_WAIT1()   asm volatile("cp.async.wait_group 1;" ::: "memory")

__device__ __forceinline__ void ldsm_x4(uint32_t& r0, uint32_t& r1, uint32_t& r2, uint32_t& r3,
                                        uint32_t addr) {
    asm volatile("ldmatrix.sync.aligned.m8n8.x4.shared.b16 {%0,%1,%2,%3}, [%4];"
                 : "=r"(r0), "=r"(r1), "=r"(r2), "=r"(r3) : "r"(addr));
}
__device__ __forceinline__ void ldsm_x4_t(uint32_t& r0, uint32_t& r1, uint32_t& r2, uint32_t& r3,
                                          uint32_t addr) {
    asm volatile("ldmatrix.sync.aligned.m8n8.x4.trans.shared.b16 {%0,%1,%2,%3}, [%4];"
                 : "=r"(r0), "=r"(r1), "=r"(r2), "=r"(r3) : "r"(addr));
}

__device__ __forceinline__ void mma16816(float* c, const uint32_t* a, const uint32_t* b) {
    asm volatile("mma.sync.aligned.m16n8k16.row.col.f32.f16.f16.f32 "
                 "{%0,%1,%2,%3}, {%4,%5,%6,%7}, {%8,%9}, {%0,%1,%2,%3};"
                 : "+f"(c[0]), "+f"(c[1]), "+f"(c[2]), "+f"(c[3])
                 : "r"(a[0]), "r"(a[1]), "r"(a[2]), "r"(a[3]), "r"(b[0]), "r"(b[1]));
}

__device__ __forceinline__ void f16split(float x, unsigned short& h, unsigned short& l) {
    __half hb = __float2half_rn(x);
    __half lb = __float2half_rn(x - __half2float(hb));
    h = *reinterpret_cast<unsigned short*>(&hb);
    l = *reinterpret_cast<unsigned short*>(&lb);
}

// ---------------- 1) e = LN(node_emb + time_emb), bias = e @ b_pool ----------------
__global__ void k_prep(const float* __restrict__ ne, const float* __restrict__ te,
                       const float* __restrict__ gw, const float* __restrict__ gbln,
                       const float* __restrict__ uw, const float* __restrict__ ubln,
                       const float* __restrict__ gate_b, const float* __restrict__ update_b)
{
    int n = blockIdx.x;
    int lane = threadIdx.x;
    int d = lane & 15;
    float v = ne[n * DD + d] + te[d];

    float s = v;
    #pragma unroll
    for (int off = 16; off > 0; off >>= 1) s += __shfl_xor_sync(0xffffffffu, s, off);
    float mean = s * (1.0f / 32.0f);
    float dv = v - mean;
    float q = dv * dv;
    #pragma unroll
    for (int off = 16; off > 0; off >>= 1) q += __shfl_xor_sync(0xffffffffu, q, off);
    float var = q * (1.0f / 32.0f);
    float inv = rsqrtf(var + 1e-12f);

    float eg = dv * inv * gw[d] + gbln[d];
    float eu = dv * inv * uw[d] + ubln[d];
    if (lane < 16) { g_eg[n * DD + d] = eg; g_eu[n * DD + d] = eu; }

    for (int o = lane; o < 128; o += 32) {
        float b = 0.f;
        #pragma unroll
        for (int dd = 0; dd < 16; dd++)
            b += __shfl_sync(0xffffffffu, eg, dd) * gate_b[dd * 128 + o];
        g_bg[n * 128 + o] = b;
    }
    for (int o = lane; o < 64; o += 32) {
        float b = 0.f;
        #pragma unroll
        for (int dd = 0; dd < 16; dd++)
            b += __shfl_sync(0xffffffffu, eu, dd) * update_b[dd * 64 + o];
        g_bu[n * 64 + o] = b;
    }
}

// ---------------- 2) S = softmax(e e^T), fp16 ----------------
__global__ void k_supports()
{
    int n = blockIdx.x;
    int which = blockIdx.y;
    const float* e = which ? g_eu : g_eg;
    unsigned short* Sh = which ? g_Suh : g_Sgh;

    __shared__ float en[16];
    __shared__ float red[256];
    int tid = threadIdx.x;
    if (tid < 16) en[tid] = e[n * DD + tid];
    __syncthreads();

    float lv[4];
    float mx = -1e30f;
    #pragma unroll
    for (int i = 0; i < 4; i++) {
        int m = tid + i * 256;
        const float* em = &e[m * DD];
        float dot = 0.f;
        #pragma unroll
        for (int dd = 0; dd < 16; dd++) dot += en[dd] * em[dd];
        lv[i] = dot;
        mx = fmaxf(mx, dot);
    }
    red[tid] = mx; __syncthreads();
    for (int s = 128; s > 0; s >>= 1) {
        if (tid < s) red[tid] = fmaxf(red[tid], red[tid + s]);
        __syncthreads();
    }
    mx = red[0];
    __syncthreads();

    float sum = 0.f;
    #pragma unroll
    for (int i = 0; i < 4; i++) { lv[i] = expf(lv[i] - mx); sum += lv[i]; }
    red[tid] = sum; __syncthreads();
    for (int s = 128; s > 0; s >>= 1) {
        if (tid < s) red[tid] += red[tid + s];
        __syncthreads();
    }
    float invs = 1.0f / red[0];
    #pragma unroll
    for (int i = 0; i < 4; i++) {
        float v = lv[i] * invs;
        __half hh = __float2half_rn(v);
        Sh[n * NN + tid + i * 256] = *reinterpret_cast<unsigned short*>(&hh);
    }
}

// ---------------- 3) tensor-core wgen (combined gate+update) ----------------
__global__ void __launch_bounds__(256)
k_wgen_mma(const float* __restrict__ gate_W, const float* __restrict__ update_W)
{
    const int bx = blockIdx.x;
    const int which = bx >= (KIO_G / 512);
    const int KIO = which ? KIO_U : KIO_G;
    const float* Wp = which ? update_W : gate_W;
    unsigned short* wh = which ? g_wuh : g_wgh;
    const float* e = which ? g_eu : g_eg;
    const int kio0 = (which ? bx - KIO_G / 512 : bx) << 9;
    const int n0 = blockIdx.y << 6;

    __shared__ char sm[16384 + 2048 + 2048];   // Bs [16][512]f16 | eh | el
    const uint32_t su = smem_to_u32(sm);
    const int tid = threadIdx.x;
    const int wid = tid >> 5, lane = tid & 31;

    {
        float4 v = *(const float4*)&e[n0 * DD + tid * 4];
        ushort4 h4, l4;
        f16split(v.x, h4.x, l4.x); f16split(v.y, h4.y, l4.y);
        f16split(v.z, h4.z, l4.z); f16split(v.w, h4.w, l4.w);
        *(ushort4*)(sm + 16384 + tid * 8) = h4;
        *(ushort4*)(sm + 18432 + tid * 8) = l4;
    }
    #pragma unroll
    for (int i = 0; i < 8; i++) {
        int lin = tid + (i << 8);
        int r = lin >> 7;
        int cf4 = lin & 127;
        float4 v = *(const float4*)&Wp[(size_t)r * KIO + kio0 + cf4 * 4];
        __half2 p0 = __floats2half2_rn(v.x, v.y);
        __half2 p1 = __floats2half2_rn(v.z, v.w);
        uint2 pk = { *reinterpret_cast<uint32_t*>(&p0), *reinterpret_cast<uint32_t*>(&p1) };
        uint32_t cb = (uint32_t)(cf4 * 8);
        *(uint2*)(sm + r * 1024 + (cb ^ ((r & 7) << 4))) = pk;
    }
    __syncthreads();

    const int mw = wid & 3;
    const int nhalf = wid >> 2;
    const int g = lane >> 2, t4 = lane & 3;

    uint32_t a_h[4], a_l[4];
    {
        uint32_t ao = (uint32_t)((mw * 16 + (lane & 15)) * 32 + ((lane >> 4) << 4));
        ldsm_x4(a_h[0], a_h[1], a_h[2], a_h[3], su + 16384 + ao);
        ldsm_x4(a_l[0], a_l[1], a_l[2], a_l[3], su + 18432 + ao);
    }

    const int brow = (lane & 7) + (((lane >> 3) & 1) << 3);
    const uint32_t bxor = (uint32_t)((brow & 7) << 4);
    const uint32_t bgrp = (uint32_t)((lane >> 4) << 4);

    #pragma unroll
    for (int nt2 = 0; nt2 < 16; nt2++) {
        uint32_t b[2][2];
        uint32_t bo = (uint32_t)(brow * 1024) + ((uint32_t)(nhalf * 512 + nt2 * 32 + bgrp) ^ bxor);
        ldsm_x4_t(b[0][0], b[0][1], b[1][0], b[1][1], su + bo);
        #pragma unroll
        for (int t = 0; t < 2; t++) {
            float c[4] = {0.f, 0.f, 0.f, 0.f};
            mma16816(c, a_h, b[t]);
            mma16816(c, a_l, b[t]);
            int node = n0 + mw * 16 + g;
            int kio = kio0 + nhalf * 256 + nt2 * 16 + t * 8 + 2 * t4;
            __half2 p0 = __floats2half2_rn(c[0], c[1]);
            __half2 p1 = __floats2half2_rn(c[2], c[3]);
            *(uint32_t*)(wh + (size_t)node * KIO + kio)       = *reinterpret_cast<uint32_t*>(&p0);
            *(uint32_t*)(wh + (size_t)(node + 8) * KIO + kio) = *reinterpret_cast<uint32_t*>(&p1);
        }
    }
}

// ---------------- 4) build X0 splits + fused XTh transpose ----------------
__global__ void k_build_xin(const float* __restrict__ x, const float* __restrict__ state)
{
    __shared__ unsigned short th[32][34];
    int bc = blockIdx.x << 5;
    int bn = blockIdx.y << 5;
    int tx = threadIdx.x, ty = threadIdx.y;  // 32 x 8
    int b = bc >> 7;
    int c = (bc & 127) + tx;

    #pragma unroll
    for (int i = 0; i < 4; i++) {
        int n = bn + ty + i * 8;
        float v = (c < 64) ? x[b * (NN * CC) + n * CC + c]
                           : state[b * (NN * HH) + n * HH + (c - 64)];
        unsigned short h, l;
        f16split(v, h, l);
        int o = n * BC + bc + tx;
        g_X0h[o] = h;
        g_X0l[o] = l;
        th[ty + i * 8][tx] = h;
    }
    __syncthreads();
    #pragma unroll
    for (int i = 0; i < 4; i++)
        g_XTh[(bc + ty + i * 8) * NN + bn + tx] = th[tx][ty + i * 8];
}

// ---------------- 4b) u16 transposes ----------------
__global__ void k_transposeX(const unsigned short* __restrict__ in,
                             unsigned short* __restrict__ outp)
{
    __shared__ unsigned short t[32][34];
    int tilex = ((blockIdx.x >> 1) << 2) + 2 + (blockIdx.x & 1);
    int bc = tilex << 5;
    int bn = blockIdx.y << 5;
    int x = threadIdx.x, y = threadIdx.y;
    #pragma unroll
    for (int i = 0; i < 4; i++)
        t[y + i * 8][x] = in[(bn + y + i * 8) * BC + bc + x];
    __syncthreads();
    #pragma unroll
    for (int i = 0; i < 4; i++)
        outp[(bc + y + i * 8) * NN + bn + x] = t[x][y + i * 8];
}

__global__ void k_transposeS()
{
    __shared__ unsigned short t[32][34];
    const unsigned short* in = blockIdx.z ? g_Suh : g_Sgh;
    unsigned short* outp = blockIdx.z ? g_STu : g_STg;
    int bc = blockIdx.x << 5;
    int bn = blockIdx.y << 5;
    int x = threadIdx.x, y = threadIdx.y;
    #pragma unroll
    for (int i = 0; i < 4; i++)
        t[y + i * 8][x] = in[(bn + y + i * 8) * NN + bc + x];
    __syncthreads();
    #pragma unroll
    for (int i = 0; i < 4; i++)
        outp[(bc + y + i * 8) * NN + bn + x] = t[x][y + i * 8];
}

// ---------------- 4c) T2 = 2*S@S - I (fp16), both matrices in one launch ----------------
#define SS_STAGE 32768
#define SS_SMEM  65536

__global__ void __launch_bounds__(256, 2)
k_ss()
{
    extern __shared__ char smem[];
    const uint32_t smem_u = smem_to_u32(smem);
    const unsigned short* Sh  = blockIdx.z ? g_Suh : g_Sgh;
    const unsigned short* STt = blockIdx.z ? g_STu : g_STg;
    unsigned short* T2 = blockIdx.z ? g_T2u : g_T2g;

    const int tid = threadIdx.x;
    const int wid = tid >> 5, lane = tid & 31;
    const int brow = blockIdx.y << 7;
    const int bcol = blockIdx.x << 7;
    const int wm = wid & 1, wn = wid >> 1;

    const unsigned short* srcs[2];
    srcs[0] = Sh + (size_t)brow * NN;
    srcs[1] = STt + (size_t)bcol * NN;

    float acc[4][4][4];
    #pragma unroll
    for (int i = 0; i < 4; i++)
        #pragma unroll
        for (int j = 0; j < 4; j++)
            #pragma unroll
            for (int q = 0; q < 4; q++) acc[i][j][q] = 0.f;

    const int arow = wm * 64 + (lane & 15);
    const int axor = (arow & 7) << 4;
    const int agco = (lane >> 4) << 4;
    const int bn   = wn * 32 + ((lane >> 4) << 3) + (lane & 7);
    const int bxor = (bn & 7) << 4;
    const int bko  = ((lane >> 3) & 1) << 4;

    auto load_stage = [&](int buf, int kk) {
        uint32_t dst0 = smem_u + buf * SS_STAGE;
        #pragma unroll
        for (int i = 0; i < 8; i++) {
            int lin = tid + (i << 8);
            int arr = lin >> 10;
            int r = (lin >> 3) & 127;
            int cb = (lin & 7) << 4;
            const char* src = (const char*)(srcs[arr] + (size_t)r * NN + kk) + cb;
            uint32_t d = dst0 + arr * 16384 + r * 128 + (cb ^ ((r & 7) << 4));
            CP_ASYNC16(d, src);
        }
        CP_COMMIT();
    };

    load_stage(0, 0);

    #pragma unroll 1
    for (int s = 0; s < 16; s++) {
        const int buf = s & 1;
        CP_WAIT0();
        __syncthreads();
        if (s + 1 < 16) load_stage(1 - buf, (s + 1) << 6);

        const uint32_t sb = smem_u + buf * SS_STAGE;
        #pragma unroll
        for (int ks = 0; ks < 4; ks++) {
            const int c = ks << 5;
            uint32_t ah[4][4], bh[4][2];
            #pragma unroll
            for (int mt = 0; mt < 4; mt++) {
                uint32_t ao = (uint32_t)((arow + mt * 16) * 128) + (uint32_t)((c + agco) ^ axor);
                ldsm_x4(ah[mt][0], ah[mt][1], ah[mt][2], ah[mt][3], sb + ao);
            }
            #pragma unroll
            for (int nb = 0; nb < 2; nb++) {
                uint32_t bo = (uint32_t)((bn + nb * 16) * 128) + (uint32_t)((c + bko) ^ bxor);
                ldsm_x4(bh[2 * nb][0], bh[2 * nb][1], bh[2 * nb + 1][0], bh[2 * nb + 1][1],
                        sb + 16384 + bo);
            }
            #pragma unroll
            for (int mt = 0; mt < 4; mt++)
                #pragma unroll
                for (int nt = 0; nt < 4; nt++)
                    mma16816(acc[mt][nt], ah[mt], bh[nt]);
        }
        __syncthreads();
    }

    const int g = lane >> 2, t4 = lane & 3;
    #pragma unroll
    for (int mt = 0; mt < 4; mt++) {
        #pragma unroll
        for (int nt = 0; nt < 4; nt++) {
            int m0 = wm * 64 + mt * 16 + g;
            int n0c = wn * 32 + nt * 8 + 2 * t4;
            #pragma unroll
            for (int half = 0; half < 2; half++) {
                int m = m0 + half * 8;
                int row = brow + m, col = bcol + n0c;
                float v0 = 2.0f * acc[mt][nt][2 * half]     - (row == col ? 1.0f : 0.0f);
                float v1 = 2.0f * acc[mt][nt][2 * half + 1] - (row == col + 1 ? 1.0f : 0.0f);
                __half2 p = __floats2half2_rn(v0, v1);
                *(uint32_t*)(T2 + (size_t)row * NN + col) = *reinterpret_cast<uint32_t*>(&p);
            }
        }
    }
}

// ---------------- 5) fused big GEMM: [Y1;Y2] = [S;T2] @ X ----------------
#define STAGE_BYTES 32768
#define TCG_SMEM 66560

__global__ void __launch_bounds__(256, 2)
k_mmagemm2(const unsigned short* __restrict__ A1,
           const unsigned short* __restrict__ A2,
           const unsigned short* __restrict__ Bh,
           unsigned short* __restrict__ O1h, unsigned short* __restrict__ O1l,
           unsigned short* __restrict__ O2h, unsigned short* __restrict__ O2l)
{
    extern __shared__ char smem[];
    const uint32_t smem_u = smem_to_u32(smem);
    const int tid = threadIdx.x;
    const int wid = tid >> 5;
    const int lane = tid & 31;
    const int by = blockIdx.y;
    const int rowA = (by & 7) << 7;
    const int bcol = blockIdx.x << 7;
    const int wm = wid & 1;
    const int wn = wid >> 1;

    const unsigned short* Aarr = (by < 8) ? A1 : A2;
    unsigned short* Xh = (by < 8) ? O1h : O2h;
    unsigned short* Xl = (by < 8) ? O1l : O2l;

    const unsigned short* srcs[2];
    srcs[0] = Aarr + (size_t)rowA * NN;
    srcs[1] = Bh + (size_t)bcol * NN;

    float acc[4][4][4];
    #pragma unroll
    for (int i = 0; i < 4; i++)
        #pragma unroll
        for (int j = 0; j < 4; j++)
            #pragma unroll
            for (int q = 0; q < 4; q++) acc[i][j][q] = 0.f;

    const int arow = wm * 64 + (lane & 15);
    const int axor = (arow & 7) << 4;
    const int agco = (lane >> 4) << 4;
    const int bn   = wn * 32 + ((lane >> 4) << 3) + (lane & 7);
    const int bxor = (bn & 7) << 4;
    const int bko  = ((lane >> 3) & 1) << 4;

    auto load_stage = [&](int buf, int kk) {
        uint32_t dst0 = smem_u + buf * STAGE_BYTES;
        #pragma unroll
        for (int i = 0; i < 8; i++) {
            int lin = tid + (i << 8);
            int arr = lin >> 10;
            int r = (lin >> 3) & 127;
            int cb = (lin & 7) << 4;
            const char* src = (const char*)(srcs[arr] + (size_t)r * NN + kk) + cb;
            uint32_t d = dst0 + arr * 16384 + r * 128 + (cb ^ ((r & 7) << 4));
            CP_ASYNC16(d, src);
        }
        CP_COMMIT();
    };

    load_stage(0, 0);

    #pragma unroll 1
    for (int s = 0; s < 16; s++) {
        const int buf = s & 1;
        CP_WAIT0();
        __syncthreads();
        if (s + 1 < 16) load_stage(1 - buf, (s + 1) << 6);

        const uint32_t sb = smem_u + buf * STAGE_BYTES;
        #pragma unroll
        for (int ks = 0; ks < 4; ks++) {
            const int c = ks << 5;
            uint32_t ah[4][4], bh[4][2];
            #pragma unroll
            for (int mt = 0; mt < 4; mt++) {
                uint32_t ao = (uint32_t)((arow + mt * 16) * 128) + (uint32_t)((c + agco) ^ axor);
                ldsm_x4(ah[mt][0], ah[mt][1], ah[mt][2], ah[mt][3], sb + ao);
            }
            #pragma unroll
            for (int nb = 0; nb < 2; nb++) {
                uint32_t bo = (uint32_t)((bn + nb * 16) * 128) + (uint32_t)((c + bko) ^ bxor);
                ldsm_x4(bh[2 * nb][0], bh[2 * nb][1], bh[2 * nb + 1][0], bh[2 * nb + 1][1],
                        sb + 16384 + bo);
            }
            #pragma unroll
            for (int mt = 0; mt < 4; mt++)
                #pragma unroll
                for (int nt = 0; nt < 4; nt++)
                    mma16816(acc[mt][nt], ah[mt], bh[nt]);
        }
        __syncthreads();
    }

    float* sf = (float*)smem;
    __syncthreads();
    {
        int g = lane >> 2, t4 = lane & 3;
        #pragma unroll
        for (int mt = 0; mt < 4; mt++) {
            int m0 = wm * 64 + mt * 16 + g;
            #pragma unroll
            for (int nt = 0; nt < 4; nt++) {
                int n0 = wn * 32 + nt * 8 + 2 * t4;
                sf[m0 * 129 + n0]           = acc[mt][nt][0];
                sf[m0 * 129 + n0 + 1]       = acc[mt][nt][1];
                sf[(m0 + 8) * 129 + n0]     = acc[mt][nt][2];
                sf[(m0 + 8) * 129 + n0 + 1] = acc[mt][nt][3];
            }
        }
    }
    __syncthreads();

    #pragma unroll 4
    for (int it = 0; it < 64; it++) {
        int idx = tid + (it << 8);
        int m = idx >> 7, j = idx & 127;
        float v = sf[m * 129 + j];
        unsigned short h, l;
        f16split(v, h, l);
        size_t o = (size_t)(rowA + m) * BC + bcol + j;
        Xh[o] = h; Xl[o] = l;
    }
}

// ---------------- 6) node GEMM gate (2-term, double-buffered) ----------------
#define GATE_STAGE 32768
#define GATE_SMEM 65536

__global__ void __launch_bounds__(256)
k_tc_gate(const float* __restrict__ state)
{
    extern __shared__ char sm[];
    const uint32_t su = smem_to_u32(sm);
    const int n = blockIdx.x;
    const int tid = threadIdx.x;
    const int wid = tid >> 5, lane = tid & 31;
    const int wm = wid & 1, wn = wid >> 1;

    const unsigned short* xh[3] = { g_X0h + (size_t)n * BC, g_X1h + (size_t)n * BC, g_X2h + (size_t)n * BC };
    const unsigned short* xl[3] = { g_X0l + (size_t)n * BC, g_X1l + (size_t)n * BC, g_X2l + (size_t)n * BC };
    const unsigned short* wh = g_wgh + (size_t)n * KIO_G;

    float acc[2][4][4];
    #pragma unroll
    for (int i = 0; i < 2; i++)
        #pragma unroll
        for (int j = 0; j < 4; j++)
            #pragma unroll
            for (int q = 0; q < 4; q++) acc[i][j][q] = 0.f;

    const int arow = wm * 32 + (lane & 15);
    const int axor = (arow & 7) << 4;
    const int agco = (lane >> 4) << 4;
    const int brow = (lane & 7) + (((lane >> 3) & 1) << 3);
    const int bxor = (lane & 7) << 4;
    const int bgrp = (lane >> 4) << 4;

    auto load_stage = [&](int buf, int q) {
        const int t = q >> 1;
        const int c0 = (q & 1) << 6;
        uint32_t b0 = su + buf * GATE_STAGE;
        #pragma unroll
        for (int i = 0; i < 2; i++) {
            int lin = tid + (i << 8);
            int r = lin >> 3;
            int cb = (lin & 7) << 4;
            uint32_t dsw = r * 128 + (cb ^ ((r & 7) << 4));
            CP_ASYNC16(b0 + dsw,        (const char*)(xh[t] + r * 128 + c0) + cb);
            CP_ASYNC16(b0 + 8192 + dsw, (const char*)(xl[t] + r * 128 + c0) + cb);
        }
        #pragma unroll
        for (int i = 0; i < 4; i++) {
            int lin = tid + (i << 8);
            int kr = lin >> 4;
            int cb = (lin & 15) << 4;
            uint32_t dsw = kr * 256 + (cb ^ ((kr & 7) << 4));
            CP_ASYNC16(b0 + 16384 + dsw, (const char*)(wh + (size_t)(q * 64 + kr) * 128) + cb);
        }
        CP_COMMIT();
    };

    load_stage(0, 0);

    #pragma unroll 1
    for (int q = 0; q < 6; q++) {
        const int buf = q & 1;
        if (q + 1 < 6) { load_stage(1 - buf, q + 1); CP_WAIT1(); }
        else           { CP_WAIT0(); }
        __syncthreads();

        const uint32_t sb = su + buf * GATE_STAGE;
        #pragma unroll
        for (int ks = 0; ks < 4; ks++) {
            const int c = ks << 5;
            uint32_t ah[2][4], al[2][4], bh[4][2];
            #pragma unroll
            for (int mt = 0; mt < 2; mt++) {
                uint32_t ao = (uint32_t)((arow + mt * 16) * 128) + (uint32_t)((c + agco) ^ axor);
                ldsm_x4(ah[mt][0], ah[mt][1], ah[mt][2], ah[mt][3], sb + ao);
                ldsm_x4(al[mt][0], al[mt][1], al[mt][2], al[mt][3], sb + 8192 + ao);
            }
            #pragma unroll
            for (int nb = 0; nb < 2; nb++) {
                uint32_t bo = (uint32_t)((ks * 16 + brow) * 256)
                            + (uint32_t)((wn * 64 + nb * 32 + bgrp) ^ bxor);
                ldsm_x4_t(bh[2 * nb][0], bh[2 * nb][1], bh[2 * nb + 1][0], bh[2 * nb + 1][1],
                          sb + 16384 + bo);
            }
            #pragma unroll
            for (int mt = 0; mt < 2; mt++)
                #pragma unroll
                for (int nt = 0; nt < 4; nt++) {
                    mma16816(acc[mt][nt], ah[mt], bh[nt]);
                    mma16816(acc[mt][nt], al[mt], bh[nt]);
                }
        }
        __syncthreads();
    }

    const int g = lane >> 2, t4 = lane & 3;
    #pragma unroll
    for (int mt = 0; mt < 2; mt++) {
        int b0 = wm * 32 + mt * 16 + g;
        #pragma unroll
        for (int nt = 0; nt < 4; nt++) {
            int o = wn * 32 + nt * 8 + 2 * t4;
            float bi0 = g_bg[n * 128 + o];
            float bi1 = g_bg[n * 128 + o + 1];
            #pragma unroll
            for (int half = 0; half < 2; half++) {
                int b = b0 + half * 8;
                float v0 = acc[mt][nt][2 * half]     + bi0;
                float v1 = acc[mt][nt][2 * half + 1] + bi1;
                float s0 = 1.0f / (1.0f + expf(-v0));
                float s1 = 1.0f / (1.0f + expf(-v1));
                if (o < 64) {
                    int sidx = b * (NN * HH) + n * HH + o;
                    float zs0 = s0 * state[sidx];
                    float zs1 = s1 * state[sidx + 1];
                    unsigned short h0, l0, h1, l1;
                    f16split(zs0, h0, l0); f16split(zs1, h1, l1);
                    int xo = n * BC + b * CIN + 64 + o;
                    g_X0h[xo] = h0; g_X0h[xo + 1] = h1;
                    g_X0l[xo] = l0; g_X0l[xo + 1] = l1;
                } else {
                    int base = b * (NN * HH) + n * HH + (o - 64);
                    g_r[base] = s0; g_r[base + 1] = s1;
                }
            }
        }
    }
}

// ---------------- 7) node GEMM update (2-term, double-buffered) ----------------
#define UPD_STAGE 24576

__global__ void __launch_bounds__(128)
k_tc_upd(const float* __restrict__ state, float* __restrict__ dout)
{
    __shared__ char sm[2 * UPD_STAGE];
    const uint32_t su = smem_to_u32(sm);
    const int n = blockIdx.x;
    const int tid = threadIdx.x;
    const int wid = tid >> 5, lane = tid & 31;
    const int wm = wid & 1, wn = wid >> 1;

    const unsigned short* xh[3] = { g_X0h + (size_t)n * BC, g_X1h + (size_t)n * BC, g_X2h + (size_t)n * BC };
    const unsigned short* xl[3] = { g_X0l + (size_t)n * BC, g_X1l + (size_t)n * BC, g_X2l + (size_t)n * BC };
    const unsigned short* wh = g_wuh + (size_t)n * KIO_U;

    float acc[2][4][4];
    #pragma unroll
    for (int i = 0; i < 2; i++)
        #pragma unroll
        for (int j = 0; j < 4; j++)
            #pragma unroll
            for (int q = 0; q < 4; q++) acc[i][j][q] = 0.f;

    const int arow = wm * 32 + (lane & 15);
    const int axor = (arow & 7) << 4;
    const int agco = (lane >> 4) << 4;
    const int brow = (lane & 7) + (((lane >> 3) & 1) << 3);
    const int bxor = (lane & 7) << 4;
    const int bgrp = (lane >> 4) << 4;

    auto load_stage = [&](int buf, int q) {
        const int t = q >> 1;
        const int c0 = (q & 1) << 6;
        uint32_t b0 = su + buf * UPD_STAGE;
        #pragma unroll
        for (int i = 0; i < 4; i++) {
            int lin = tid + (i << 7);
            int r = lin >> 3;
            int cb = (lin & 7) << 4;
            uint32_t dsw = r * 128 + (cb ^ ((r & 7) << 4));
            CP_ASYNC16(b0 + dsw,        (const char*)(xh[t] + r * 128 + c0) + cb);
            CP_ASYNC16(b0 + 8192 + dsw, (const char*)(xl[t] + r * 128 + c0) + cb);
        }
        #pragma unroll
        for (int i = 0; i < 4; i++) {
            int lin = tid + (i << 7);
            int kr = lin >> 3;
            int cb = (lin & 7) << 4;
            uint32_t dsw = kr * 128 + (cb ^ ((kr & 7) << 4));
            CP_ASYNC16(b0 + 16384 + dsw, (const char*)(wh + (size_t)(q * 64 + kr) * 64) + cb);
        }
        CP_COMMIT();
    };

    load_stage(0, 0);

    #pragma unroll 1
    for (int q = 0; q < 6; q++) {
        const int buf = q & 1;
        if (q + 1 < 6) { load_stage(1 - buf, q + 1); CP_WAIT1(); }
        else           { CP_WAIT0(); }
        __syncthreads();

        const uint32_t sb = su + buf * UPD_STAGE;
        #pragma unroll
        for (int ks = 0; ks < 4; ks++) {
            const int c = ks << 5;
            uint32_t ah[2][4], al[2][4], bh[4][2];
            #pragma unroll
            for (int mt = 0; mt < 2; mt++) {
                uint32_t ao = (uint32_t)((arow + mt * 16) * 128) + (uint32_t)((c + agco) ^ axor);
                ldsm_x4(ah[mt][0], ah[mt][1], ah[mt][2], ah[mt][3], sb + ao);
                ldsm_x4(al[mt][0], al[mt][1], al[mt][2], al[mt][3], sb + 8192 + ao);
            }
            #pragma unroll
            for (int nb = 0; nb < 2; nb++) {
                uint32_t bo = (uint32_t)((ks * 16 + brow) * 128)
                            + (uint32_t)((wn * 64 + nb * 32 + bgrp) ^ bxor);
                ldsm_x4_t(bh[2 * nb][0], bh[2 * nb][1], bh[2 * nb + 1][0], bh[2 * nb + 1][1],
                          sb + 16384 + bo);
            }
            #pragma unroll
            for (int mt = 0; mt < 2; mt++)
                #pragma unroll
                for (int nt = 0; nt < 4; nt++) {
                    mma16816(acc[mt][nt], ah[mt], bh[nt]);
                    mma16816(acc[mt][nt], al[mt], bh[nt]);
                }
        }
        __syncthreads();
    }

    const int g = lane >> 2, t4 = lane & 3;
    #pragma unroll
    for (int mt = 0; mt < 2; mt++) {
        int b0 = wm * 32 + mt * 16 + g;
        #pragma unroll
        for (int nt = 0; nt < 4; nt++) {
            int o = wn * 32 + nt * 8 + 2 * t4;
            float bi0 = g_bu[n * 64 + o];
            float bi1 = g_bu[n * 64 + o + 1];
            #pragma unroll
            for (int half = 0; half < 2; half++) {
                int b = b0 + half * 8;
                float hc0 = tanhf(acc[mt][nt][2 * half]     + bi0);
                float hc1 = tanhf(acc[mt][nt][2 * half + 1] + bi1);
                int idx = b * (NN * HH) + n * HH + o;
                float r0 = g_r[idx],     st0 = state[idx];
                float r1 = g_r[idx + 1], st1 = state[idx + 1];
                dout[idx]     = r0 * st0 + (1.0f - r0) * hc0;
                dout[idx + 1] = r1 * st1 + (1.0f - r1) * hc1;
            }
        }
    }
}

// ---------------- launch ----------------
extern "C" void kernel_launch(void* const* d_in, const int* in_sizes, int n_in,
                              void* d_out, int out_size)
{
    const float* x         = (const float*)d_in[0];
    const float* state     = (const float*)d_in[2];
    const float* node_emb  = (const float*)d_in[3];
    const float* time_emb  = (const float*)d_in[5];
    const float* gate_W    = (const float*)d_in[6];
    const float* gate_b    = (const float*)d_in[7];
    const float* gate_lnw  = (const float*)d_in[8];
    const float* gate_lnb  = (const float*)d_in[9];
    const float* update_W  = (const float*)d_in[10];
    const float* update_b  = (const float*)d_in[11];
    const float* update_lnw= (const float*)d_in[12];
    const float* update_lnb= (const float*)d_in[13];
    float* out = (float*)d_out;

    unsigned short *Sgh, *Suh, *T2g, *T2u, *XTh;
    unsigned short *X0h, *X1h, *X1l, *X2h, *X2l;
    cudaGetSymbolAddress((void**)&Sgh, g_Sgh);
    cudaGetSymbolAddress((void**)&Suh, g_Suh);
    cudaGetSymbolAddress((void**)&T2g, g_T2g);
    cudaGetSymbolAddress((void**)&T2u, g_T2u);
    cudaGetSymbolAddress((void**)&XTh, g_XTh);
    cudaGetSymbolAddress((void**)&X0h, g_X0h);
    cudaGetSymbolAddress((void**)&X1h, g_X1h);
    cudaGetSymbolAddress((void**)&X1l, g_X1l);
    cudaGetSymbolAddress((void**)&X2h, g_X2h);
    cudaGetSymbolAddress((void**)&X2l, g_X2l);

    // streams/events created on first (uncaptured) call, reused during capture
    static cudaStream_t sB = nullptr, sW = nullptr;
    static cudaEvent_t evRoot = nullptr, evPrep = nullptr, evB = nullptr, evW = nullptr;
    if (!sB) {
        cudaStreamCreateWithFlags(&sB, cudaStreamNonBlocking);
        cudaStreamCreateWithFlags(&sW, cudaStreamNonBlocking);
        cudaEventCreateWithFlags(&evRoot, cudaEventDisableTiming);
        cudaEventCreateWithFlags(&evPrep, cudaEventDisableTiming);
        cudaEventCreateWithFlags(&evB, cudaEventDisableTiming);
        cudaEventCreateWithFlags(&evW, cudaEventDisableTiming);
        cudaFuncSetAttribute(k_mmagemm2, cudaFuncAttributeMaxDynamicSharedMemorySize, TCG_SMEM);
        cudaFuncSetAttribute(k_ss, cudaFuncAttributeMaxDynamicSharedMemorySize, SS_SMEM);
        cudaFuncSetAttribute(k_tc_gate, cudaFuncAttributeMaxDynamicSharedMemorySize, GATE_SMEM);
    }

    // fork point (root of capture on stream 0)
    cudaEventRecord(evRoot, 0);

    // branch B: build X0 splits + XTh (no deps)
    cudaStreamWaitEvent(sB, evRoot, 0);
    k_build_xin<<<dim3(BC / 32, NN / 32), dim3(32, 8), 0, sB>>>(x, state);
    cudaEventRecord(evB, sB);

    // main: prep
    k_prep<<<NN, 32>>>(node_emb, time_emb, gate_lnw, gate_lnb, update_lnw, update_lnb,
                       gate_b, update_b);
    cudaEventRecord(evPrep, 0);

    // branch W: per-node weights (needs e from prep)
    cudaStreamWaitEvent(sW, evPrep, 0);
    k_wgen_mma<<<dim3(KIO_G / 512 + KIO_U / 512, NN / 64), 256, 0, sW>>>(gate_W, update_W);
    cudaEventRecord(evW, sW);

    // main: supports -> S^T -> T2
    k_supports<<<dim3(NN, 2), 256>>>();
    k_transposeS<<<dim3(32, 32, 2), dim3(32, 8)>>>();
    k_ss<<<dim3(8, 8, 2), 256, SS_SMEM>>>();

    dim3 gg2(BC / 128, 16);

    // ---- gate magcn ----
    cudaStreamWaitEvent(0, evB, 0);   // XTh/X0 ready
    k_mmagemm2<<<gg2, 256, TCG_SMEM>>>(Sgh, T2g, XTh, X1h, X1l, X2h, X2l);
    cudaStreamWaitEvent(0, evW, 0);   // weights ready
    k_tc_gate<<<NN, 256, GATE_SMEM>>>(state);   // z*state -> X0 state-half; r -> g_r

    // ---- update magcn ----
    k_transposeX<<<dim3(BC / 64, NN / 32), dim3(32, 8)>>>(X0h, XTh);  // state-half only
    k_mmagemm2<<<gg2, 256, TCG_SMEM>>>(Suh, T2u, XTh, X1h, X1l, X2h, X2l);
    k_tc_upd<<<NN, 128>>>(state, out);
}

// round 11
// speedup vs baseline: 5.2806x; 1.1534x over previous
#include <cuda_runtime.h>
#include <cuda_fp16.h>
#include <math.h>
#include <stdint.h>

#define NN 1024
#define BB 64
#define CC 64
#define HH 64
#define DD 16
#define CIN 128
#define BC 8192            // BB * CIN
#define KIO_G 49152        // 384*128
#define KIO_U 24576        // 384*64

// ---------------- scratch ----------------
__device__ float g_eg[NN * DD];
__device__ float g_eu[NN * DD];
__device__ float g_bg[NN * 128];
__device__ float g_bu[NN * 64];
__device__ float g_r[BB * NN * HH];

__device__ unsigned short g_Sgh[NN * NN];
__device__ unsigned short g_Suh[NN * NN];
__device__ unsigned short g_T2g[NN * NN];   // 2*Sg^2 - I (fp16)
__device__ unsigned short g_T2u[NN * NN];   // 2*Su^2 - I (fp16)
__device__ unsigned short g_X0h[NN * BC];
__device__ unsigned short g_X0l[NN * BC];
__device__ unsigned short g_X1h[NN * BC];
__device__ unsigned short g_X1l[NN * BC];
__device__ unsigned short g_X2h[NN * BC];
__device__ unsigned short g_X2l[NN * BC];
__device__ unsigned short g_wgh[NN * KIO_G];
__device__ unsigned short g_wuh[NN * KIO_U];

// ---------------- helpers ----------------
__device__ __forceinline__ uint32_t smem_to_u32(const void* p) {
    uint32_t a;
    asm("{ .reg .u64 t; cvta.to.shared.u64 t, %1; cvt.u32.u64 %0, t; }" : "=r"(a) : "l"(p));
    return a;
}

#define CP_ASYNC16(dst, src) \
    asm volatile("cp.async.cg.shared.global [%0], [%1], 16;" :: "r"(dst), "l"(src))
#define CP_COMMIT()  asm volatile("cp.async.commit_group;" ::: "memory")
#define CP_WAIT0()   asm volatile("cp.async.wait_group 0;" ::: "memory")
#define CP_WAIT1()   asm volatile("cp.async.wait_group 1;" ::: "memory")

__device__ __forceinline__ void ldsm_x4(uint32_t& r0, uint32_t& r1, uint32_t& r2, uint32_t& r3,
                                        uint32_t addr) {
    asm volatile("ldmatrix.sync.aligned.m8n8.x4.shared.b16 {%0,%1,%2,%3}, [%4];"
                 : "=r"(r0), "=r"(r1), "=r"(r2), "=r"(r3) : "r"(addr));
}
__device__ __forceinline__ void ldsm_x4_t(uint32_t& r0, uint32_t& r1, uint32_t& r2, uint32_t& r3,
                                          uint32_t addr) {
    asm volatile("ldmatrix.sync.aligned.m8n8.x4.trans.shared.b16 {%0,%1,%2,%3}, [%4];"
                 : "=r"(r0), "=r"(r1), "=r"(r2), "=r"(r3) : "r"(addr));
}

__device__ __forceinline__ void mma16816(float* c, const uint32_t* a, const uint32_t* b) {
    asm volatile("mma.sync.aligned.m16n8k16.row.col.f32.f16.f16.f32 "
                 "{%0,%1,%2,%3}, {%4,%5,%6,%7}, {%8,%9}, {%0,%1,%2,%3};"
                 : "+f"(c[0]), "+f"(c[1]), "+f"(c[2]), "+f"(c[3])
                 : "r"(a[0]), "r"(a[1]), "r"(a[2]), "r"(a[3]), "r"(b[0]), "r"(b[1]));
}

__device__ __forceinline__ void f16split(float x, unsigned short& h, unsigned short& l) {
    __half hb = __float2half_rn(x);
    __half lb = __float2half_rn(x - __half2float(hb));
    h = *reinterpret_cast<unsigned short*>(&hb);
    l = *reinterpret_cast<unsigned short*>(&lb);
}

// ---------------- 1) e = LN(node_emb + time_emb), bias = e @ b_pool ----------------
__global__ void k_prep(const float* __restrict__ ne, const float* __restrict__ te,
                       const float* __restrict__ gw, const float* __restrict__ gbln,
                       const float* __restrict__ uw, const float* __restrict__ ubln,
                       const float* __restrict__ gate_b, const float* __restrict__ update_b)
{
    int n = blockIdx.x;
    int lane = threadIdx.x;
    int d = lane & 15;
    float v = ne[n * DD + d] + te[d];

    float s = v;
    #pragma unroll
    for (int off = 16; off > 0; off >>= 1) s += __shfl_xor_sync(0xffffffffu, s, off);
    float mean = s * (1.0f / 32.0f);
    float dv = v - mean;
    float q = dv * dv;
    #pragma unroll
    for (int off = 16; off > 0; off >>= 1) q += __shfl_xor_sync(0xffffffffu, q, off);
    float var = q * (1.0f / 32.0f);
    float inv = rsqrtf(var + 1e-12f);

    float eg = dv * inv * gw[d] + gbln[d];
    float eu = dv * inv * uw[d] + ubln[d];
    if (lane < 16) { g_eg[n * DD + d] = eg; g_eu[n * DD + d] = eu; }

    for (int o = lane; o < 128; o += 32) {
        float b = 0.f;
        #pragma unroll
        for (int dd = 0; dd < 16; dd++)
            b += __shfl_sync(0xffffffffu, eg, dd) * gate_b[dd * 128 + o];
        g_bg[n * 128 + o] = b;
    }
    for (int o = lane; o < 64; o += 32) {
        float b = 0.f;
        #pragma unroll
        for (int dd = 0; dd < 16; dd++)
            b += __shfl_sync(0xffffffffu, eu, dd) * update_b[dd * 64 + o];
        g_bu[n * 64 + o] = b;
    }
}

// ---------------- 2) S = softmax(e e^T), fp16; 8 rows/block via smem e^T ----------------
#define SUP_STRIDE 1032
#define SUP_SMEM (16 * SUP_STRIDE * 4)

__global__ void __launch_bounds__(256)
k_supports()
{
    extern __shared__ float eT[];   // [16][SUP_STRIDE]
    const int which = blockIdx.y;
    const float* e = which ? g_eu : g_eg;
    unsigned short* Sh = which ? g_Suh : g_Sgh;
    const int tid = threadIdx.x;
    const int warp = tid >> 5, lane = tid & 31;
    const int n = (blockIdx.x << 3) + warp;

    // load e (1024x16) transposed into smem
    #pragma unroll
    for (int i = 0; i < 64; i++) {
        int idx = tid + (i << 8);
        int m = idx >> 4, dd = idx & 15;
        eT[dd * SUP_STRIDE + m] = e[idx];
    }
    __syncthreads();

    float en[16];
    #pragma unroll
    for (int dd = 0; dd < 16; dd++) en[dd] = eT[dd * SUP_STRIDE + n];

    float lv[32];
    float mx = -1e30f;
    #pragma unroll
    for (int j = 0; j < 8; j++) {
        int m0 = (j << 7) + (lane << 2);
        float ax = 0.f, ay = 0.f, az = 0.f, aw = 0.f;
        #pragma unroll
        for (int dd = 0; dd < 16; dd++) {
            float4 v = *(const float4*)&eT[dd * SUP_STRIDE + m0];
            ax += en[dd] * v.x; ay += en[dd] * v.y;
            az += en[dd] * v.z; aw += en[dd] * v.w;
        }
        lv[j * 4 + 0] = ax; lv[j * 4 + 1] = ay;
        lv[j * 4 + 2] = az; lv[j * 4 + 3] = aw;
        mx = fmaxf(mx, fmaxf(fmaxf(ax, ay), fmaxf(az, aw)));
    }
    #pragma unroll
    for (int off = 16; off > 0; off >>= 1)
        mx = fmaxf(mx, __shfl_xor_sync(0xffffffffu, mx, off));

    float sum = 0.f;
    #pragma unroll
    for (int i = 0; i < 32; i++) { lv[i] = expf(lv[i] - mx); sum += lv[i]; }
    #pragma unroll
    for (int off = 16; off > 0; off >>= 1)
        sum += __shfl_xor_sync(0xffffffffu, sum, off);
    float invs = 1.0f / sum;

    #pragma unroll
    for (int j = 0; j < 8; j++) {
        int m0 = (j << 7) + (lane << 2);
        __half2 p0 = __floats2half2_rn(lv[j * 4 + 0] * invs, lv[j * 4 + 1] * invs);
        __half2 p1 = __floats2half2_rn(lv[j * 4 + 2] * invs, lv[j * 4 + 3] * invs);
        uint2 pk = { *reinterpret_cast<uint32_t*>(&p0), *reinterpret_cast<uint32_t*>(&p1) };
        *(uint2*)&Sh[n * NN + m0] = pk;
    }
}

// ---------------- 3) tensor-core wgen (combined gate+update) ----------------
__global__ void __launch_bounds__(256)
k_wgen_mma(const float* __restrict__ gate_W, const float* __restrict__ update_W)
{
    const int bx = blockIdx.x;
    const int which = bx >= (KIO_G / 512);
    const int KIO = which ? KIO_U : KIO_G;
    const float* Wp = which ? update_W : gate_W;
    unsigned short* wh = which ? g_wuh : g_wgh;
    const float* e = which ? g_eu : g_eg;
    const int kio0 = (which ? bx - KIO_G / 512 : bx) << 9;
    const int n0 = blockIdx.y << 6;

    __shared__ char sm[16384 + 2048 + 2048];
    const uint32_t su = smem_to_u32(sm);
    const int tid = threadIdx.x;
    const int wid = tid >> 5, lane = tid & 31;

    {
        float4 v = *(const float4*)&e[n0 * DD + tid * 4];
        ushort4 h4, l4;
        f16split(v.x, h4.x, l4.x); f16split(v.y, h4.y, l4.y);
        f16split(v.z, h4.z, l4.z); f16split(v.w, h4.w, l4.w);
        *(ushort4*)(sm + 16384 + tid * 8) = h4;
        *(ushort4*)(sm + 18432 + tid * 8) = l4;
    }
    #pragma unroll
    for (int i = 0; i < 8; i++) {
        int lin = tid + (i << 8);
        int r = lin >> 7;
        int cf4 = lin & 127;
        float4 v = *(const float4*)&Wp[(size_t)r * KIO + kio0 + cf4 * 4];
        __half2 p0 = __floats2half2_rn(v.x, v.y);
        __half2 p1 = __floats2half2_rn(v.z, v.w);
        uint2 pk = { *reinterpret_cast<uint32_t*>(&p0), *reinterpret_cast<uint32_t*>(&p1) };
        uint32_t cb = (uint32_t)(cf4 * 8);
        *(uint2*)(sm + r * 1024 + (cb ^ ((r & 7) << 4))) = pk;
    }
    __syncthreads();

    const int mw = wid & 3;
    const int nhalf = wid >> 2;
    const int g = lane >> 2, t4 = lane & 3;

    uint32_t a_h[4], a_l[4];
    {
        uint32_t ao = (uint32_t)((mw * 16 + (lane & 15)) * 32 + ((lane >> 4) << 4));
        ldsm_x4(a_h[0], a_h[1], a_h[2], a_h[3], su + 16384 + ao);
        ldsm_x4(a_l[0], a_l[1], a_l[2], a_l[3], su + 18432 + ao);
    }

    const int brow = (lane & 7) + (((lane >> 3) & 1) << 3);
    const uint32_t bxor = (uint32_t)((brow & 7) << 4);
    const uint32_t bgrp = (uint32_t)((lane >> 4) << 4);

    #pragma unroll
    for (int nt2 = 0; nt2 < 16; nt2++) {
        uint32_t b[2][2];
        uint32_t bo = (uint32_t)(brow * 1024) + ((uint32_t)(nhalf * 512 + nt2 * 32 + bgrp) ^ bxor);
        ldsm_x4_t(b[0][0], b[0][1], b[1][0], b[1][1], su + bo);
        #pragma unroll
        for (int t = 0; t < 2; t++) {
            float c[4] = {0.f, 0.f, 0.f, 0.f};
            mma16816(c, a_h, b[t]);
            mma16816(c, a_l, b[t]);
            int node = n0 + mw * 16 + g;
            int kio = kio0 + nhalf * 256 + nt2 * 16 + t * 8 + 2 * t4;
            __half2 p0 = __floats2half2_rn(c[0], c[1]);
            __half2 p1 = __floats2half2_rn(c[2], c[3]);
            *(uint32_t*)(wh + (size_t)node * KIO + kio)       = *reinterpret_cast<uint32_t*>(&p0);
            *(uint32_t*)(wh + (size_t)(node + 8) * KIO + kio) = *reinterpret_cast<uint32_t*>(&p1);
        }
    }
}

// ---------------- 4) build X0 = split(concat(x, state)) ----------------
__global__ void k_build_xin(const float* __restrict__ x, const float* __restrict__ state)
{
    int t = blockIdx.x * 256 + threadIdx.x;
    int n = t >> 11;
    int j = t & 2047;
    int b = j >> 5;
    int c = (j & 31) << 2;

    float4 v;
    if (c < 64) {
        v = *(const float4*)&x[b * (NN * CC) + n * CC + c];
    } else {
        v = *(const float4*)&state[b * (NN * HH) + n * HH + (c - 64)];
    }
    int o = n * BC + b * CIN + c;
    ushort4 h4, l4;
    f16split(v.x, h4.x, l4.x); f16split(v.y, h4.y, l4.y);
    f16split(v.z, h4.z, l4.z); f16split(v.w, h4.w, l4.w);
    *(ushort4*)&g_X0h[o] = h4;
    *(ushort4*)&g_X0l[o] = l4;
}

// ---------------- 4c) T2 = 2*S@S - I (fp16); B loaded from S via trans-ldmatrix ----------------
#define SS_STAGE 32768
#define SS_SMEM  65536

__global__ void __launch_bounds__(256, 2)
k_ss()
{
    extern __shared__ char smem[];
    const uint32_t smem_u = smem_to_u32(smem);
    const unsigned short* Sh = blockIdx.z ? g_Suh : g_Sgh;
    unsigned short* T2 = blockIdx.z ? g_T2u : g_T2g;

    const int tid = threadIdx.x;
    const int wid = tid >> 5, lane = tid & 31;
    const int brow = blockIdx.y << 7;
    const int bcol = blockIdx.x << 7;
    const int wm = wid & 1, wn = wid >> 1;

    float acc[4][4][4];
    #pragma unroll
    for (int i = 0; i < 4; i++)
        #pragma unroll
        for (int j = 0; j < 4; j++)
            #pragma unroll
            for (int q = 0; q < 4; q++) acc[i][j][q] = 0.f;

    const int arow = wm * 64 + (lane & 15);
    const int axor = (arow & 7) << 4;
    const int agco = (lane >> 4) << 4;
    const int bkrow = (lane & 7) + (((lane >> 3) & 1) << 3);
    const uint32_t bxor2 = (uint32_t)((lane & 7) << 4);
    const uint32_t bgrp = (uint32_t)((lane >> 4) << 4);

    // A tile: S[brow..+127][kk..+63] 128B rows. B tile: S[kk..+63][bcol..+127] 256B rows.
    auto load_stage = [&](int buf, int kk) {
        uint32_t dst0 = smem_u + buf * SS_STAGE;
        #pragma unroll
        for (int i = 0; i < 8; i++) {
            int lin = tid + (i << 8);
            if (lin < 1024) {
                int r = lin >> 3;
                int cb = (lin & 7) << 4;
                const char* src = (const char*)(Sh + (size_t)(brow + r) * NN + kk) + cb;
                CP_ASYNC16(dst0 + r * 128 + (cb ^ ((r & 7) << 4)), src);
            } else {
                int idx = lin - 1024;
                int kr = idx >> 4;
                int cb = (idx & 15) << 4;
                const char* src = (const char*)(Sh + (size_t)(kk + kr) * NN + bcol) + cb;
                CP_ASYNC16(dst0 + 16384 + kr * 256 + (cb ^ ((kr & 7) << 4)), src);
            }
        }
        CP_COMMIT();
    };

    load_stage(0, 0);

    #pragma unroll 1
    for (int s = 0; s < 16; s++) {
        const int buf = s & 1;
        CP_WAIT0();
        __syncthreads();
        if (s + 1 < 16) load_stage(1 - buf, (s + 1) << 6);

        const uint32_t sb = smem_u + buf * SS_STAGE;
        #pragma unroll
        for (int ks = 0; ks < 4; ks++) {
            const int c = ks << 5;
            uint32_t ah[4][4], bh[4][2];
            #pragma unroll
            for (int mt = 0; mt < 4; mt++) {
                uint32_t ao = (uint32_t)((arow + mt * 16) * 128) + (uint32_t)((c + agco) ^ axor);
                ldsm_x4(ah[mt][0], ah[mt][1], ah[mt][2], ah[mt][3], sb + ao);
            }
            #pragma unroll
            for (int nb = 0; nb < 2; nb++) {
                uint32_t bo = (uint32_t)((ks * 16 + bkrow) * 256)
                            + ((uint32_t)(wn * 64 + nb * 32 + bgrp) ^ bxor2);
                ldsm_x4_t(bh[2 * nb][0], bh[2 * nb][1], bh[2 * nb + 1][0], bh[2 * nb + 1][1],
                          sb + 16384 + bo);
            }
            #pragma unroll
            for (int mt = 0; mt < 4; mt++)
                #pragma unroll
                for (int nt = 0; nt < 4; nt++)
                    mma16816(acc[mt][nt], ah[mt], bh[nt]);
        }
        __syncthreads();
    }

    const int g = lane >> 2, t4 = lane & 3;
    #pragma unroll
    for (int mt = 0; mt < 4; mt++) {
        #pragma unroll
        for (int nt = 0; nt < 4; nt++) {
            int m0 = wm * 64 + mt * 16 + g;
            int n0c = wn * 32 + nt * 8 + 2 * t4;
            #pragma unroll
            for (int half = 0; half < 2; half++) {
                int m = m0 + half * 8;
                int row = brow + m, col = bcol + n0c;
                float v0 = 2.0f * acc[mt][nt][2 * half]     - (row == col ? 1.0f : 0.0f);
                float v1 = 2.0f * acc[mt][nt][2 * half + 1] - (row == col + 1 ? 1.0f : 0.0f);
                __half2 p = __floats2half2_rn(v0, v1);
                *(uint32_t*)(T2 + (size_t)row * NN + col) = *reinterpret_cast<uint32_t*>(&p);
            }
        }
    }
}

// ---------------- 5) fused big GEMM: [Y1;Y2] = [S;T2] @ X; B from X0h via trans ----------------
#define STAGE_BYTES 32768
#define TCG_SMEM 66560

__global__ void __launch_bounds__(256, 2)
k_mmagemm2(const unsigned short* __restrict__ A1,
           const unsigned short* __restrict__ A2,
           const unsigned short* __restrict__ Bx,   // X0h [k=node][col] row-major
           unsigned short* __restrict__ O1h, unsigned short* __restrict__ O1l,
           unsigned short* __restrict__ O2h, unsigned short* __restrict__ O2l)
{
    extern __shared__ char smem[];
    const uint32_t smem_u = smem_to_u32(smem);
    const int tid = threadIdx.x;
    const int wid = tid >> 5;
    const int lane = tid & 31;
    const int by = blockIdx.y;
    const int rowA = (by & 7) << 7;
    const int bcol = blockIdx.x << 7;
    const int wm = wid & 1;
    const int wn = wid >> 1;

    const unsigned short* Aarr = (by < 8) ? A1 : A2;
    unsigned short* Xh = (by < 8) ? O1h : O2h;
    unsigned short* Xl = (by < 8) ? O1l : O2l;

    float acc[4][4][4];
    #pragma unroll
    for (int i = 0; i < 4; i++)
        #pragma unroll
        for (int j = 0; j < 4; j++)
            #pragma unroll
            for (int q = 0; q < 4; q++) acc[i][j][q] = 0.f;

    const int arow = wm * 64 + (lane & 15);
    const int axor = (arow & 7) << 4;
    const int agco = (lane >> 4) << 4;
    const int bkrow = (lane & 7) + (((lane >> 3) & 1) << 3);
    const uint32_t bxor2 = (uint32_t)((lane & 7) << 4);
    const uint32_t bgrp = (uint32_t)((lane >> 4) << 4);

    // A tile: A[rowA..+127][kk..+63] 128B rows. B tile: X0h[kk..+63][bcol..+127] 256B rows.
    auto load_stage = [&](int buf, int kk) {
        uint32_t dst0 = smem_u + buf * STAGE_BYTES;
        #pragma unroll
        for (int i = 0; i < 8; i++) {
            int lin = tid + (i << 8);
            if (lin < 1024) {
                int r = lin >> 3;
                int cb = (lin & 7) << 4;
                const char* src = (const char*)(Aarr + (size_t)(rowA + r) * NN + kk) + cb;
                CP_ASYNC16(dst0 + r * 128 + (cb ^ ((r & 7) << 4)), src);
            } else {
                int idx = lin - 1024;
                int kr = idx >> 4;
                int cb = (idx & 15) << 4;
                const char* src = (const char*)(Bx + (size_t)(kk + kr) * BC + bcol) + cb;
                CP_ASYNC16(dst0 + 16384 + kr * 256 + (cb ^ ((kr & 7) << 4)), src);
            }
        }
        CP_COMMIT();
    };

    load_stage(0, 0);

    #pragma unroll 1
    for (int s = 0; s < 16; s++) {
        const int buf = s & 1;
        CP_WAIT0();
        __syncthreads();
        if (s + 1 < 16) load_stage(1 - buf, (s + 1) << 6);

        const uint32_t sb = smem_u + buf * STAGE_BYTES;
        #pragma unroll
        for (int ks = 0; ks < 4; ks++) {
            const int c = ks << 5;
            uint32_t ah[4][4], bh[4][2];
            #pragma unroll
            for (int mt = 0; mt < 4; mt++) {
                uint32_t ao = (uint32_t)((arow + mt * 16) * 128) + (uint32_t)((c + agco) ^ axor);
                ldsm_x4(ah[mt][0], ah[mt][1], ah[mt][2], ah[mt][3], sb + ao);
            }
            #pragma unroll
            for (int nb = 0; nb < 2; nb++) {
                uint32_t bo = (uint32_t)((ks * 16 + bkrow) * 256)
                            + ((uint32_t)(wn * 64 + nb * 32 + bgrp) ^ bxor2);
                ldsm_x4_t(bh[2 * nb][0], bh[2 * nb][1], bh[2 * nb + 1][0], bh[2 * nb + 1][1],
                          sb + 16384 + bo);
            }
            #pragma unroll
            for (int mt = 0; mt < 4; mt++)
                #pragma unroll
                for (int nt = 0; nt < 4; nt++)
                    mma16816(acc[mt][nt], ah[mt], bh[nt]);
        }
        __syncthreads();
    }

    float* sf = (float*)smem;
    __syncthreads();
    {
        int g = lane >> 2, t4 = lane & 3;
        #pragma unroll
        for (int mt = 0; mt < 4; mt++) {
            int m0 = wm * 64 + mt * 16 + g;
            #pragma unroll
            for (int nt = 0; nt < 4; nt++) {
                int n0 = wn * 32 + nt * 8 + 2 * t4;
                sf[m0 * 129 + n0]           = acc[mt][nt][0];
                sf[m0 * 129 + n0 + 1]       = acc[mt][nt][1];
                sf[(m0 + 8) * 129 + n0]     = acc[mt][nt][2];
                sf[(m0 + 8) * 129 + n0 + 1] = acc[mt][nt][3];
            }
        }
    }
    __syncthreads();

    #pragma unroll 4
    for (int it = 0; it < 64; it++) {
        int idx = tid + (it << 8);
        int m = idx >> 7, j = idx & 127;
        float v = sf[m * 129 + j];
        unsigned short h, l;
        f16split(v, h, l);
        size_t o = (size_t)(rowA + m) * BC + bcol + j;
        Xh[o] = h; Xl[o] = l;
    }
}

// ---------------- 6) node GEMM gate (2-term, double-buffered) ----------------
#define GATE_STAGE 32768
#define GATE_SMEM 65536

__global__ void __launch_bounds__(256)
k_tc_gate(const float* __restrict__ state)
{
    extern __shared__ char sm[];
    const uint32_t su = smem_to_u32(sm);
    const int n = blockIdx.x;
    const int tid = threadIdx.x;
    const int wid = tid >> 5, lane = tid & 31;
    const int wm = wid & 1, wn = wid >> 1;

    const unsigned short* xh[3] = { g_X0h + (size_t)n * BC, g_X1h + (size_t)n * BC, g_X2h + (size_t)n * BC };
    const unsigned short* xl[3] = { g_X0l + (size_t)n * BC, g_X1l + (size_t)n * BC, g_X2l + (size_t)n * BC };
    const unsigned short* wh = g_wgh + (size_t)n * KIO_G;

    float acc[2][4][4];
    #pragma unroll
    for (int i = 0; i < 2; i++)
        #pragma unroll
        for (int j = 0; j < 4; j++)
            #pragma unroll
            for (int q = 0; q < 4; q++) acc[i][j][q] = 0.f;

    const int arow = wm * 32 + (lane & 15);
    const int axor = (arow & 7) << 4;
    const int agco = (lane >> 4) << 4;
    const int brow = (lane & 7) + (((lane >> 3) & 1) << 3);
    const int bxor = (lane & 7) << 4;
    const int bgrp = (lane >> 4) << 4;

    auto load_stage = [&](int buf, int q) {
        const int t = q >> 1;
        const int c0 = (q & 1) << 6;
        uint32_t b0 = su + buf * GATE_STAGE;
        #pragma unroll
        for (int i = 0; i < 2; i++) {
            int lin = tid + (i << 8);
            int r = lin >> 3;
            int cb = (lin & 7) << 4;
            uint32_t dsw = r * 128 + (cb ^ ((r & 7) << 4));
            CP_ASYNC16(b0 + dsw,        (const char*)(xh[t] + r * 128 + c0) + cb);
            CP_ASYNC16(b0 + 8192 + dsw, (const char*)(xl[t] + r * 128 + c0) + cb);
        }
        #pragma unroll
        for (int i = 0; i < 4; i++) {
            int lin = tid + (i << 8);
            int kr = lin >> 4;
            int cb = (lin & 15) << 4;
            uint32_t dsw = kr * 256 + (cb ^ ((kr & 7) << 4));
            CP_ASYNC16(b0 + 16384 + dsw, (const char*)(wh + (size_t)(q * 64 + kr) * 128) + cb);
        }
        CP_COMMIT();
    };

    load_stage(0, 0);

    #pragma unroll 1
    for (int q = 0; q < 6; q++) {
        const int buf = q & 1;
        if (q + 1 < 6) { load_stage(1 - buf, q + 1); CP_WAIT1(); }
        else           { CP_WAIT0(); }
        __syncthreads();

        const uint32_t sb = su + buf * GATE_STAGE;
        #pragma unroll
        for (int ks = 0; ks < 4; ks++) {
            const int c = ks << 5;
            uint32_t ah[2][4], al[2][4], bh[4][2];
            #pragma unroll
            for (int mt = 0; mt < 2; mt++) {
                uint32_t ao = (uint32_t)((arow + mt * 16) * 128) + (uint32_t)((c + agco) ^ axor);
                ldsm_x4(ah[mt][0], ah[mt][1], ah[mt][2], ah[mt][3], sb + ao);
                ldsm_x4(al[mt][0], al[mt][1], al[mt][2], al[mt][3], sb + 8192 + ao);
            }
            #pragma unroll
            for (int nb = 0; nb < 2; nb++) {
                uint32_t bo = (uint32_t)((ks * 16 + brow) * 256)
                            + (uint32_t)((wn * 64 + nb * 32 + bgrp) ^ bxor);
                ldsm_x4_t(bh[2 * nb][0], bh[2 * nb][1], bh[2 * nb + 1][0], bh[2 * nb + 1][1],
                          sb + 16384 + bo);
            }
            #pragma unroll
            for (int mt = 0; mt < 2; mt++)
                #pragma unroll
                for (int nt = 0; nt < 4; nt++) {
                    mma16816(acc[mt][nt], ah[mt], bh[nt]);
                    mma16816(acc[mt][nt], al[mt], bh[nt]);
                }
        }
        __syncthreads();
    }

    const int g = lane >> 2, t4 = lane & 3;
    #pragma unroll
    for (int mt = 0; mt < 2; mt++) {
        int b0 = wm * 32 + mt * 16 + g;
        #pragma unroll
        for (int nt = 0; nt < 4; nt++) {
            int o = wn * 32 + nt * 8 + 2 * t4;
            float bi0 = g_bg[n * 128 + o];
            float bi1 = g_bg[n * 128 + o + 1];
            #pragma unroll
            for (int half = 0; half < 2; half++) {
                int b = b0 + half * 8;
                float v0 = acc[mt][nt][2 * half]     + bi0;
                float v1 = acc[mt][nt][2 * half + 1] + bi1;
                float s0 = 1.0f / (1.0f + expf(-v0));
                float s1 = 1.0f / (1.0f + expf(-v1));
                if (o < 64) {
                    int sidx = b * (NN * HH) + n * HH + o;
                    float zs0 = s0 * state[sidx];
                    float zs1 = s1 * state[sidx + 1];
                    unsigned short h0, l0, h1, l1;
                    f16split(zs0, h0, l0); f16split(zs1, h1, l1);
                    int xo = n * BC + b * CIN + 64 + o;
                    g_X0h[xo] = h0; g_X0h[xo + 1] = h1;
                    g_X0l[xo] = l0; g_X0l[xo + 1] = l1;
                } else {
                    int base = b * (NN * HH) + n * HH + (o - 64);
                    g_r[base] = s0; g_r[base + 1] = s1;
                }
            }
        }
    }
}

// ---------------- 7) node GEMM update (2-term, double-buffered) ----------------
#define UPD_STAGE 24576

__global__ void __launch_bounds__(128)
k_tc_upd(const float* __restrict__ state, float* __restrict__ dout)
{
    __shared__ char sm[2 * UPD_STAGE];
    const uint32_t su = smem_to_u32(sm);
    const int n = blockIdx.x;
    const int tid = threadIdx.x;
    const int wid = tid >> 5, lane = tid & 31;
    const int wm = wid & 1, wn = wid >> 1;

    const unsigned short* xh[3] = { g_X0h + (size_t)n * BC, g_X1h + (size_t)n * BC, g_X2h + (size_t)n * BC };
    const unsigned short* xl[3] = { g_X0l + (size_t)n * BC, g_X1l + (size_t)n * BC, g_X2l + (size_t)n * BC };
    const unsigned short* wh = g_wuh + (size_t)n * KIO_U;

    float acc[2][4][4];
    #pragma unroll
    for (int i = 0; i < 2; i++)
        #pragma unroll
        for (int j = 0; j < 4; j++)
            #pragma unroll
            for (int q = 0; q < 4; q++) acc[i][j][q] = 0.f;

    const int arow = wm * 32 + (lane & 15);
    const int axor = (arow & 7) << 4;
    const int agco = (lane >> 4) << 4;
    const int brow = (lane & 7) + (((lane >> 3) & 1) << 3);
    const int bxor = (lane & 7) << 4;
    const int bgrp = (lane >> 4) << 4;

    auto load_stage = [&](int buf, int q) {
        const int t = q >> 1;
        const int c0 = (q & 1) << 6;
        uint32_t b0 = su + buf * UPD_STAGE;
        #pragma unroll
        for (int i = 0; i < 4; i++) {
            int lin = tid + (i << 7);
            int r = lin >> 3;
            int cb = (lin & 7) << 4;
            uint32_t dsw = r * 128 + (cb ^ ((r & 7) << 4));
            CP_ASYNC16(b0 + dsw,        (const char*)(xh[t] + r * 128 + c0) + cb);
            CP_ASYNC16(b0 + 8192 + dsw, (const char*)(xl[t] + r * 128 + c0) + cb);
        }
        #pragma unroll
        for (int i = 0; i < 4; i++) {
            int lin = tid + (i << 7);
            int kr = lin >> 3;
            int cb = (lin & 7) << 4;
            uint32_t dsw = kr * 128 + (cb ^ ((kr & 7) << 4));
            CP_ASYNC16(b0 + 16384 + dsw, (const char*)(wh + (size_t)(q * 64 + kr) * 64) + cb);
        }
        CP_COMMIT();
    };

    load_stage(0, 0);

    #pragma unroll 1
    for (int q = 0; q < 6; q++) {
        const int buf = q & 1;
        if (q + 1 < 6) { load_stage(1 - buf, q + 1); CP_WAIT1(); }
        else           { CP_WAIT0(); }
        __syncthreads();

        const uint32_t sb = su + buf * UPD_STAGE;
        #pragma unroll
        for (int ks = 0; ks < 4; ks++) {
            const int c = ks << 5;
            uint32_t ah[2][4], al[2][4], bh[4][2];
            #pragma unroll
            for (int mt = 0; mt < 2; mt++) {
                uint32_t ao = (uint32_t)((arow + mt * 16) * 128) + (uint32_t)((c + agco) ^ axor);
                ldsm_x4(ah[mt][0], ah[mt][1], ah[mt][2], ah[mt][3], sb + ao);
                ldsm_x4(al[mt][0], al[mt][1], al[mt][2], al[mt][3], sb + 8192 + ao);
            }
            #pragma unroll
            for (int nb = 0; nb < 2; nb++) {
                uint32_t bo = (uint32_t)((ks * 16 + brow) * 128)
                            + (uint32_t)((wn * 64 + nb * 32 + bgrp) ^ bxor);
                ldsm_x4_t(bh[2 * nb][0], bh[2 * nb][1], bh[2 * nb + 1][0], bh[2 * nb + 1][1],
                          sb + 16384 + bo);
            }
            #pragma unroll
            for (int mt = 0; mt < 2; mt++)
                #pragma unroll
                for (int nt = 0; nt < 4; nt++) {
                    mma16816(acc[mt][nt], ah[mt], bh[nt]);
                    mma16816(acc[mt][nt], al[mt], bh[nt]);
                }
        }
        __syncthreads();
    }

    const int g = lane >> 2, t4 = lane & 3;
    #pragma unroll
    for (int mt = 0; mt < 2; mt++) {
        int b0 = wm * 32 + mt * 16 + g;
        #pragma unroll
        for (int nt = 0; nt < 4; nt++) {
            int o = wn * 32 + nt * 8 + 2 * t4;
            float bi0 = g_bu[n * 64 + o];
            float bi1 = g_bu[n * 64 + o + 1];
            #pragma unroll
            for (int half = 0; half < 2; half++) {
                int b = b0 + half * 8;
                float hc0 = tanhf(acc[mt][nt][2 * half]     + bi0);
                float hc1 = tanhf(acc[mt][nt][2 * half + 1] + bi1);
                int idx = b * (NN * HH) + n * HH + o;
                float r0 = g_r[idx],     st0 = state[idx];
                float r1 = g_r[idx + 1], st1 = state[idx + 1];
                dout[idx]     = r0 * st0 + (1.0f - r0) * hc0;
                dout[idx + 1] = r1 * st1 + (1.0f - r1) * hc1;
            }
        }
    }
}

// ---------------- launch ----------------
extern "C" void kernel_launch(void* const* d_in, const int* in_sizes, int n_in,
                              void* d_out, int out_size)
{
    const float* x         = (const float*)d_in[0];
    const float* state     = (const float*)d_in[2];
    const float* node_emb  = (const float*)d_in[3];
    const float* time_emb  = (const float*)d_in[5];
    const float* gate_W    = (const float*)d_in[6];
    const float* gate_b    = (const float*)d_in[7];
    const float* gate_lnw  = (const float*)d_in[8];
    const float* gate_lnb  = (const float*)d_in[9];
    const float* update_W  = (const float*)d_in[10];
    const float* update_b  = (const float*)d_in[11];
    const float* update_lnw= (const float*)d_in[12];
    const float* update_lnb= (const float*)d_in[13];
    float* out = (float*)d_out;

    unsigned short *Sgh, *Suh, *T2g, *T2u;
    unsigned short *X0h, *X1h, *X1l, *X2h, *X2l;
    cudaGetSymbolAddress((void**)&Sgh, g_Sgh);
    cudaGetSymbolAddress((void**)&Suh, g_Suh);
    cudaGetSymbolAddress((void**)&T2g, g_T2g);
    cudaGetSymbolAddress((void**)&T2u, g_T2u);
    cudaGetSymbolAddress((void**)&X0h, g_X0h);
    cudaGetSymbolAddress((void**)&X1h, g_X1h);
    cudaGetSymbolAddress((void**)&X1l, g_X1l);
    cudaGetSymbolAddress((void**)&X2h, g_X2h);
    cudaGetSymbolAddress((void**)&X2l, g_X2l);

    static cudaStream_t sB = nullptr, sW = nullptr;
    static cudaEvent_t evRoot = nullptr, evPrep = nullptr, evB = nullptr, evW = nullptr;
    if (!sB) {
        cudaStreamCreateWithFlags(&sB, cudaStreamNonBlocking);
        cudaStreamCreateWithFlags(&sW, cudaStreamNonBlocking);
        cudaEventCreateWithFlags(&evRoot, cudaEventDisableTiming);
        cudaEventCreateWithFlags(&evPrep, cudaEventDisableTiming);
        cudaEventCreateWithFlags(&evB, cudaEventDisableTiming);
        cudaEventCreateWithFlags(&evW, cudaEventDisableTiming);
        cudaFuncSetAttribute(k_mmagemm2, cudaFuncAttributeMaxDynamicSharedMemorySize, TCG_SMEM);
        cudaFuncSetAttribute(k_ss, cudaFuncAttributeMaxDynamicSharedMemorySize, SS_SMEM);
        cudaFuncSetAttribute(k_tc_gate, cudaFuncAttributeMaxDynamicSharedMemorySize, GATE_SMEM);
        cudaFuncSetAttribute(k_supports, cudaFuncAttributeMaxDynamicSharedMemorySize, SUP_SMEM);
    }

    cudaEventRecord(evRoot, 0);

    // branch B: build X0 splits (no deps)
    cudaStreamWaitEvent(sB, evRoot, 0);
    k_build_xin<<<(NN * BC / 4) / 256, 256, 0, sB>>>(x, state);
    cudaEventRecord(evB, sB);

    // main: prep
    k_prep<<<NN, 32>>>(node_emb, time_emb, gate_lnw, gate_lnb, update_lnw, update_lnb,
                       gate_b, update_b);
    cudaEventRecord(evPrep, 0);

    // branch W: per-node weights (needs e)
    cudaStreamWaitEvent(sW, evPrep, 0);
    k_wgen_mma<<<dim3(KIO_G / 512 + KIO_U / 512, NN / 64), 256, 0, sW>>>(gate_W, update_W);
    cudaEventRecord(evW, sW);

    // main: supports -> T2 (B via trans-ldmatrix, no S^T)
    k_supports<<<dim3(NN / 8, 2), 256, SUP_SMEM>>>();
    k_ss<<<dim3(8, 8, 2), 256, SS_SMEM>>>();

    dim3 gg2(BC / 128, 16);

    // ---- gate magcn ----
    cudaStreamWaitEvent(0, evB, 0);
    k_mmagemm2<<<gg2, 256, TCG_SMEM>>>(Sgh, T2g, X0h, X1h, X1l, X2h, X2l);
    cudaStreamWaitEvent(0, evW, 0);
    k_tc_gate<<<NN, 256, GATE_SMEM>>>(state);   // z*state -> X0 state-half; r -> g_r

    // ---- update magcn (B reads patched X0h directly) ----
    k_mmagemm2<<<gg2, 256, TCG_SMEM>>>(Suh, T2u, X0h, X1h, X1l, X2h, X2l);
    k_tc_upd<<<NN, 128>>>(state, out);
}